// round 3
// baseline (speedup 1.0000x reference)
#include <cuda_runtime.h>
#include <math.h>
#include <stdint.h>

#define NUM_HEADS  8
#define NUM_LEVELS 4
#define NUM_POINTS 4
#define HEAD_DIM   32
#define EMBED      256
#define BS_        8
#define LQ_        900
#define LEN_V_     21760
#define NQ   (BS_*LQ_)        // 7200
#define MV   (BS_*LEN_V_)     // 174080

// -------- scratch (device globals; no allocations allowed) --------
__device__ float  g_v  [(size_t)MV*EMBED];          // projected value, 178 MB
__device__ float  g_off[(size_t)NQ*256];
__device__ float  g_aw [(size_t)NQ*128];
__device__ float4 g_samp[(size_t)NQ*NUM_HEADS*16];  // (locx, locy, weight, _)
__device__ float  g_mid[(size_t)NQ*EMBED];

// =================== 3xTF32 tensor-core GEMM: C = A(MxK)*B(KxN) + bias ========
// Block tile 128x128, K-tile 32, 8 warps (2M x 4N), warp tile 64x32.
// Split-precision: a = a_hi + a_lo (tf32 each); c += ah*bh + ah*bl + al*bh
// -> fp32-class accuracy (~2^-22) at 3x tensor-op cost.
#define BM 128
#define BN 128
#define BK 32
#define LDA (BK + 4)   // 36: bank = (4*row+col)%32 -> conflict-free fragment reads
#define GEMM_SMEM (4 * BM * LDA * 4)   // As_hi, As_lo, Bs_hi, Bs_lo (73728 B)

__device__ __forceinline__ uint32_t f2tf32(float f) {
    uint32_t u;
    asm("cvt.rna.tf32.f32 %0, %1;" : "=r"(u) : "f"(f));
    return u;
}

__device__ __forceinline__ void split_tf32(float f, uint32_t& hi, uint32_t& lo) {
    hi = f2tf32(f);
    lo = f2tf32(f - __uint_as_float(hi));
}

__device__ __forceinline__ void mma_tf32(float* c, const uint32_t* a, const uint32_t* b) {
    asm volatile(
        "mma.sync.aligned.m16n8k8.row.col.f32.tf32.tf32.f32 "
        "{%0,%1,%2,%3}, {%4,%5,%6,%7}, {%8,%9}, {%0,%1,%2,%3};\n"
        : "+f"(c[0]), "+f"(c[1]), "+f"(c[2]), "+f"(c[3])
        : "r"(a[0]), "r"(a[1]), "r"(a[2]), "r"(a[3]), "r"(b[0]), "r"(b[1]));
}

__global__ __launch_bounds__(256) void tf32_gemm_bias(
    const float* __restrict__ A, const float* __restrict__ B,
    const float* __restrict__ bias, float* __restrict__ C,
    int M, int N, int K)
{
    extern __shared__ uint32_t smem[];
    uint32_t* As_hi = smem;
    uint32_t* As_lo = smem + BM * LDA;
    uint32_t* Bs_hi = smem + 2 * BM * LDA;
    uint32_t* Bs_lo = smem + 3 * BM * LDA;

    const int tid   = threadIdx.x;
    const int lane  = tid & 31;
    const int warp  = tid >> 5;
    const int warpM = warp >> 2;      // 0..1
    const int warpN = warp & 3;       // 0..3
    const int brow  = blockIdx.y * BM;
    const int bcol  = blockIdx.x * BN;
    const int g     = lane >> 2;      // group id 0..7
    const int tg    = lane & 3;       // thread-in-group 0..3

    float acc[4][4][4];
    #pragma unroll
    for (int i = 0; i < 4; i++)
        #pragma unroll
        for (int j = 0; j < 4; j++)
            #pragma unroll
            for (int r = 0; r < 4; r++) acc[i][j][r] = 0.f;

    // ---- global-load helpers (register prefetch double buffer)
    float4 pa[4], pb[4];
    auto load_tiles = [&](int kt) {
        #pragma unroll
        for (int i = 0; i < 4; i++) {
            int idx  = tid + i * 256;
            int arow = idx >> 3;
            int ac4  = idx & 7;
            int grow = brow + arow;
            pa[i] = make_float4(0.f, 0.f, 0.f, 0.f);
            if (grow < M)
                pa[i] = *reinterpret_cast<const float4*>(&A[(long)grow * K + kt + ac4 * 4]);
        }
        #pragma unroll
        for (int i = 0; i < 4; i++) {
            int idx  = tid + i * 256;
            int krow = idx >> 5;           // 0..31
            int nc4  = idx & 31;
            pb[i] = *reinterpret_cast<const float4*>(&B[(long)(kt + krow) * N + bcol + nc4 * 4]);
        }
    };

    load_tiles(0);

    for (int kt = 0; kt < K; kt += BK) {
        // ---- store prefetched tiles to smem with tf32 hi/lo split
        #pragma unroll
        for (int i = 0; i < 4; i++) {
            int idx  = tid + i * 256;
            int arow = idx >> 3;
            int ac4  = idx & 7;
            uint32_t h0,l0,h1,l1,h2,l2,h3,l3;
            split_tf32(pa[i].x, h0, l0);
            split_tf32(pa[i].y, h1, l1);
            split_tf32(pa[i].z, h2, l2);
            split_tf32(pa[i].w, h3, l3);
            uint32_t* ah = &As_hi[arow * LDA + ac4 * 4];
            uint32_t* al = &As_lo[arow * LDA + ac4 * 4];
            ah[0]=h0; ah[1]=h1; ah[2]=h2; ah[3]=h3;
            al[0]=l0; al[1]=l1; al[2]=l2; al[3]=l3;
        }
        #pragma unroll
        for (int i = 0; i < 4; i++) {
            int idx  = tid + i * 256;
            int krow = idx >> 5;
            int nc4  = idx & 31;
            uint32_t h0,l0,h1,l1,h2,l2,h3,l3;
            split_tf32(pb[i].x, h0, l0);
            split_tf32(pb[i].y, h1, l1);
            split_tf32(pb[i].z, h2, l2);
            split_tf32(pb[i].w, h3, l3);
            Bs_hi[(nc4*4+0) * LDA + krow] = h0;  Bs_lo[(nc4*4+0) * LDA + krow] = l0;
            Bs_hi[(nc4*4+1) * LDA + krow] = h1;  Bs_lo[(nc4*4+1) * LDA + krow] = l1;
            Bs_hi[(nc4*4+2) * LDA + krow] = h2;  Bs_lo[(nc4*4+2) * LDA + krow] = l2;
            Bs_hi[(nc4*4+3) * LDA + krow] = h3;  Bs_lo[(nc4*4+3) * LDA + krow] = l3;
        }
        __syncthreads();

        // ---- prefetch next tile while MMAing this one
        if (kt + BK < K) load_tiles(kt + BK);

        #pragma unroll
        for (int ks = 0; ks < BK / 8; ks++) {
            const int kb = ks * 8;
            uint32_t afh[4][4], afl[4][4], bfh[4][2], bfl[4][2];
            #pragma unroll
            for (int mt = 0; mt < 4; mt++) {
                int rb = warpM * 64 + mt * 16;
                afh[mt][0] = As_hi[(rb + g    ) * LDA + kb + tg    ];
                afh[mt][1] = As_hi[(rb + g + 8) * LDA + kb + tg    ];
                afh[mt][2] = As_hi[(rb + g    ) * LDA + kb + tg + 4];
                afh[mt][3] = As_hi[(rb + g + 8) * LDA + kb + tg + 4];
                afl[mt][0] = As_lo[(rb + g    ) * LDA + kb + tg    ];
                afl[mt][1] = As_lo[(rb + g + 8) * LDA + kb + tg    ];
                afl[mt][2] = As_lo[(rb + g    ) * LDA + kb + tg + 4];
                afl[mt][3] = As_lo[(rb + g + 8) * LDA + kb + tg + 4];
            }
            #pragma unroll
            for (int nt = 0; nt < 4; nt++) {
                int nb = warpN * 32 + nt * 8;
                bfh[nt][0] = Bs_hi[(nb + g) * LDA + kb + tg    ];
                bfh[nt][1] = Bs_hi[(nb + g) * LDA + kb + tg + 4];
                bfl[nt][0] = Bs_lo[(nb + g) * LDA + kb + tg    ];
                bfl[nt][1] = Bs_lo[(nb + g) * LDA + kb + tg + 4];
            }
            #pragma unroll
            for (int mt = 0; mt < 4; mt++)
                #pragma unroll
                for (int nt = 0; nt < 4; nt++) {
                    mma_tf32(acc[mt][nt], afh[mt], bfh[nt]);   // hi*hi
                    mma_tf32(acc[mt][nt], afh[mt], bfl[nt]);   // hi*lo
                    mma_tf32(acc[mt][nt], afl[mt], bfh[nt]);   // lo*hi
                }
        }
        __syncthreads();
    }

    // ---- epilogue: + bias, guarded store
    #pragma unroll
    for (int mt = 0; mt < 4; mt++) {
        int row0 = brow + warpM * 64 + mt * 16 + g;
        #pragma unroll
        for (int nt = 0; nt < 4; nt++) {
            int col = bcol + warpN * 32 + nt * 8 + tg * 2;
            float b0 = bias[col], b1 = bias[col + 1];
            if (row0 < M) {
                float2 o = make_float2(acc[mt][nt][0] + b0, acc[mt][nt][1] + b1);
                *reinterpret_cast<float2*>(&C[(long)row0 * N + col]) = o;
            }
            if (row0 + 8 < M) {
                float2 o = make_float2(acc[mt][nt][2] + b0, acc[mt][nt][3] + b1);
                *reinterpret_cast<float2*>(&C[(long)(row0 + 8) * N + col]) = o;
            }
        }
    }
}

// =================== softmax + sampling-loc precompute (4 threads per (bq,h)) ==
__global__ void softmax_loc4(const float* __restrict__ refp)
{
    int t  = blockIdx.x * blockDim.x + threadIdx.x;
    int id = t >> 2;                 // (bq, h)
    int l  = t & 3;                  // level
    if (id >= NQ * NUM_HEADS) return;
    int bq = id >> 3;
    int h  = id & 7;

    float4 a = *reinterpret_cast<const float4*>(&g_aw[(long)bq * 128 + h * 16 + l * 4]);
    float m = fmaxf(fmaxf(a.x, a.y), fmaxf(a.z, a.w));
    m = fmaxf(m, __shfl_xor_sync(0xffffffffu, m, 1));
    m = fmaxf(m, __shfl_xor_sync(0xffffffffu, m, 2));
    float e0 = expf(a.x - m), e1 = expf(a.y - m), e2 = expf(a.z - m), e3 = expf(a.w - m);
    float s = e0 + e1 + e2 + e3;
    s += __shfl_xor_sync(0xffffffffu, s, 1);
    s += __shfl_xor_sync(0xffffffffu, s, 2);
    float inv = 1.f / s;

    const float invWH[4] = {1.f/128.f, 1.f/64.f, 1.f/32.f, 1.f/16.f};
    float iw = invWH[l];
    float2 ref = *reinterpret_cast<const float2*>(&refp[((long)bq * 4 + l) * 2]);
    float4 o0 = *reinterpret_cast<const float4*>(&g_off[(long)bq * 256 + h * 32 + l * 8]);
    float4 o1 = *reinterpret_cast<const float4*>(&g_off[(long)bq * 256 + h * 32 + l * 8 + 4]);

    float4* out = &g_samp[(long)id * 16 + l * 4];
    out[0] = make_float4(ref.x + o0.x * iw, ref.y + o0.y * iw, e0 * inv, 0.f);
    out[1] = make_float4(ref.x + o0.z * iw, ref.y + o0.w * iw, e1 * inv, 0.f);
    out[2] = make_float4(ref.x + o1.x * iw, ref.y + o1.y * iw, e2 * inv, 0.f);
    out[3] = make_float4(ref.x + o1.z * iw, ref.y + o1.w * iw, e3 * inv, 0.f);
}

// =================== bilinear gather + weighted accumulate ===================
// one warp per (b, q, h); lane = head_dim element -> each corner read = 128B coalesced line
__global__ __launch_bounds__(256) void msda_sample()
{
    int warp = (blockIdx.x * blockDim.x + threadIdx.x) >> 5;
    int lane = threadIdx.x & 31;
    if (warp >= NQ * NUM_HEADS) return;
    int h  = warp & 7;
    int bq = warp >> 3;
    int b  = bq / LQ_;

    const float4* samp = &g_samp[(long)warp * 16];
    const float* vb = g_v + (long)b * LEN_V_ * EMBED + h * HEAD_DIM + lane;

    const int   Wl[4]     = {128, 64, 32, 16};
    const int   starts[4] = {0, 16384, 20480, 21504};

    float acc = 0.f;
    #pragma unroll
    for (int l = 0; l < 4; l++) {
        const int W = Wl[l];
        const int H = W;
        const float* vl = vb + (long)starts[l] * EMBED;
        #pragma unroll
        for (int p = 0; p < 4; p++) {
            float4 sp = samp[l * 4 + p];     // uniform across warp
            float px = sp.x * (float)W - 0.5f;
            float py = sp.y * (float)H - 0.5f;
            float x0f = floorf(px), y0f = floorf(py);
            float dx = px - x0f, dy = py - y0f;
            int x0 = (int)x0f, y0 = (int)y0f;
            float w00 = (1.f - dx) * (1.f - dy) * sp.z;
            float w10 = dx * (1.f - dy) * sp.z;
            float w01 = (1.f - dx) * dy * sp.z;
            float w11 = dx * dy * sp.z;
            bool xv0 = (x0 >= 0) && (x0 < W);
            bool xv1 = (x0 >= -1) && (x0 + 1 < W);
            bool yv0 = (y0 >= 0) && (y0 < H);
            bool yv1 = (y0 >= -1) && (y0 + 1 < H);
            if (xv0 && yv0) acc += w00 * vl[((long)y0 * W + x0) * EMBED];
            if (xv1 && yv0) acc += w10 * vl[((long)y0 * W + x0 + 1) * EMBED];
            if (xv0 && yv1) acc += w01 * vl[((long)(y0 + 1) * W + x0) * EMBED];
            if (xv1 && yv1) acc += w11 * vl[((long)(y0 + 1) * W + x0 + 1) * EMBED];
        }
    }
    g_mid[(long)bq * EMBED + h * HEAD_DIM + lane] = acc;
}

// =================== launch ===================
extern "C" void kernel_launch(void* const* d_in, const int* in_sizes, int n_in,
                              void* d_out, int out_size)
{
    const float* query   = (const float*)d_in[0];
    const float* refp    = (const float*)d_in[1];
    const float* value   = (const float*)d_in[2];
    const float* w_value = (const float*)d_in[3];
    const float* b_value = (const float*)d_in[4];
    const float* w_off   = (const float*)d_in[5];
    const float* b_off   = (const float*)d_in[6];
    const float* w_attn  = (const float*)d_in[7];
    const float* b_attn  = (const float*)d_in[8];
    const float* w_out   = (const float*)d_in[9];
    const float* b_out   = (const float*)d_in[10];
    float* out = (float*)d_out;

    float *pv, *poff, *paw, *pmid;
    cudaGetSymbolAddress((void**)&pv,   g_v);
    cudaGetSymbolAddress((void**)&poff, g_off);
    cudaGetSymbolAddress((void**)&paw,  g_aw);
    cudaGetSymbolAddress((void**)&pmid, g_mid);

    static int smem_set = 0;
    if (!smem_set) {
        cudaFuncSetAttribute(tf32_gemm_bias,
                             cudaFuncAttributeMaxDynamicSharedMemorySize, GEMM_SMEM);
        smem_set = 1;
    }

    // Launch order puts the big v-GEMM at position 4 (the slot ncu captures).
    // 1) off = query @ w_off + b_off     (7200 x 256 x 256)
    {
        dim3 grid(256 / BN, (NQ + BM - 1) / BM);
        tf32_gemm_bias<<<grid, 256, GEMM_SMEM>>>(query, w_off, b_off, poff, NQ, 256, EMBED);
    }
    // 2) aw = query @ w_attn + b_attn    (7200 x 128 x 256)
    {
        dim3 grid(128 / BN, (NQ + BM - 1) / BM);
        tf32_gemm_bias<<<grid, 256, GEMM_SMEM>>>(query, w_attn, b_attn, paw, NQ, 128, EMBED);
    }
    // 3) softmax + sampling locations
    {
        int total = NQ * NUM_HEADS * 4;
        softmax_loc4<<<(total + 255) / 256, 256>>>(refp);
    }
    // 4) v = value @ w_value + b_value   (174080 x 256 x 256)  <- profiled slot
    {
        dim3 grid(EMBED / BN, (MV + BM - 1) / BM);
        tf32_gemm_bias<<<grid, 256, GEMM_SMEM>>>(value, w_value, b_value, pv, MV, EMBED, EMBED);
    }
    // 5) bilinear sample + weighted sum  (one warp per (b,q,h))
    {
        int warps = NQ * NUM_HEADS;                 // 57600
        msda_sample<<<(warps * 32 + 255) / 256, 256>>>();
    }
    // 6) out = mid @ w_out + b_out -> d_out
    {
        dim3 grid(EMBED / BN, (NQ + BM - 1) / BM);
        tf32_gemm_bias<<<grid, 256, GEMM_SMEM>>>(pmid, w_out, b_out, out, NQ, EMBED, EMBED);
    }
}

// round 4
// speedup vs baseline: 1.7631x; 1.7631x over previous
#include <cuda_runtime.h>
#include <cuda_bf16.h>
#include <math.h>
#include <stdint.h>

#define NUM_HEADS  8
#define NUM_LEVELS 4
#define NUM_POINTS 4
#define HEAD_DIM   32
#define EMBED      256
#define BS_        8
#define LQ_        900
#define LEN_V_     21760
#define NQ   (BS_*LQ_)        // 7200
#define MV   (BS_*LEN_V_)     // 174080

// -------- scratch (device globals; no allocations allowed) --------
__device__ float  g_v  [(size_t)MV*EMBED];          // projected value, 178 MB
__device__ float  g_off[(size_t)NQ*256];
__device__ float  g_aw [(size_t)NQ*128];
__device__ float4 g_samp[(size_t)NQ*NUM_HEADS*16];  // (locx, locy, weight, _)
__device__ float  g_mid[(size_t)NQ*EMBED];

// ============ bf16 split-2 tensor GEMM: C = A(MxK)*B(KxN) + bias =============
// a = a0 + a1 (bf16 each); c += a0*b0 + a0*b1 + a1*b0  (error ~2^-15)
// Block 128x128, K-tile 32, 8 warps (2Mx4N), warp tile 64x32,
// mma.sync.m16n8k16.bf16, all fragment loads via ldmatrix.x4.
#define BM 128
#define BN 128
#define BK 32
#define LDW 20                       // 32-bit words per smem row (16 data + 4 pad)
#define TILE_WORDS (BM * LDW)        // 2560
#define GEMM_SMEM (4 * TILE_WORDS * 4)  // As0,As1,Bs0,Bs1 = 40960 B

__device__ __forceinline__ void split2(float a, float b, uint32_t& hi, uint32_t& lo) {
    __nv_bfloat162 h = __floats2bfloat162_rn(a, b);
    float ra = a - __bfloat162float(h.x);
    float rb = b - __bfloat162float(h.y);
    __nv_bfloat162 l = __floats2bfloat162_rn(ra, rb);
    hi = *reinterpret_cast<uint32_t*>(&h);
    lo = *reinterpret_cast<uint32_t*>(&l);
}

__device__ __forceinline__ void ldsm_x4(uint32_t& r0, uint32_t& r1, uint32_t& r2,
                                        uint32_t& r3, uint32_t addr) {
    asm volatile("ldmatrix.sync.aligned.m8n8.x4.shared.b16 {%0,%1,%2,%3}, [%4];"
                 : "=r"(r0), "=r"(r1), "=r"(r2), "=r"(r3) : "r"(addr));
}

__device__ __forceinline__ void mma_bf16(float* c, const uint32_t* a, const uint32_t* b) {
    asm volatile(
        "mma.sync.aligned.m16n8k16.row.col.f32.bf16.bf16.f32 "
        "{%0,%1,%2,%3}, {%4,%5,%6,%7}, {%8,%9}, {%0,%1,%2,%3};\n"
        : "+f"(c[0]), "+f"(c[1]), "+f"(c[2]), "+f"(c[3])
        : "r"(a[0]), "r"(a[1]), "r"(a[2]), "r"(a[3]), "r"(b[0]), "r"(b[1]));
}

__global__ __launch_bounds__(256) void bf16x3_gemm_bias(
    const float* __restrict__ A, const float* __restrict__ B,
    const float* __restrict__ bias, float* __restrict__ C,
    int M, int N, int K)
{
    extern __shared__ uint32_t smem[];
    uint32_t* As0 = smem;
    uint32_t* As1 = smem + TILE_WORDS;
    uint32_t* Bs0 = smem + 2 * TILE_WORDS;
    uint32_t* Bs1 = smem + 3 * TILE_WORDS;

    const int tid   = threadIdx.x;
    const int lane  = tid & 31;
    const int warp  = tid >> 5;
    const int warpM = warp >> 2;      // 0..1
    const int warpN = warp & 3;       // 0..3
    const int brow  = blockIdx.y * BM;
    const int bcol  = blockIdx.x * BN;
    const int g     = lane >> 2;
    const int tg    = lane & 3;

    const uint32_t s_as0 = (uint32_t)__cvta_generic_to_shared(As0);
    const uint32_t s_bs0 = (uint32_t)__cvta_generic_to_shared(Bs0);
    const uint32_t lohalf = TILE_WORDS * 4;  // byte offset As0->As1 / Bs0->Bs1

    // per-thread ldmatrix byte offsets (k-word offset added per ks)
    const uint32_t a_off = (((lane & 15) * LDW) + ((lane >> 4) << 2)) * 4;
    const uint32_t b_off = ((((lane & 7) + ((lane >> 4) << 3)) * LDW) + (((lane >> 3) & 1) << 2)) * 4;

    float acc[4][4][4];
    #pragma unroll
    for (int i = 0; i < 4; i++)
        #pragma unroll
        for (int j = 0; j < 4; j++)
            #pragma unroll
            for (int r = 0; r < 4; r++) acc[i][j][r] = 0.f;

    // ---- global prefetch registers
    float4 pa[4];
    float2 qb0[4], qb1[4];
    auto load_tiles = [&](int kt) {
        #pragma unroll
        for (int i = 0; i < 4; i++) {
            int idx  = tid + i * 256;
            int arow = idx >> 3;           // 0..127
            int ac4  = idx & 7;            // k float4 index
            int grow = brow + arow;
            pa[i] = make_float4(0.f, 0.f, 0.f, 0.f);
            if (grow < M)
                pa[i] = *reinterpret_cast<const float4*>(&A[(long)grow * K + kt + ac4 * 4]);
        }
        #pragma unroll
        for (int i = 0; i < 4; i++) {
            int idx = tid + i * 256;
            int kp  = idx & 15;            // k-pair index 0..15
            int np  = idx >> 4;            // n-pair index 0..63  (idx<1024)
            np &= 63;
            qb0[i] = *reinterpret_cast<const float2*>(&B[(long)(kt + 2 * kp)     * N + bcol + 2 * np]);
            qb1[i] = *reinterpret_cast<const float2*>(&B[(long)(kt + 2 * kp + 1) * N + bcol + 2 * np]);
        }
    };

    load_tiles(0);

    for (int kt = 0; kt < K; kt += BK) {
        // ---- split + store to smem (bf16x2 words, k-major pairs)
        #pragma unroll
        for (int i = 0; i < 4; i++) {
            int idx  = tid + i * 256;
            int arow = idx >> 3;
            int ac4  = idx & 7;
            uint32_t h0, l0, h1, l1;
            split2(pa[i].x, pa[i].y, h0, l0);
            split2(pa[i].z, pa[i].w, h1, l1);
            As0[arow * LDW + ac4 * 2]     = h0;
            As0[arow * LDW + ac4 * 2 + 1] = h1;
            As1[arow * LDW + ac4 * 2]     = l0;
            As1[arow * LDW + ac4 * 2 + 1] = l1;
        }
        #pragma unroll
        for (int i = 0; i < 4; i++) {
            int idx = tid + i * 256;
            int kp  = idx & 15;
            int np  = (idx >> 4) & 63;
            uint32_t h0, l0, h1, l1;
            split2(qb0[i].x, qb1[i].x, h0, l0);   // n = 2np
            split2(qb0[i].y, qb1[i].y, h1, l1);   // n = 2np+1
            Bs0[(2 * np)     * LDW + kp] = h0;
            Bs0[(2 * np + 1) * LDW + kp] = h1;
            Bs1[(2 * np)     * LDW + kp] = l0;
            Bs1[(2 * np + 1) * LDW + kp] = l1;
        }
        __syncthreads();

        if (kt + BK < K) load_tiles(kt + BK);

        #pragma unroll
        for (int ks = 0; ks < 2; ks++) {
            const uint32_t kb = ks * 8 * 4;   // byte offset of k-word block
            uint32_t ah[4][4], al[4][4], bh[4][2], bl[4][2];
            #pragma unroll
            for (int mt = 0; mt < 4; mt++) {
                uint32_t base = s_as0 + a_off + (uint32_t)((warpM * 64 + mt * 16) * LDW * 4) + kb;
                ldsm_x4(ah[mt][0], ah[mt][1], ah[mt][2], ah[mt][3], base);
                ldsm_x4(al[mt][0], al[mt][1], al[mt][2], al[mt][3], base + lohalf);
            }
            #pragma unroll
            for (int p = 0; p < 2; p++) {      // nt pair: covers nt=2p, 2p+1
                uint32_t base = s_bs0 + b_off + (uint32_t)((warpN * 32 + p * 16) * LDW * 4) + kb;
                ldsm_x4(bh[2*p][0], bh[2*p][1], bh[2*p+1][0], bh[2*p+1][1], base);
                ldsm_x4(bl[2*p][0], bl[2*p][1], bl[2*p+1][0], bl[2*p+1][1], base + lohalf);
            }
            #pragma unroll
            for (int mt = 0; mt < 4; mt++)
                #pragma unroll
                for (int nt = 0; nt < 4; nt++) {
                    mma_bf16(acc[mt][nt], ah[mt], bh[nt]);   // a0*b0
                    mma_bf16(acc[mt][nt], ah[mt], bl[nt]);   // a0*b1
                    mma_bf16(acc[mt][nt], al[mt], bh[nt]);   // a1*b0
                }
        }
        __syncthreads();
    }

    // ---- epilogue: + bias, guarded store
    #pragma unroll
    for (int mt = 0; mt < 4; mt++) {
        int row0 = brow + warpM * 64 + mt * 16 + g;
        #pragma unroll
        for (int nt = 0; nt < 4; nt++) {
            int col = bcol + warpN * 32 + nt * 8 + tg * 2;
            float b0 = bias[col], b1 = bias[col + 1];
            if (row0 < M) {
                float2 o = make_float2(acc[mt][nt][0] + b0, acc[mt][nt][1] + b1);
                *reinterpret_cast<float2*>(&C[(long)row0 * N + col]) = o;
            }
            if (row0 + 8 < M) {
                float2 o = make_float2(acc[mt][nt][2] + b0, acc[mt][nt][3] + b1);
                *reinterpret_cast<float2*>(&C[(long)(row0 + 8) * N + col]) = o;
            }
        }
    }
}

// =================== softmax + sampling-loc precompute (4 threads per (bq,h)) ==
__global__ void softmax_loc4(const float* __restrict__ refp)
{
    int t  = blockIdx.x * blockDim.x + threadIdx.x;
    int id = t >> 2;                 // (bq, h)
    int l  = t & 3;                  // level
    if (id >= NQ * NUM_HEADS) return;
    int bq = id >> 3;
    int h  = id & 7;

    float4 a = *reinterpret_cast<const float4*>(&g_aw[(long)bq * 128 + h * 16 + l * 4]);
    float m = fmaxf(fmaxf(a.x, a.y), fmaxf(a.z, a.w));
    m = fmaxf(m, __shfl_xor_sync(0xffffffffu, m, 1));
    m = fmaxf(m, __shfl_xor_sync(0xffffffffu, m, 2));
    float e0 = expf(a.x - m), e1 = expf(a.y - m), e2 = expf(a.z - m), e3 = expf(a.w - m);
    float s = e0 + e1 + e2 + e3;
    s += __shfl_xor_sync(0xffffffffu, s, 1);
    s += __shfl_xor_sync(0xffffffffu, s, 2);
    float inv = 1.f / s;

    const float invWH[4] = {1.f/128.f, 1.f/64.f, 1.f/32.f, 1.f/16.f};
    float iw = invWH[l];
    float2 ref = *reinterpret_cast<const float2*>(&refp[((long)bq * 4 + l) * 2]);
    float4 o0 = *reinterpret_cast<const float4*>(&g_off[(long)bq * 256 + h * 32 + l * 8]);
    float4 o1 = *reinterpret_cast<const float4*>(&g_off[(long)bq * 256 + h * 32 + l * 8 + 4]);

    float4* out = &g_samp[(long)id * 16 + l * 4];
    out[0] = make_float4(ref.x + o0.x * iw, ref.y + o0.y * iw, e0 * inv, 0.f);
    out[1] = make_float4(ref.x + o0.z * iw, ref.y + o0.w * iw, e1 * inv, 0.f);
    out[2] = make_float4(ref.x + o1.x * iw, ref.y + o1.y * iw, e2 * inv, 0.f);
    out[3] = make_float4(ref.x + o1.z * iw, ref.y + o1.w * iw, e3 * inv, 0.f);
}

// =================== bilinear gather + weighted accumulate ===================
// one warp per (b, q, h); lane = head_dim element -> each corner read = 128B coalesced line
__global__ __launch_bounds__(256) void msda_sample()
{
    int warp = (blockIdx.x * blockDim.x + threadIdx.x) >> 5;
    int lane = threadIdx.x & 31;
    if (warp >= NQ * NUM_HEADS) return;
    int h  = warp & 7;
    int bq = warp >> 3;
    int b  = bq / LQ_;

    const float4* samp = &g_samp[(long)warp * 16];
    const float* vb = g_v + (long)b * LEN_V_ * EMBED + h * HEAD_DIM + lane;

    const int   Wl[4]     = {128, 64, 32, 16};
    const int   starts[4] = {0, 16384, 20480, 21504};

    float acc = 0.f;
    #pragma unroll
    for (int l = 0; l < 4; l++) {
        const int W = Wl[l];
        const int H = W;
        const float* vl = vb + (long)starts[l] * EMBED;
        #pragma unroll
        for (int p = 0; p < 4; p++) {
            float4 sp = samp[l * 4 + p];     // uniform across warp
            float px = sp.x * (float)W - 0.5f;
            float py = sp.y * (float)H - 0.5f;
            float x0f = floorf(px), y0f = floorf(py);
            float dx = px - x0f, dy = py - y0f;
            int x0 = (int)x0f, y0 = (int)y0f;
            float w00 = (1.f - dx) * (1.f - dy) * sp.z;
            float w10 = dx * (1.f - dy) * sp.z;
            float w01 = (1.f - dx) * dy * sp.z;
            float w11 = dx * dy * sp.z;
            bool xv0 = (x0 >= 0) && (x0 < W);
            bool xv1 = (x0 >= -1) && (x0 + 1 < W);
            bool yv0 = (y0 >= 0) && (y0 < H);
            bool yv1 = (y0 >= -1) && (y0 + 1 < H);
            if (xv0 && yv0) acc += w00 * vl[((long)y0 * W + x0) * EMBED];
            if (xv1 && yv0) acc += w10 * vl[((long)y0 * W + x0 + 1) * EMBED];
            if (xv0 && yv1) acc += w01 * vl[((long)(y0 + 1) * W + x0) * EMBED];
            if (xv1 && yv1) acc += w11 * vl[((long)(y0 + 1) * W + x0 + 1) * EMBED];
        }
    }
    g_mid[(long)bq * EMBED + h * HEAD_DIM + lane] = acc;
}

// =================== launch ===================
extern "C" void kernel_launch(void* const* d_in, const int* in_sizes, int n_in,
                              void* d_out, int out_size)
{
    const float* query   = (const float*)d_in[0];
    const float* refp    = (const float*)d_in[1];
    const float* value   = (const float*)d_in[2];
    const float* w_value = (const float*)d_in[3];
    const float* b_value = (const float*)d_in[4];
    const float* w_off   = (const float*)d_in[5];
    const float* b_off   = (const float*)d_in[6];
    const float* w_attn  = (const float*)d_in[7];
    const float* b_attn  = (const float*)d_in[8];
    const float* w_out   = (const float*)d_in[9];
    const float* b_out   = (const float*)d_in[10];
    float* out = (float*)d_out;

    float *pv, *poff, *paw, *pmid;
    cudaGetSymbolAddress((void**)&pv,   g_v);
    cudaGetSymbolAddress((void**)&poff, g_off);
    cudaGetSymbolAddress((void**)&paw,  g_aw);
    cudaGetSymbolAddress((void**)&pmid, g_mid);

    static int smem_set = 0;
    if (!smem_set) {
        cudaFuncSetAttribute(bf16x3_gemm_bias,
                             cudaFuncAttributeMaxDynamicSharedMemorySize, GEMM_SMEM);
        smem_set = 1;
    }

    // 1) off = query @ w_off + b_off     (7200 x 256 x 256)
    {
        dim3 grid(256 / BN, (NQ + BM - 1) / BM);
        bf16x3_gemm_bias<<<grid, 256, GEMM_SMEM>>>(query, w_off, b_off, poff, NQ, 256, EMBED);
    }
    // 2) aw = query @ w_attn + b_attn    (7200 x 128 x 256)
    {
        dim3 grid(128 / BN, (NQ + BM - 1) / BM);
        bf16x3_gemm_bias<<<grid, 256, GEMM_SMEM>>>(query, w_attn, b_attn, paw, NQ, 128, EMBED);
    }
    // 3) softmax + sampling locations
    {
        int total = NQ * NUM_HEADS * 4;
        softmax_loc4<<<(total + 255) / 256, 256>>>(refp);
    }
    // 4) v = value @ w_value + b_value   (174080 x 256 x 256)  <- profiled slot
    {
        dim3 grid(EMBED / BN, (MV + BM - 1) / BM);
        bf16x3_gemm_bias<<<grid, 256, GEMM_SMEM>>>(value, w_value, b_value, pv, MV, EMBED, EMBED);
    }
    // 5) bilinear sample + weighted sum  (one warp per (b,q,h))
    {
        int warps = NQ * NUM_HEADS;                 // 57600
        msda_sample<<<(warps * 32 + 255) / 256, 256>>>();
    }
    // 6) out = mid @ w_out + b_out -> d_out
    {
        dim3 grid(EMBED / BN, (NQ + BM - 1) / BM);
        bf16x3_gemm_bias<<<grid, 256, GEMM_SMEM>>>(pmid, w_out, b_out, out, NQ, EMBED, EMBED);
    }
}

// round 5
// speedup vs baseline: 2.3229x; 1.3175x over previous
#include <cuda_runtime.h>
#include <cuda_bf16.h>
#include <math.h>
#include <stdint.h>

#define NUM_HEADS  8
#define NUM_LEVELS 4
#define NUM_POINTS 4
#define HEAD_DIM   32
#define EMBED      256
#define BS_        8
#define LQ_        900
#define LEN_V_     21760
#define NQ   (BS_*LQ_)        // 7200
#define MV   (BS_*LEN_V_)     // 174080

// -------- scratch (device globals; no allocations allowed) --------
__device__ float  g_v  [(size_t)MV*EMBED];          // projected value, 178 MB
__device__ float  g_off[(size_t)NQ*256];
__device__ float  g_aw [(size_t)NQ*128];
__device__ float4 g_samp[(size_t)NQ*NUM_HEADS*16];  // (locx, locy, weight, _)
__device__ float  g_mid[(size_t)NQ*EMBED];

// packed weights: [n][k] bf16, hi and lo planes
__device__ __nv_bfloat16 g_wvh[256*256], g_wvl[256*256];
__device__ __nv_bfloat16 g_ofh[256*256], g_ofl[256*256];
__device__ __nv_bfloat16 g_awh[128*256], g_awl[128*256];
__device__ __nv_bfloat16 g_ouh[256*256], g_oul[256*256];

// ============ bf16 split-2 tensor GEMM: C = A(MxK)*B(KxN) + bias =============
// a = a0 + a1 (bf16 each); c += a0*b0 + a0*b1 + a1*b0  (error ~2^-15)
// Block 128x128, K-tile 32, 8 warps (2Mx4N), warp tile 64x32,
// mma.sync.m16n8k16.bf16, fragments via ldmatrix.x4,
// B pre-split/packed in global, streamed by cp.async; double-buffered smem.
#define BM 128
#define BN 128
#define BK 32
#define LDW 20                        // words per smem row (16 data + 4 pad)
#define TILE_WORDS (BM * LDW)         // 2560
#define STAGE_WORDS (4 * TILE_WORDS)  // As0,As1,Bs0,Bs1 per stage
#define GEMM_SMEM (2 * STAGE_WORDS * 4)   // 81920 B

__device__ __forceinline__ void split2(float a, float b, uint32_t& hi, uint32_t& lo) {
    __nv_bfloat162 h = __floats2bfloat162_rn(a, b);
    float ra = a - __bfloat162float(h.x);
    float rb = b - __bfloat162float(h.y);
    __nv_bfloat162 l = __floats2bfloat162_rn(ra, rb);
    hi = *reinterpret_cast<uint32_t*>(&h);
    lo = *reinterpret_cast<uint32_t*>(&l);
}

__device__ __forceinline__ void ldsm_x4(uint32_t& r0, uint32_t& r1, uint32_t& r2,
                                        uint32_t& r3, uint32_t addr) {
    asm volatile("ldmatrix.sync.aligned.m8n8.x4.shared.b16 {%0,%1,%2,%3}, [%4];"
                 : "=r"(r0), "=r"(r1), "=r"(r2), "=r"(r3) : "r"(addr));
}

__device__ __forceinline__ void mma_bf16(float* c, const uint32_t* a, const uint32_t* b) {
    asm volatile(
        "mma.sync.aligned.m16n8k16.row.col.f32.bf16.bf16.f32 "
        "{%0,%1,%2,%3}, {%4,%5,%6,%7}, {%8,%9}, {%0,%1,%2,%3};\n"
        : "+f"(c[0]), "+f"(c[1]), "+f"(c[2]), "+f"(c[3])
        : "r"(a[0]), "r"(a[1]), "r"(a[2]), "r"(a[3]), "r"(b[0]), "r"(b[1]));
}

__device__ __forceinline__ void cp16(uint32_t dst, const void* src) {
    asm volatile("cp.async.ca.shared.global [%0], [%1], 16;" :: "r"(dst), "l"(src));
}

__global__ __launch_bounds__(256) void bf16x3_gemm_bias(
    const float* __restrict__ A,
    const __nv_bfloat16* __restrict__ Bh, const __nv_bfloat16* __restrict__ Bl,
    const float* __restrict__ bias, float* __restrict__ C,
    int M, int N, int K)
{
    extern __shared__ uint32_t smem[];
    const uint32_t smem_u32 = (uint32_t)__cvta_generic_to_shared(smem);

    const int tid   = threadIdx.x;
    const int lane  = tid & 31;
    const int warp  = tid >> 5;
    const int warpM = warp >> 2;      // 0..1
    const int warpN = warp & 3;       // 0..3
    const int brow  = blockIdx.y * BM;
    const int bcol  = blockIdx.x * BN;
    const int g     = lane >> 2;
    const int tg    = lane & 3;

    const uint32_t lohalf = TILE_WORDS * 4;  // byte offset hi->lo plane

    // per-thread ldmatrix byte offsets (within a plane)
    const uint32_t a_off = (((lane & 15) * LDW) + ((lane >> 4) << 2)) * 4;
    const uint32_t b_off = ((((lane & 7) + ((lane >> 4) << 3)) * LDW) + (((lane >> 3) & 1) << 2)) * 4;

    float acc[4][4][4];
    #pragma unroll
    for (int i = 0; i < 4; i++)
        #pragma unroll
        for (int j = 0; j < 4; j++)
            #pragma unroll
            for (int r = 0; r < 4; r++) acc[i][j][r] = 0.f;

    // ---- A global prefetch registers
    float4 pa[4];
    auto load_A = [&](int kt) {
        #pragma unroll
        for (int i = 0; i < 4; i++) {
            int idx  = tid + i * 256;
            int arow = idx >> 3;           // 0..127
            int ac4  = idx & 7;            // k float4 index
            int grow = brow + arow;
            pa[i] = make_float4(0.f, 0.f, 0.f, 0.f);
            if (grow < M)
                pa[i] = *reinterpret_cast<const float4*>(&A[(long)grow * K + kt + ac4 * 4]);
        }
    };

    // split + store A regs into stage's A planes
    auto store_A = [&](int stage) {
        uint32_t* As0 = smem + stage * STAGE_WORDS;
        uint32_t* As1 = As0 + TILE_WORDS;
        #pragma unroll
        for (int i = 0; i < 4; i++) {
            int idx  = tid + i * 256;
            int arow = idx >> 3;
            int ac4  = idx & 7;
            uint32_t h0, l0, h1, l1;
            split2(pa[i].x, pa[i].y, h0, l0);
            split2(pa[i].z, pa[i].w, h1, l1);
            *reinterpret_cast<uint2*>(&As0[arow * LDW + ac4 * 2]) = make_uint2(h0, h1);
            *reinterpret_cast<uint2*>(&As1[arow * LDW + ac4 * 2]) = make_uint2(l0, l1);
        }
    };

    // cp.async B tile (pre-split/packed [n][k] bf16) into stage's B planes
    auto issue_B = [&](int stage, int kt) {
        uint32_t base = smem_u32 + (uint32_t)((stage * STAGE_WORDS + 2 * TILE_WORDS) * 4);
        #pragma unroll
        for (int i = 0; i < 2; i++) {
            int idx = tid + i * 256;       // 0..511
            int row = idx >> 2, c = idx & 3;
            cp16(base + (uint32_t)((row * LDW + c * 4) * 4),
                 Bh + ((long)(bcol + row) * K + kt + c * 8));
        }
        #pragma unroll
        for (int i = 0; i < 2; i++) {
            int idx = tid + i * 256;
            int row = idx >> 2, c = idx & 3;
            cp16(base + lohalf + (uint32_t)((row * LDW + c * 4) * 4),
                 Bl + ((long)(bcol + row) * K + kt + c * 8));
        }
        asm volatile("cp.async.commit_group;" ::: "memory");
    };

    // ---- prologue: fill stage 0
    issue_B(0, 0);
    load_A(0);
    store_A(0);
    asm volatile("cp.async.wait_group 0;" ::: "memory");
    __syncthreads();

    for (int kt = 0; kt < K; kt += BK) {
        const int s = (kt >> 5) & 1;
        const bool has_next = (kt + BK < K);
        if (has_next) {
            issue_B(s ^ 1, kt + BK);
            load_A(kt + BK);
        }

        const uint32_t s_as0 = smem_u32 + (uint32_t)(s * STAGE_WORDS * 4);
        const uint32_t s_bs0 = s_as0 + 2 * lohalf;

        #pragma unroll
        for (int ks = 0; ks < 2; ks++) {
            const uint32_t kb = ks * 8 * 4;
            uint32_t ah[4][4], al[4][4], bh[4][2], bl[4][2];
            #pragma unroll
            for (int mt = 0; mt < 4; mt++) {
                uint32_t base = s_as0 + a_off + (uint32_t)((warpM * 64 + mt * 16) * LDW * 4) + kb;
                ldsm_x4(ah[mt][0], ah[mt][1], ah[mt][2], ah[mt][3], base);
                ldsm_x4(al[mt][0], al[mt][1], al[mt][2], al[mt][3], base + lohalf);
            }
            #pragma unroll
            for (int p = 0; p < 2; p++) {
                uint32_t base = s_bs0 + b_off + (uint32_t)((warpN * 32 + p * 16) * LDW * 4) + kb;
                ldsm_x4(bh[2*p][0], bh[2*p][1], bh[2*p+1][0], bh[2*p+1][1], base);
                ldsm_x4(bl[2*p][0], bl[2*p][1], bl[2*p+1][0], bl[2*p+1][1], base + lohalf);
            }
            #pragma unroll
            for (int mt = 0; mt < 4; mt++)
                #pragma unroll
                for (int nt = 0; nt < 4; nt++) {
                    mma_bf16(acc[mt][nt], ah[mt], bh[nt]);   // a0*b0
                    mma_bf16(acc[mt][nt], ah[mt], bl[nt]);   // a0*b1
                    mma_bf16(acc[mt][nt], al[mt], bh[nt]);   // a1*b0
                }
        }

        if (has_next) {
            store_A(s ^ 1);
            asm volatile("cp.async.wait_group 0;" ::: "memory");
        }
        __syncthreads();
    }

    // ---- epilogue: + bias, guarded store
    #pragma unroll
    for (int mt = 0; mt < 4; mt++) {
        int row0 = brow + warpM * 64 + mt * 16 + g;
        #pragma unroll
        for (int nt = 0; nt < 4; nt++) {
            int col = bcol + warpN * 32 + nt * 8 + tg * 2;
            float b0 = bias[col], b1 = bias[col + 1];
            if (row0 < M) {
                float2 o = make_float2(acc[mt][nt][0] + b0, acc[mt][nt][1] + b1);
                *reinterpret_cast<float2*>(&C[(long)row0 * N + col]) = o;
            }
            if (row0 + 8 < M) {
                float2 o = make_float2(acc[mt][nt][2] + b0, acc[mt][nt][3] + b1);
                *reinterpret_cast<float2*>(&C[(long)(row0 + 8) * N + col]) = o;
            }
        }
    }
}

// =================== weight pack: W[K][N] fp32 -> hi/lo [n][k] bf16 ==========
__global__ void pack_w(const float* __restrict__ W,
                       __nv_bfloat16* __restrict__ hi, __nv_bfloat16* __restrict__ lo,
                       int K, int N)
{
    int idx = blockIdx.x * blockDim.x + threadIdx.x;
    if (idx >= K * N) return;
    int n = idx / K, k = idx - n * K;
    float f = W[(long)k * N + n];
    __nv_bfloat16 h = __float2bfloat16(f);
    __nv_bfloat16 l = __float2bfloat16(f - __bfloat162float(h));
    hi[idx] = h;
    lo[idx] = l;
}

// =================== softmax + sampling-loc precompute (4 threads per (bq,h)) ==
__global__ void softmax_loc4(const float* __restrict__ refp)
{
    int t  = blockIdx.x * blockDim.x + threadIdx.x;
    int id = t >> 2;                 // (bq, h)
    int l  = t & 3;                  // level
    if (id >= NQ * NUM_HEADS) return;
    int bq = id >> 3;
    int h  = id & 7;

    float4 a = *reinterpret_cast<const float4*>(&g_aw[(long)bq * 128 + h * 16 + l * 4]);
    float m = fmaxf(fmaxf(a.x, a.y), fmaxf(a.z, a.w));
    m = fmaxf(m, __shfl_xor_sync(0xffffffffu, m, 1));
    m = fmaxf(m, __shfl_xor_sync(0xffffffffu, m, 2));
    float e0 = expf(a.x - m), e1 = expf(a.y - m), e2 = expf(a.z - m), e3 = expf(a.w - m);
    float s = e0 + e1 + e2 + e3;
    s += __shfl_xor_sync(0xffffffffu, s, 1);
    s += __shfl_xor_sync(0xffffffffu, s, 2);
    float inv = 1.f / s;

    const float invWH[4] = {1.f/128.f, 1.f/64.f, 1.f/32.f, 1.f/16.f};
    float iw = invWH[l];
    float2 ref = *reinterpret_cast<const float2*>(&refp[((long)bq * 4 + l) * 2]);
    float4 o0 = *reinterpret_cast<const float4*>(&g_off[(long)bq * 256 + h * 32 + l * 8]);
    float4 o1 = *reinterpret_cast<const float4*>(&g_off[(long)bq * 256 + h * 32 + l * 8 + 4]);

    float4* out = &g_samp[(long)id * 16 + l * 4];
    out[0] = make_float4(ref.x + o0.x * iw, ref.y + o0.y * iw, e0 * inv, 0.f);
    out[1] = make_float4(ref.x + o0.z * iw, ref.y + o0.w * iw, e1 * inv, 0.f);
    out[2] = make_float4(ref.x + o1.x * iw, ref.y + o1.y * iw, e2 * inv, 0.f);
    out[3] = make_float4(ref.x + o1.z * iw, ref.y + o1.w * iw, e3 * inv, 0.f);
}

// =================== bilinear gather + weighted accumulate ===================
// one warp per (b, q, h); lane = head_dim element -> each corner read = 128B coalesced line
__global__ __launch_bounds__(256) void msda_sample()
{
    int warp = (blockIdx.x * blockDim.x + threadIdx.x) >> 5;
    int lane = threadIdx.x & 31;
    if (warp >= NQ * NUM_HEADS) return;
    int h  = warp & 7;
    int bq = warp >> 3;
    int b  = bq / LQ_;

    const float4* samp = &g_samp[(long)warp * 16];
    const float* vb = g_v + (long)b * LEN_V_ * EMBED + h * HEAD_DIM + lane;

    const int   Wl[4]     = {128, 64, 32, 16};
    const int   starts[4] = {0, 16384, 20480, 21504};

    float acc = 0.f;
    #pragma unroll
    for (int l = 0; l < 4; l++) {
        const int W = Wl[l];
        const int H = W;
        const float* vl = vb + (long)starts[l] * EMBED;
        #pragma unroll
        for (int p = 0; p < 4; p++) {
            float4 sp = samp[l * 4 + p];     // uniform across warp
            float px = sp.x * (float)W - 0.5f;
            float py = sp.y * (float)H - 0.5f;
            float x0f = floorf(px), y0f = floorf(py);
            float dx = px - x0f, dy = py - y0f;
            int x0 = (int)x0f, y0 = (int)y0f;
            float w00 = (1.f - dx) * (1.f - dy) * sp.z;
            float w10 = dx * (1.f - dy) * sp.z;
            float w01 = (1.f - dx) * dy * sp.z;
            float w11 = dx * dy * sp.z;
            bool xv0 = (x0 >= 0) && (x0 < W);
            bool xv1 = (x0 >= -1) && (x0 + 1 < W);
            bool yv0 = (y0 >= 0) && (y0 < H);
            bool yv1 = (y0 >= -1) && (y0 + 1 < H);
            if (xv0 && yv0) acc += w00 * vl[((long)y0 * W + x0) * EMBED];
            if (xv1 && yv0) acc += w10 * vl[((long)y0 * W + x0 + 1) * EMBED];
            if (xv0 && yv1) acc += w01 * vl[((long)(y0 + 1) * W + x0) * EMBED];
            if (xv1 && yv1) acc += w11 * vl[((long)(y0 + 1) * W + x0 + 1) * EMBED];
        }
    }
    g_mid[(long)bq * EMBED + h * HEAD_DIM + lane] = acc;
}

// =================== launch ===================
extern "C" void kernel_launch(void* const* d_in, const int* in_sizes, int n_in,
                              void* d_out, int out_size)
{
    const float* query   = (const float*)d_in[0];
    const float* refp    = (const float*)d_in[1];
    const float* value   = (const float*)d_in[2];
    const float* w_value = (const float*)d_in[3];
    const float* b_value = (const float*)d_in[4];
    const float* w_off   = (const float*)d_in[5];
    const float* b_off   = (const float*)d_in[6];
    const float* w_attn  = (const float*)d_in[7];
    const float* b_attn  = (const float*)d_in[8];
    const float* w_out   = (const float*)d_in[9];
    const float* b_out   = (const float*)d_in[10];
    float* out = (float*)d_out;

    float *pv, *poff, *paw, *pmid;
    cudaGetSymbolAddress((void**)&pv,   g_v);
    cudaGetSymbolAddress((void**)&poff, g_off);
    cudaGetSymbolAddress((void**)&paw,  g_aw);
    cudaGetSymbolAddress((void**)&pmid, g_mid);

    __nv_bfloat16 *wvh, *wvl, *ofh, *ofl, *awh, *awl, *ouh, *oul;
    cudaGetSymbolAddress((void**)&wvh, g_wvh);  cudaGetSymbolAddress((void**)&wvl, g_wvl);
    cudaGetSymbolAddress((void**)&ofh, g_ofh);  cudaGetSymbolAddress((void**)&ofl, g_ofl);
    cudaGetSymbolAddress((void**)&awh, g_awh);  cudaGetSymbolAddress((void**)&awl, g_awl);
    cudaGetSymbolAddress((void**)&ouh, g_ouh);  cudaGetSymbolAddress((void**)&oul, g_oul);

    static int smem_set = 0;
    if (!smem_set) {
        cudaFuncSetAttribute(bf16x3_gemm_bias,
                             cudaFuncAttributeMaxDynamicSharedMemorySize, GEMM_SMEM);
        smem_set = 1;
    }

    // 0) pack weights (tiny)
    pack_w<<<(256*256 + 255) / 256, 256>>>(w_value, wvh, wvl, 256, 256);
    pack_w<<<(256*256 + 255) / 256, 256>>>(w_off,   ofh, ofl, 256, 256);
    pack_w<<<(128*256 + 255) / 256, 256>>>(w_attn,  awh, awl, 256, 128);
    pack_w<<<(256*256 + 255) / 256, 256>>>(w_out,   ouh, oul, 256, 256);

    // 1) off = query @ w_off + b_off     (7200 x 256 x 256)
    {
        dim3 grid(256 / BN, (NQ + BM - 1) / BM);
        bf16x3_gemm_bias<<<grid, 256, GEMM_SMEM>>>(query, ofh, ofl, b_off, poff, NQ, 256, EMBED);
    }
    // 2) aw = query @ w_attn + b_attn    (7200 x 128 x 256)
    {
        dim3 grid(128 / BN, (NQ + BM - 1) / BM);
        bf16x3_gemm_bias<<<grid, 256, GEMM_SMEM>>>(query, awh, awl, b_attn, paw, NQ, 128, EMBED);
    }
    // 3) softmax + sampling locations
    {
        int total = NQ * NUM_HEADS * 4;
        softmax_loc4<<<(total + 255) / 256, 256>>>(refp);
    }
    // 4) v = value @ w_value + b_value   (174080 x 256 x 256)
    {
        dim3 grid(EMBED / BN, (MV + BM - 1) / BM);
        bf16x3_gemm_bias<<<grid, 256, GEMM_SMEM>>>(value, wvh, wvl, b_value, pv, MV, EMBED, EMBED);
    }
    // 5) bilinear sample + weighted sum  (one warp per (b,q,h))
    {
        int warps = NQ * NUM_HEADS;                 // 57600
        msda_sample<<<(warps * 32 + 255) / 256, 256>>>();
    }
    // 6) out = mid @ w_out + b_out -> d_out
    {
        dim3 grid(EMBED / BN, (NQ + BM - 1) / BM);
        bf16x3_gemm_bias<<<grid, 256, GEMM_SMEM>>>(pmid, ouh, oul, b_out, out, NQ, EMBED, EMBED);
    }
}

// round 8
// speedup vs baseline: 2.6422x; 1.1375x over previous
#include <cuda_runtime.h>
#include <cuda_bf16.h>
#include <math.h>
#include <stdint.h>

#define NUM_HEADS  8
#define NUM_LEVELS 4
#define NUM_POINTS 4
#define HEAD_DIM   32
#define EMBED      256
#define BS_        8
#define LQ_        900
#define LEN_V_     21760
#define NQ   (BS_*LQ_)        // 7200
#define MV   (BS_*LEN_V_)     // 174080

// single extern shared declaration for the whole TU
extern __shared__ char dsmem[];

// -------- scratch (device globals; no allocations allowed) --------
__device__ float  g_v  [(size_t)MV*EMBED];          // projected value, 178 MB
__device__ float  g_off[(size_t)NQ*256];
__device__ float  g_aw [(size_t)NQ*128];
__device__ float4 g_samp[(size_t)NQ*NUM_HEADS*16];  // (locx, locy, weight, _)
__device__ float  g_mid[(size_t)NQ*EMBED];

// packed weights: [n][k] bf16, hi and lo planes
__device__ __nv_bfloat16 g_wvh[256*256], g_wvl[256*256];
__device__ __nv_bfloat16 g_ofh[256*256], g_ofl[256*256];
__device__ __nv_bfloat16 g_awh[128*256], g_awl[128*256];
__device__ __nv_bfloat16 g_ouh[256*256], g_oul[256*256];

// ======================= common helpers =======================
__device__ __forceinline__ void split2(float a, float b, uint32_t& hi, uint32_t& lo) {
    __nv_bfloat162 h = __floats2bfloat162_rn(a, b);
    float ra = a - __bfloat162float(h.x);
    float rb = b - __bfloat162float(h.y);
    __nv_bfloat162 l = __floats2bfloat162_rn(ra, rb);
    hi = *reinterpret_cast<uint32_t*>(&h);
    lo = *reinterpret_cast<uint32_t*>(&l);
}

__device__ __forceinline__ void cp16(uint32_t dst, const void* src) {
    asm volatile("cp.async.ca.shared.global [%0], [%1], 16;" :: "r"(dst), "l"(src));
}

__device__ __forceinline__ void ldsm_x4(uint32_t& r0, uint32_t& r1, uint32_t& r2,
                                        uint32_t& r3, uint32_t addr) {
    asm volatile("ldmatrix.sync.aligned.m8n8.x4.shared.b16 {%0,%1,%2,%3}, [%4];"
                 : "=r"(r0), "=r"(r1), "=r"(r2), "=r"(r3) : "r"(addr));
}

__device__ __forceinline__ void mma_bf16(float* c, const uint32_t* a, const uint32_t* b) {
    asm volatile(
        "mma.sync.aligned.m16n8k16.row.col.f32.bf16.bf16.f32 "
        "{%0,%1,%2,%3}, {%4,%5,%6,%7}, {%8,%9}, {%0,%1,%2,%3};\n"
        : "+f"(c[0]), "+f"(c[1]), "+f"(c[2]), "+f"(c[3])
        : "r"(a[0]), "r"(a[1]), "r"(a[2]), "r"(a[3]), "r"(b[0]), "r"(b[1]));
}

#define LDW 20   // 32-bit words per smem row (16 data + 4 pad), conflict-free ldmatrix

// =============== v-projection GEMM: BM=128, BN=256 (full N per CTA) ===========
// C(174080x256) = A * B + bias, bf16 split-2 (3 MMA terms), double-buffered.
#define V_AS 2560                 // words per A plane (128 rows x 20)
#define V_BS 5120                 // words per B plane (256 rows x 20)
#define V_STAGE (2*V_AS + 2*V_BS) // 15360 words
#define V_SMEM (2 * V_STAGE * 4)  // 122880 B
#define V_A_LO (V_AS * 4)         // byte offset As0 -> As1
#define V_B_LO (V_BS * 4)         // byte offset Bs0 -> Bs1

__global__ __launch_bounds__(256, 1) void bf16x3_gemm_v(
    const float* __restrict__ A,
    const __nv_bfloat16* __restrict__ Bh, const __nv_bfloat16* __restrict__ Bl,
    const float* __restrict__ bias, float* __restrict__ C)
{
    uint32_t* smem = reinterpret_cast<uint32_t*>(dsmem);
    const uint32_t smem_u32 = (uint32_t)__cvta_generic_to_shared(smem);

    const int tid   = threadIdx.x;
    const int lane  = tid & 31;
    const int warp  = tid >> 5;
    const int warpM = warp >> 2;      // 0..1 (64 rows each)
    const int warpN = warp & 3;       // 0..3 (64 cols each)
    const int brow  = blockIdx.x * 128;
    const int g     = lane >> 2;
    const int tg    = lane & 3;

    const uint32_t a_off = (((lane & 15) * LDW) + ((lane >> 4) << 2)) * 4;
    const uint32_t b_off = ((((lane & 7) + ((lane >> 4) << 3)) * LDW) + (((lane >> 3) & 1) << 2)) * 4;

    float acc[4][8][4];
    #pragma unroll
    for (int i = 0; i < 4; i++)
        #pragma unroll
        for (int j = 0; j < 8; j++)
            #pragma unroll
            for (int r = 0; r < 4; r++) acc[i][j][r] = 0.f;

    float4 pa[4];
    auto load_A = [&](int kt) {
        #pragma unroll
        for (int i = 0; i < 4; i++) {
            int idx  = tid + i * 256;
            int arow = idx >> 3;          // 0..127
            int ac4  = idx & 7;
            pa[i] = *reinterpret_cast<const float4*>(&A[(long)(brow + arow) * 256 + kt + ac4 * 4]);
        }
    };

    auto store_A = [&](int stage) {
        uint32_t* As0 = smem + stage * V_STAGE;
        uint32_t* As1 = As0 + V_AS;
        #pragma unroll
        for (int i = 0; i < 4; i++) {
            int idx  = tid + i * 256;
            int arow = idx >> 3;
            int ac4  = idx & 7;
            uint32_t h0, l0, h1, l1;
            split2(pa[i].x, pa[i].y, h0, l0);
            split2(pa[i].z, pa[i].w, h1, l1);
            *reinterpret_cast<uint2*>(&As0[arow * LDW + ac4 * 2]) = make_uint2(h0, h1);
            *reinterpret_cast<uint2*>(&As1[arow * LDW + ac4 * 2]) = make_uint2(l0, l1);
        }
    };

    auto issue_B = [&](int stage, int kt) {
        uint32_t base = smem_u32 + (uint32_t)((stage * V_STAGE + 2 * V_AS) * 4);
        #pragma unroll
        for (int i = 0; i < 4; i++) {
            int idx = tid + i * 256;       // 0..1023
            int row = idx >> 2, c = idx & 3;
            cp16(base + (uint32_t)((row * LDW + c * 4) * 4),
                 Bh + ((long)row * 256 + kt + c * 8));
        }
        #pragma unroll
        for (int i = 0; i < 4; i++) {
            int idx = tid + i * 256;
            int row = idx >> 2, c = idx & 3;
            cp16(base + V_B_LO + (uint32_t)((row * LDW + c * 4) * 4),
                 Bl + ((long)row * 256 + kt + c * 8));
        }
        asm volatile("cp.async.commit_group;" ::: "memory");
    };

    issue_B(0, 0);
    load_A(0);
    store_A(0);
    asm volatile("cp.async.wait_group 0;" ::: "memory");
    __syncthreads();

    for (int kt = 0; kt < 256; kt += 32) {
        const int s = (kt >> 5) & 1;
        const bool has_next = (kt + 32 < 256);
        if (has_next) {
            issue_B(s ^ 1, kt + 32);
            load_A(kt + 32);
        }

        const uint32_t s_as0 = smem_u32 + (uint32_t)(s * V_STAGE * 4);
        const uint32_t s_bs0 = s_as0 + 2 * V_A_LO;

        #pragma unroll
        for (int ks = 0; ks < 2; ks++) {
            const uint32_t kb = ks * 8 * 4;
            uint32_t ah[4][4], al[4][4], bh[8][2], bl[8][2];
            #pragma unroll
            for (int mt = 0; mt < 4; mt++) {
                uint32_t base = s_as0 + a_off + (uint32_t)((warpM * 64 + mt * 16) * LDW * 4) + kb;
                ldsm_x4(ah[mt][0], ah[mt][1], ah[mt][2], ah[mt][3], base);
                ldsm_x4(al[mt][0], al[mt][1], al[mt][2], al[mt][3], base + V_A_LO);
            }
            #pragma unroll
            for (int p = 0; p < 4; p++) {
                uint32_t base = s_bs0 + b_off + (uint32_t)((warpN * 64 + p * 16) * LDW * 4) + kb;
                ldsm_x4(bh[2*p][0], bh[2*p][1], bh[2*p+1][0], bh[2*p+1][1], base);
                ldsm_x4(bl[2*p][0], bl[2*p][1], bl[2*p+1][0], bl[2*p+1][1], base + V_B_LO);
            }
            #pragma unroll
            for (int mt = 0; mt < 4; mt++)
                #pragma unroll
                for (int nt = 0; nt < 8; nt++) {
                    mma_bf16(acc[mt][nt], ah[mt], bh[nt]);
                    mma_bf16(acc[mt][nt], ah[mt], bl[nt]);
                    mma_bf16(acc[mt][nt], al[mt], bh[nt]);
                }
        }

        if (has_next) {
            store_A(s ^ 1);
            asm volatile("cp.async.wait_group 0;" ::: "memory");
        }
        __syncthreads();
    }

    // epilogue: + bias (M divides exactly; no guards)
    #pragma unroll
    for (int mt = 0; mt < 4; mt++) {
        long row0 = brow + warpM * 64 + mt * 16 + g;
        #pragma unroll
        for (int nt = 0; nt < 8; nt++) {
            int col = warpN * 64 + nt * 8 + tg * 2;
            float b0 = bias[col], b1 = bias[col + 1];
            *reinterpret_cast<float2*>(&C[row0 * 256 + col]) =
                make_float2(acc[mt][nt][0] + b0, acc[mt][nt][1] + b1);
            *reinterpret_cast<float2*>(&C[(row0 + 8) * 256 + col]) =
                make_float2(acc[mt][nt][2] + b0, acc[mt][nt][3] + b1);
        }
    }
}

// ============ bf16 split-2 mma.sync GEMM (small GEMMs, BN=128) =============
#define BM 128
#define BN 128
#define BK 32
#define TILE_WORDS (BM * LDW)
#define STAGE_WORDS (4 * TILE_WORDS)
#define GEMM_SMEM (2 * STAGE_WORDS * 4)

__global__ __launch_bounds__(256) void bf16x3_gemm_bias(
    const float* __restrict__ A,
    const __nv_bfloat16* __restrict__ Bh, const __nv_bfloat16* __restrict__ Bl,
    const float* __restrict__ bias, float* __restrict__ C,
    int M, int N, int K)
{
    uint32_t* smem = reinterpret_cast<uint32_t*>(dsmem);
    const uint32_t smem_u32 = (uint32_t)__cvta_generic_to_shared(smem);

    const int tid   = threadIdx.x;
    const int lane  = tid & 31;
    const int warp  = tid >> 5;
    const int warpM = warp >> 2;
    const int warpN = warp & 3;
    const int brow  = blockIdx.y * BM;
    const int bcol  = blockIdx.x * BN;
    const int g     = lane >> 2;
    const int tg    = lane & 3;

    const uint32_t lohalf = TILE_WORDS * 4;
    const uint32_t a_off = (((lane & 15) * LDW) + ((lane >> 4) << 2)) * 4;
    const uint32_t b_off = ((((lane & 7) + ((lane >> 4) << 3)) * LDW) + (((lane >> 3) & 1) << 2)) * 4;

    float acc[4][4][4];
    #pragma unroll
    for (int i = 0; i < 4; i++)
        #pragma unroll
        for (int j = 0; j < 4; j++)
            #pragma unroll
            for (int r = 0; r < 4; r++) acc[i][j][r] = 0.f;

    float4 pa[4];
    auto load_A = [&](int kt) {
        #pragma unroll
        for (int i = 0; i < 4; i++) {
            int idx  = tid + i * 256;
            int arow = idx >> 3;
            int ac4  = idx & 7;
            int grow = brow + arow;
            pa[i] = make_float4(0.f, 0.f, 0.f, 0.f);
            if (grow < M)
                pa[i] = *reinterpret_cast<const float4*>(&A[(long)grow * K + kt + ac4 * 4]);
        }
    };

    auto store_A = [&](int stage) {
        uint32_t* As0 = smem + stage * STAGE_WORDS;
        uint32_t* As1 = As0 + TILE_WORDS;
        #pragma unroll
        for (int i = 0; i < 4; i++) {
            int idx  = tid + i * 256;
            int arow = idx >> 3;
            int ac4  = idx & 7;
            uint32_t h0, l0, h1, l1;
            split2(pa[i].x, pa[i].y, h0, l0);
            split2(pa[i].z, pa[i].w, h1, l1);
            *reinterpret_cast<uint2*>(&As0[arow * LDW + ac4 * 2]) = make_uint2(h0, h1);
            *reinterpret_cast<uint2*>(&As1[arow * LDW + ac4 * 2]) = make_uint2(l0, l1);
        }
    };

    auto issue_B = [&](int stage, int kt) {
        uint32_t base = smem_u32 + (uint32_t)((stage * STAGE_WORDS + 2 * TILE_WORDS) * 4);
        #pragma unroll
        for (int i = 0; i < 2; i++) {
            int idx = tid + i * 256;
            int row = idx >> 2, c = idx & 3;
            cp16(base + (uint32_t)((row * LDW + c * 4) * 4),
                 Bh + ((long)(bcol + row) * K + kt + c * 8));
        }
        #pragma unroll
        for (int i = 0; i < 2; i++) {
            int idx = tid + i * 256;
            int row = idx >> 2, c = idx & 3;
            cp16(base + lohalf + (uint32_t)((row * LDW + c * 4) * 4),
                 Bl + ((long)(bcol + row) * K + kt + c * 8));
        }
        asm volatile("cp.async.commit_group;" ::: "memory");
    };

    issue_B(0, 0);
    load_A(0);
    store_A(0);
    asm volatile("cp.async.wait_group 0;" ::: "memory");
    __syncthreads();

    for (int kt = 0; kt < K; kt += BK) {
        const int s = (kt >> 5) & 1;
        const bool has_next = (kt + BK < K);
        if (has_next) {
            issue_B(s ^ 1, kt + BK);
            load_A(kt + BK);
        }

        const uint32_t s_as0 = smem_u32 + (uint32_t)(s * STAGE_WORDS * 4);
        const uint32_t s_bs0 = s_as0 + 2 * lohalf;

        #pragma unroll
        for (int ks = 0; ks < 2; ks++) {
            const uint32_t kb = ks * 8 * 4;
            uint32_t ah[4][4], al[4][4], bh[4][2], bl[4][2];
            #pragma unroll
            for (int mt = 0; mt < 4; mt++) {
                uint32_t base = s_as0 + a_off + (uint32_t)((warpM * 64 + mt * 16) * LDW * 4) + kb;
                ldsm_x4(ah[mt][0], ah[mt][1], ah[mt][2], ah[mt][3], base);
                ldsm_x4(al[mt][0], al[mt][1], al[mt][2], al[mt][3], base + lohalf);
            }
            #pragma unroll
            for (int p = 0; p < 2; p++) {
                uint32_t base = s_bs0 + b_off + (uint32_t)((warpN * 32 + p * 16) * LDW * 4) + kb;
                ldsm_x4(bh[2*p][0], bh[2*p][1], bh[2*p+1][0], bh[2*p+1][1], base);
                ldsm_x4(bl[2*p][0], bl[2*p][1], bl[2*p+1][0], bl[2*p+1][1], base + lohalf);
            }
            #pragma unroll
            for (int mt = 0; mt < 4; mt++)
                #pragma unroll
                for (int nt = 0; nt < 4; nt++) {
                    mma_bf16(acc[mt][nt], ah[mt], bh[nt]);
                    mma_bf16(acc[mt][nt], ah[mt], bl[nt]);
                    mma_bf16(acc[mt][nt], al[mt], bh[nt]);
                }
        }

        if (has_next) {
            store_A(s ^ 1);
            asm volatile("cp.async.wait_group 0;" ::: "memory");
        }
        __syncthreads();
    }

    #pragma unroll
    for (int mt = 0; mt < 4; mt++) {
        int row0 = brow + warpM * 64 + mt * 16 + g;
        #pragma unroll
        for (int nt = 0; nt < 4; nt++) {
            int col = bcol + warpN * 32 + nt * 8 + tg * 2;
            float b0 = bias[col], b1 = bias[col + 1];
            if (row0 < M) {
                float2 o = make_float2(acc[mt][nt][0] + b0, acc[mt][nt][1] + b1);
                *reinterpret_cast<float2*>(&C[(long)row0 * N + col]) = o;
            }
            if (row0 + 8 < M) {
                float2 o = make_float2(acc[mt][nt][2] + b0, acc[mt][nt][3] + b1);
                *reinterpret_cast<float2*>(&C[(long)(row0 + 8) * N + col]) = o;
            }
        }
    }
}

// ====== merged weight pack: all 4 weights, fp32 [K][N] -> bf16 hi/lo [n][k] ====
__global__ void pack_all(const float* __restrict__ Wv, const float* __restrict__ Wo,
                         const float* __restrict__ Wa, const float* __restrict__ Wu,
                         __nv_bfloat16* __restrict__ vh, __nv_bfloat16* __restrict__ vl,
                         __nv_bfloat16* __restrict__ oh, __nv_bfloat16* __restrict__ ol,
                         __nv_bfloat16* __restrict__ ah, __nv_bfloat16* __restrict__ al,
                         __nv_bfloat16* __restrict__ uh, __nv_bfloat16* __restrict__ ul)
{
    int idx = blockIdx.x * blockDim.x + threadIdx.x;
    const float* W; __nv_bfloat16 *hi, *lo; int local, N;
    if (idx < 65536)        { W = Wv; hi = vh; lo = vl; local = idx;          N = 256; }
    else if (idx < 131072)  { W = Wo; hi = oh; lo = ol; local = idx - 65536;  N = 256; }
    else if (idx < 163840)  { W = Wa; hi = ah; lo = al; local = idx - 131072; N = 128; }
    else if (idx < 229376)  { W = Wu; hi = uh; lo = ul; local = idx - 163840; N = 256; }
    else return;
    int n = local >> 8, k = local & 255;      // K = 256 for all
    float f = W[(long)k * N + n];
    __nv_bfloat16 h = __float2bfloat16(f);
    __nv_bfloat16 l = __float2bfloat16(f - __bfloat162float(h));
    hi[local] = h;
    lo[local] = l;
}

// =================== softmax + sampling-loc precompute (4 threads per (bq,h)) ==
__global__ void softmax_loc4(const float* __restrict__ refp)
{
    int t  = blockIdx.x * blockDim.x + threadIdx.x;
    int id = t >> 2;
    int l  = t & 3;
    if (id >= NQ * NUM_HEADS) return;
    int bq = id >> 3;
    int h  = id & 7;

    float4 a = *reinterpret_cast<const float4*>(&g_aw[(long)bq * 128 + h * 16 + l * 4]);
    float m = fmaxf(fmaxf(a.x, a.y), fmaxf(a.z, a.w));
    m = fmaxf(m, __shfl_xor_sync(0xffffffffu, m, 1));
    m = fmaxf(m, __shfl_xor_sync(0xffffffffu, m, 2));
    float e0 = expf(a.x - m), e1 = expf(a.y - m), e2 = expf(a.z - m), e3 = expf(a.w - m);
    float s = e0 + e1 + e2 + e3;
    s += __shfl_xor_sync(0xffffffffu, s, 1);
    s += __shfl_xor_sync(0xffffffffu, s, 2);
    float inv = 1.f / s;

    const float invWH[4] = {1.f/128.f, 1.f/64.f, 1.f/32.f, 1.f/16.f};
    float iw = invWH[l];
    float2 ref = *reinterpret_cast<const float2*>(&refp[((long)bq * 4 + l) * 2]);
    float4 o0 = *reinterpret_cast<const float4*>(&g_off[(long)bq * 256 + h * 32 + l * 8]);
    float4 o1 = *reinterpret_cast<const float4*>(&g_off[(long)bq * 256 + h * 32 + l * 8 + 4]);

    float4* out = &g_samp[(long)id * 16 + l * 4];
    out[0] = make_float4(ref.x + o0.x * iw, ref.y + o0.y * iw, e0 * inv, 0.f);
    out[1] = make_float4(ref.x + o0.z * iw, ref.y + o0.w * iw, e1 * inv, 0.f);
    out[2] = make_float4(ref.x + o1.x * iw, ref.y + o1.y * iw, e2 * inv, 0.f);
    out[3] = make_float4(ref.x + o1.z * iw, ref.y + o1.w * iw, e3 * inv, 0.f);
}

// =================== bilinear gather + weighted accumulate ===================
__global__ __launch_bounds__(256) void msda_sample()
{
    int warp = (blockIdx.x * blockDim.x + threadIdx.x) >> 5;
    int lane = threadIdx.x & 31;
    if (warp >= NQ * NUM_HEADS) return;
    int h  = warp & 7;
    int bq = warp >> 3;
    int b  = bq / LQ_;

    const float4* samp = &g_samp[(long)warp * 16];
    const float* vb = g_v + (long)b * LEN_V_ * EMBED + h * HEAD_DIM + lane;

    const int   Wl[4]     = {128, 64, 32, 16};
    const int   starts[4] = {0, 16384, 20480, 21504};

    float acc = 0.f;
    #pragma unroll
    for (int l = 0; l < 4; l++) {
        const int W = Wl[l];
        const int H = W;
        const float* vl = vb + (long)starts[l] * EMBED;
        #pragma unroll
        for (int p = 0; p < 4; p++) {
            float4 sp = samp[l * 4 + p];
            float px = sp.x * (float)W - 0.5f;
            float py = sp.y * (float)H - 0.5f;
            float x0f = floorf(px), y0f = floorf(py);
            float dx = px - x0f, dy = py - y0f;
            int x0 = (int)x0f, y0 = (int)y0f;
            float w00 = (1.f - dx) * (1.f - dy) * sp.z;
            float w10 = dx * (1.f - dy) * sp.z;
            float w01 = (1.f - dx) * dy * sp.z;
            float w11 = dx * dy * sp.z;
            bool xv0 = (x0 >= 0) && (x0 < W);
            bool xv1 = (x0 >= -1) && (x0 + 1 < W);
            bool yv0 = (y0 >= 0) && (y0 < H);
            bool yv1 = (y0 >= -1) && (y0 + 1 < H);
            if (xv0 && yv0) acc += w00 * vl[((long)y0 * W + x0) * EMBED];
            if (xv1 && yv0) acc += w10 * vl[((long)y0 * W + x0 + 1) * EMBED];
            if (xv0 && yv1) acc += w01 * vl[((long)(y0 + 1) * W + x0) * EMBED];
            if (xv1 && yv1) acc += w11 * vl[((long)(y0 + 1) * W + x0 + 1) * EMBED];
        }
    }
    g_mid[(long)bq * EMBED + h * HEAD_DIM + lane] = acc;
}

// =================== launch ===================
extern "C" void kernel_launch(void* const* d_in, const int* in_sizes, int n_in,
                              void* d_out, int out_size)
{
    const float* query   = (const float*)d_in[0];
    const float* refp    = (const float*)d_in[1];
    const float* value   = (const float*)d_in[2];
    const float* w_value = (const float*)d_in[3];
    const float* b_value = (const float*)d_in[4];
    const float* w_off   = (const float*)d_in[5];
    const float* b_off   = (const float*)d_in[6];
    const float* w_attn  = (const float*)d_in[7];
    const float* b_attn  = (const float*)d_in[8];
    const float* w_out   = (const float*)d_in[9];
    const float* b_out   = (const float*)d_in[10];
    float* out = (float*)d_out;

    float *pv, *poff, *paw, *pmid;
    cudaGetSymbolAddress((void**)&pv,   g_v);
    cudaGetSymbolAddress((void**)&poff, g_off);
    cudaGetSymbolAddress((void**)&paw,  g_aw);
    cudaGetSymbolAddress((void**)&pmid, g_mid);

    __nv_bfloat16 *wvh, *wvl, *ofh, *ofl, *awh, *awl, *ouh, *oul;
    cudaGetSymbolAddress((void**)&wvh, g_wvh);  cudaGetSymbolAddress((void**)&wvl, g_wvl);
    cudaGetSymbolAddress((void**)&ofh, g_ofh);  cudaGetSymbolAddress((void**)&ofl, g_ofl);
    cudaGetSymbolAddress((void**)&awh, g_awh);  cudaGetSymbolAddress((void**)&awl, g_awl);
    cudaGetSymbolAddress((void**)&ouh, g_ouh);  cudaGetSymbolAddress((void**)&oul, g_oul);

    static int smem_set = 0;
    if (!smem_set) {
        cudaFuncSetAttribute(bf16x3_gemm_bias,
                             cudaFuncAttributeMaxDynamicSharedMemorySize, GEMM_SMEM);
        cudaFuncSetAttribute(bf16x3_gemm_v,
                             cudaFuncAttributeMaxDynamicSharedMemorySize, V_SMEM);
        smem_set = 1;
    }

    // 0) pack all weights (one launch)
    pack_all<<<(229376 + 255) / 256, 256>>>(w_value, w_off, w_attn, w_out,
                                            wvh, wvl, ofh, ofl, awh, awl, ouh, oul);

    // 1) off = query @ w_off + b_off     (7200 x 256 x 256)
    {
        dim3 grid(256 / BN, (NQ + BM - 1) / BM);
        bf16x3_gemm_bias<<<grid, 256, GEMM_SMEM>>>(query, ofh, ofl, b_off, poff, NQ, 256, EMBED);
    }
    // 2) aw = query @ w_attn + b_attn    (7200 x 128 x 256)
    {
        dim3 grid(128 / BN, (NQ + BM - 1) / BM);
        bf16x3_gemm_bias<<<grid, 256, GEMM_SMEM>>>(query, awh, awl, b_attn, paw, NQ, 128, EMBED);
    }
    // 3) softmax + sampling locations
    {
        int total = NQ * NUM_HEADS * 4;
        softmax_loc4<<<(total + 255) / 256, 256>>>(refp);
    }
    // 4) v = value @ w_value + b_value   (174080 x 256 x 256) — BN=256 kernel
    {
        bf16x3_gemm_v<<<MV / 128, 256, V_SMEM>>>(value, wvh, wvl, b_value, pv);
    }
    // 5) bilinear sample + weighted sum  (one warp per (b,q,h))
    {
        int warps = NQ * NUM_HEADS;
        msda_sample<<<(warps * 32 + 255) / 256, 256>>>();
    }
    // 6) out = mid @ w_out + b_out -> d_out
    {
        dim3 grid(EMBED / BN, (NQ + BM - 1) / BM);
        bf16x3_gemm_bias<<<grid, 256, GEMM_SMEM>>>(pmid, ouh, oul, b_out, out, NQ, EMBED, EMBED);
    }
}

// round 9
// speedup vs baseline: 2.6432x; 1.0004x over previous
#include <cuda_runtime.h>
#include <cuda_bf16.h>
#include <cuda_fp16.h>
#include <math.h>
#include <stdint.h>

#define NUM_HEADS  8
#define NUM_LEVELS 4
#define NUM_POINTS 4
#define HEAD_DIM   32
#define EMBED      256
#define BS_        8
#define LQ_        900
#define LEN_V_     21760
#define NQ   (BS_*LQ_)        // 7200
#define MV   (BS_*LEN_V_)     // 174080

// single extern shared declaration for the whole TU
extern __shared__ char dsmem[];

// -------- scratch (device globals; no allocations allowed) --------
__device__ __half g_v  [(size_t)MV*EMBED];          // projected value, fp16, 89 MB
__device__ float  g_qoff[(size_t)NQ*384];           // [off(256) | attn(128)] per row
__device__ float4 g_samp[(size_t)NQ*NUM_HEADS*16];  // (locx, locy, weight, _)
__device__ float  g_mid[(size_t)NQ*EMBED];
__device__ float  g_qbias[384];

// packed weights: [n][k] bf16, hi and lo planes
__device__ __nv_bfloat16 g_wvh[256*256], g_wvl[256*256];
__device__ __nv_bfloat16 g_qh [384*256], g_ql [384*256];
__device__ __nv_bfloat16 g_ouh[256*256], g_oul[256*256];

// ======================= common helpers =======================
__device__ __forceinline__ void split2(float a, float b, uint32_t& hi, uint32_t& lo) {
    __nv_bfloat162 h = __floats2bfloat162_rn(a, b);
    float ra = a - __bfloat162float(h.x);
    float rb = b - __bfloat162float(h.y);
    __nv_bfloat162 l = __floats2bfloat162_rn(ra, rb);
    hi = *reinterpret_cast<uint32_t*>(&h);
    lo = *reinterpret_cast<uint32_t*>(&l);
}

__device__ __forceinline__ void cp16(uint32_t dst, const void* src) {
    asm volatile("cp.async.ca.shared.global [%0], [%1], 16;" :: "r"(dst), "l"(src));
}

__device__ __forceinline__ void ldsm_x4(uint32_t& r0, uint32_t& r1, uint32_t& r2,
                                        uint32_t& r3, uint32_t addr) {
    asm volatile("ldmatrix.sync.aligned.m8n8.x4.shared.b16 {%0,%1,%2,%3}, [%4];"
                 : "=r"(r0), "=r"(r1), "=r"(r2), "=r"(r3) : "r"(addr));
}

__device__ __forceinline__ void mma_bf16(float* c, const uint32_t* a, const uint32_t* b) {
    asm volatile(
        "mma.sync.aligned.m16n8k16.row.col.f32.bf16.bf16.f32 "
        "{%0,%1,%2,%3}, {%4,%5,%6,%7}, {%8,%9}, {%0,%1,%2,%3};\n"
        : "+f"(c[0]), "+f"(c[1]), "+f"(c[2]), "+f"(c[3])
        : "r"(a[0]), "r"(a[1]), "r"(a[2]), "r"(a[3]), "r"(b[0]), "r"(b[1]));
}

#define LDW 20   // 32-bit words per smem row (16 data + 4 pad), conflict-free ldmatrix

// =============== v-projection GEMM: BM=128, BN=256 (full N per CTA) ===========
// C(174080x256 fp16) = A(fp32) * B(bf16 hi/lo split) + bias, double-buffered.
#define V_AS 2560                 // words per A plane (128 rows x 20)
#define V_BS 5120                 // words per B plane (256 rows x 20)
#define V_STAGE (2*V_AS + 2*V_BS) // 15360 words
#define V_SMEM (2 * V_STAGE * 4)  // 122880 B
#define V_A_LO (V_AS * 4)         // byte offset As0 -> As1
#define V_B_LO (V_BS * 4)         // byte offset Bs0 -> Bs1

__global__ __launch_bounds__(256, 1) void bf16x3_gemm_v(
    const float* __restrict__ A,
    const __nv_bfloat16* __restrict__ Bh, const __nv_bfloat16* __restrict__ Bl,
    const float* __restrict__ bias, __half* __restrict__ C)
{
    uint32_t* smem = reinterpret_cast<uint32_t*>(dsmem);
    const uint32_t smem_u32 = (uint32_t)__cvta_generic_to_shared(smem);

    const int tid   = threadIdx.x;
    const int lane  = tid & 31;
    const int warp  = tid >> 5;
    const int warpM = warp >> 2;      // 0..1 (64 rows each)
    const int warpN = warp & 3;       // 0..3 (64 cols each)
    const int brow  = blockIdx.x * 128;
    const int g     = lane >> 2;
    const int tg    = lane & 3;

    const uint32_t a_off = (((lane & 15) * LDW) + ((lane >> 4) << 2)) * 4;
    const uint32_t b_off = ((((lane & 7) + ((lane >> 4) << 3)) * LDW) + (((lane >> 3) & 1) << 2)) * 4;

    float acc[4][8][4];
    #pragma unroll
    for (int i = 0; i < 4; i++)
        #pragma unroll
        for (int j = 0; j < 8; j++)
            #pragma unroll
            for (int r = 0; r < 4; r++) acc[i][j][r] = 0.f;

    float4 pa[4];
    auto load_A = [&](int kt) {
        #pragma unroll
        for (int i = 0; i < 4; i++) {
            int idx  = tid + i * 256;
            int arow = idx >> 3;          // 0..127
            int ac4  = idx & 7;
            pa[i] = *reinterpret_cast<const float4*>(&A[(long)(brow + arow) * 256 + kt + ac4 * 4]);
        }
    };

    auto store_A = [&](int stage) {
        uint32_t* As0 = smem + stage * V_STAGE;
        uint32_t* As1 = As0 + V_AS;
        #pragma unroll
        for (int i = 0; i < 4; i++) {
            int idx  = tid + i * 256;
            int arow = idx >> 3;
            int ac4  = idx & 7;
            uint32_t h0, l0, h1, l1;
            split2(pa[i].x, pa[i].y, h0, l0);
            split2(pa[i].z, pa[i].w, h1, l1);
            *reinterpret_cast<uint2*>(&As0[arow * LDW + ac4 * 2]) = make_uint2(h0, h1);
            *reinterpret_cast<uint2*>(&As1[arow * LDW + ac4 * 2]) = make_uint2(l0, l1);
        }
    };

    auto issue_B = [&](int stage, int kt) {
        uint32_t base = smem_u32 + (uint32_t)((stage * V_STAGE + 2 * V_AS) * 4);
        #pragma unroll
        for (int i = 0; i < 4; i++) {
            int idx = tid + i * 256;       // 0..1023
            int row = idx >> 2, c = idx & 3;
            cp16(base + (uint32_t)((row * LDW + c * 4) * 4),
                 Bh + ((long)row * 256 + kt + c * 8));
        }
        #pragma unroll
        for (int i = 0; i < 4; i++) {
            int idx = tid + i * 256;
            int row = idx >> 2, c = idx & 3;
            cp16(base + V_B_LO + (uint32_t)((row * LDW + c * 4) * 4),
                 Bl + ((long)row * 256 + kt + c * 8));
        }
        asm volatile("cp.async.commit_group;" ::: "memory");
    };

    issue_B(0, 0);
    load_A(0);
    store_A(0);
    asm volatile("cp.async.wait_group 0;" ::: "memory");
    __syncthreads();

    for (int kt = 0; kt < 256; kt += 32) {
        const int s = (kt >> 5) & 1;
        const bool has_next = (kt + 32 < 256);
        if (has_next) {
            issue_B(s ^ 1, kt + 32);
            load_A(kt + 32);
        }

        const uint32_t s_as0 = smem_u32 + (uint32_t)(s * V_STAGE * 4);
        const uint32_t s_bs0 = s_as0 + 2 * V_A_LO;

        #pragma unroll
        for (int ks = 0; ks < 2; ks++) {
            const uint32_t kb = ks * 8 * 4;
            uint32_t ah[4][4], al[4][4], bh[8][2], bl[8][2];
            #pragma unroll
            for (int mt = 0; mt < 4; mt++) {
                uint32_t base = s_as0 + a_off + (uint32_t)((warpM * 64 + mt * 16) * LDW * 4) + kb;
                ldsm_x4(ah[mt][0], ah[mt][1], ah[mt][2], ah[mt][3], base);
                ldsm_x4(al[mt][0], al[mt][1], al[mt][2], al[mt][3], base + V_A_LO);
            }
            #pragma unroll
            for (int p = 0; p < 4; p++) {
                uint32_t base = s_bs0 + b_off + (uint32_t)((warpN * 64 + p * 16) * LDW * 4) + kb;
                ldsm_x4(bh[2*p][0], bh[2*p][1], bh[2*p+1][0], bh[2*p+1][1], base);
                ldsm_x4(bl[2*p][0], bl[2*p][1], bl[2*p+1][0], bl[2*p+1][1], base + V_B_LO);
            }
            #pragma unroll
            for (int mt = 0; mt < 4; mt++)
                #pragma unroll
                for (int nt = 0; nt < 8; nt++) {
                    mma_bf16(acc[mt][nt], ah[mt], bh[nt]);
                    mma_bf16(acc[mt][nt], ah[mt], bl[nt]);
                    mma_bf16(acc[mt][nt], al[mt], bh[nt]);
                }
        }

        if (has_next) {
            store_A(s ^ 1);
            asm volatile("cp.async.wait_group 0;" ::: "memory");
        }
        __syncthreads();
    }

    // epilogue: + bias, fp16 store (M divides exactly; no guards)
    #pragma unroll
    for (int mt = 0; mt < 4; mt++) {
        long row0 = brow + warpM * 64 + mt * 16 + g;
        #pragma unroll
        for (int nt = 0; nt < 8; nt++) {
            int col = warpN * 64 + nt * 8 + tg * 2;
            float b0 = bias[col], b1 = bias[col + 1];
            *reinterpret_cast<__half2*>(&C[row0 * 256 + col]) =
                __floats2half2_rn(acc[mt][nt][0] + b0, acc[mt][nt][1] + b1);
            *reinterpret_cast<__half2*>(&C[(row0 + 8) * 256 + col]) =
                __floats2half2_rn(acc[mt][nt][2] + b0, acc[mt][nt][3] + b1);
        }
    }
}

// ============ bf16 split-2 mma.sync GEMM (small GEMMs, BN=128) =============
#define BM 128
#define BN 128
#define BK 32
#define TILE_WORDS (BM * LDW)
#define STAGE_WORDS (4 * TILE_WORDS)
#define GEMM_SMEM (2 * STAGE_WORDS * 4)

__global__ __launch_bounds__(256) void bf16x3_gemm_bias(
    const float* __restrict__ A,
    const __nv_bfloat16* __restrict__ Bh, const __nv_bfloat16* __restrict__ Bl,
    const float* __restrict__ bias, float* __restrict__ C,
    int M, int N, int K)
{
    uint32_t* smem = reinterpret_cast<uint32_t*>(dsmem);
    const uint32_t smem_u32 = (uint32_t)__cvta_generic_to_shared(smem);

    const int tid   = threadIdx.x;
    const int lane  = tid & 31;
    const int warp  = tid >> 5;
    const int warpM = warp >> 2;
    const int warpN = warp & 3;
    const int brow  = blockIdx.y * BM;
    const int bcol  = blockIdx.x * BN;
    const int g     = lane >> 2;
    const int tg    = lane & 3;

    const uint32_t lohalf = TILE_WORDS * 4;
    const uint32_t a_off = (((lane & 15) * LDW) + ((lane >> 4) << 2)) * 4;
    const uint32_t b_off = ((((lane & 7) + ((lane >> 4) << 3)) * LDW) + (((lane >> 3) & 1) << 2)) * 4;

    float acc[4][4][4];
    #pragma unroll
    for (int i = 0; i < 4; i++)
        #pragma unroll
        for (int j = 0; j < 4; j++)
            #pragma unroll
            for (int r = 0; r < 4; r++) acc[i][j][r] = 0.f;

    float4 pa[4];
    auto load_A = [&](int kt) {
        #pragma unroll
        for (int i = 0; i < 4; i++) {
            int idx  = tid + i * 256;
            int arow = idx >> 3;
            int ac4  = idx & 7;
            int grow = brow + arow;
            pa[i] = make_float4(0.f, 0.f, 0.f, 0.f);
            if (grow < M)
                pa[i] = *reinterpret_cast<const float4*>(&A[(long)grow * K + kt + ac4 * 4]);
        }
    };

    auto store_A = [&](int stage) {
        uint32_t* As0 = smem + stage * STAGE_WORDS;
        uint32_t* As1 = As0 + TILE_WORDS;
        #pragma unroll
        for (int i = 0; i < 4; i++) {
            int idx  = tid + i * 256;
            int arow = idx >> 3;
            int ac4  = idx & 7;
            uint32_t h0, l0, h1, l1;
            split2(pa[i].x, pa[i].y, h0, l0);
            split2(pa[i].z, pa[i].w, h1, l1);
            *reinterpret_cast<uint2*>(&As0[arow * LDW + ac4 * 2]) = make_uint2(h0, h1);
            *reinterpret_cast<uint2*>(&As1[arow * LDW + ac4 * 2]) = make_uint2(l0, l1);
        }
    };

    auto issue_B = [&](int stage, int kt) {
        uint32_t base = smem_u32 + (uint32_t)((stage * STAGE_WORDS + 2 * TILE_WORDS) * 4);
        #pragma unroll
        for (int i = 0; i < 2; i++) {
            int idx = tid + i * 256;
            int row = idx >> 2, c = idx & 3;
            cp16(base + (uint32_t)((row * LDW + c * 4) * 4),
                 Bh + ((long)(bcol + row) * K + kt + c * 8));
        }
        #pragma unroll
        for (int i = 0; i < 2; i++) {
            int idx = tid + i * 256;
            int row = idx >> 2, c = idx & 3;
            cp16(base + lohalf + (uint32_t)((row * LDW + c * 4) * 4),
                 Bl + ((long)(bcol + row) * K + kt + c * 8));
        }
        asm volatile("cp.async.commit_group;" ::: "memory");
    };

    issue_B(0, 0);
    load_A(0);
    store_A(0);
    asm volatile("cp.async.wait_group 0;" ::: "memory");
    __syncthreads();

    for (int kt = 0; kt < K; kt += BK) {
        const int s = (kt >> 5) & 1;
        const bool has_next = (kt + BK < K);
        if (has_next) {
            issue_B(s ^ 1, kt + BK);
            load_A(kt + BK);
        }

        const uint32_t s_as0 = smem_u32 + (uint32_t)(s * STAGE_WORDS * 4);
        const uint32_t s_bs0 = s_as0 + 2 * lohalf;

        #pragma unroll
        for (int ks = 0; ks < 2; ks++) {
            const uint32_t kb = ks * 8 * 4;
            uint32_t ah[4][4], al[4][4], bh[4][2], bl[4][2];
            #pragma unroll
            for (int mt = 0; mt < 4; mt++) {
                uint32_t base = s_as0 + a_off + (uint32_t)((warpM * 64 + mt * 16) * LDW * 4) + kb;
                ldsm_x4(ah[mt][0], ah[mt][1], ah[mt][2], ah[mt][3], base);
                ldsm_x4(al[mt][0], al[mt][1], al[mt][2], al[mt][3], base + lohalf);
            }
            #pragma unroll
            for (int p = 0; p < 2; p++) {
                uint32_t base = s_bs0 + b_off + (uint32_t)((warpN * 32 + p * 16) * LDW * 4) + kb;
                ldsm_x4(bh[2*p][0], bh[2*p][1], bh[2*p+1][0], bh[2*p+1][1], base);
                ldsm_x4(bl[2*p][0], bl[2*p][1], bl[2*p+1][0], bl[2*p+1][1], base + lohalf);
            }
            #pragma unroll
            for (int mt = 0; mt < 4; mt++)
                #pragma unroll
                for (int nt = 0; nt < 4; nt++) {
                    mma_bf16(acc[mt][nt], ah[mt], bh[nt]);
                    mma_bf16(acc[mt][nt], ah[mt], bl[nt]);
                    mma_bf16(acc[mt][nt], al[mt], bh[nt]);
                }
        }

        if (has_next) {
            store_A(s ^ 1);
            asm volatile("cp.async.wait_group 0;" ::: "memory");
        }
        __syncthreads();
    }

    #pragma unroll
    for (int mt = 0; mt < 4; mt++) {
        int row0 = brow + warpM * 64 + mt * 16 + g;
        #pragma unroll
        for (int nt = 0; nt < 4; nt++) {
            int col = bcol + warpN * 32 + nt * 8 + tg * 2;
            float b0 = bias[col], b1 = bias[col + 1];
            if (row0 < M) {
                float2 o = make_float2(acc[mt][nt][0] + b0, acc[mt][nt][1] + b1);
                *reinterpret_cast<float2*>(&C[(long)row0 * N + col]) = o;
            }
            if (row0 + 8 < M) {
                float2 o = make_float2(acc[mt][nt][2] + b0, acc[mt][nt][3] + b1);
                *reinterpret_cast<float2*>(&C[(long)(row0 + 8) * N + col]) = o;
            }
        }
    }
}

// ====== merged weight pack: fp32 [K][N] -> bf16 hi/lo [n][k] planes ====
// sections: value(65536) | q-combined off+attn(98304) | out(65536)
__global__ void pack_all(const float* __restrict__ Wv, const float* __restrict__ Wo,
                         const float* __restrict__ Wa, const float* __restrict__ Wu,
                         const float* __restrict__ bo, const float* __restrict__ ba,
                         __nv_bfloat16* __restrict__ vh, __nv_bfloat16* __restrict__ vl,
                         __nv_bfloat16* __restrict__ qh, __nv_bfloat16* __restrict__ ql,
                         __nv_bfloat16* __restrict__ uh, __nv_bfloat16* __restrict__ ul,
                         float* __restrict__ qbias)
{
    int idx = blockIdx.x * blockDim.x + threadIdx.x;
    if (idx < 384)
        qbias[idx] = (idx < 256) ? bo[idx] : ba[idx - 256];

    float f; __nv_bfloat16 *hi, *lo; int local;
    if (idx < 65536) {
        local = idx;
        int n = local >> 8, k = local & 255;
        f = Wv[(long)k * 256 + n]; hi = vh; lo = vl;
    } else if (idx < 163840) {
        local = idx - 65536;                 // [n<384][k]
        int n = local >> 8, k = local & 255;
        f = (n < 256) ? Wo[(long)k * 256 + n] : Wa[(long)k * 128 + (n - 256)];
        hi = qh; lo = ql;
    } else if (idx < 229376) {
        local = idx - 163840;
        int n = local >> 8, k = local & 255;
        f = Wu[(long)k * 256 + n]; hi = uh; lo = ul;
    } else return;
    __nv_bfloat16 h = __float2bfloat16(f);
    __nv_bfloat16 l = __float2bfloat16(f - __bfloat162float(h));
    hi[local] = h;
    lo[local] = l;
}

// =================== softmax + sampling-loc precompute (4 threads per (bq,h)) ==
__global__ void softmax_loc4(const float* __restrict__ refp)
{
    int t  = blockIdx.x * blockDim.x + threadIdx.x;
    int id = t >> 2;
    int l  = t & 3;
    if (id >= NQ * NUM_HEADS) return;
    int bq = id >> 3;
    int h  = id & 7;

    const float* qrow = &g_qoff[(long)bq * 384];
    float4 a = *reinterpret_cast<const float4*>(&qrow[256 + h * 16 + l * 4]);
    float m = fmaxf(fmaxf(a.x, a.y), fmaxf(a.z, a.w));
    m = fmaxf(m, __shfl_xor_sync(0xffffffffu, m, 1));
    m = fmaxf(m, __shfl_xor_sync(0xffffffffu, m, 2));
    float e0 = expf(a.x - m), e1 = expf(a.y - m), e2 = expf(a.z - m), e3 = expf(a.w - m);
    float s = e0 + e1 + e2 + e3;
    s += __shfl_xor_sync(0xffffffffu, s, 1);
    s += __shfl_xor_sync(0xffffffffu, s, 2);
    float inv = 1.f / s;

    const float invWH[4] = {1.f/128.f, 1.f/64.f, 1.f/32.f, 1.f/16.f};
    float iw = invWH[l];
    float2 ref = *reinterpret_cast<const float2*>(&refp[((long)bq * 4 + l) * 2]);
    float4 o0 = *reinterpret_cast<const float4*>(&qrow[h * 32 + l * 8]);
    float4 o1 = *reinterpret_cast<const float4*>(&qrow[h * 32 + l * 8 + 4]);

    float4* out = &g_samp[(long)id * 16 + l * 4];
    out[0] = make_float4(ref.x + o0.x * iw, ref.y + o0.y * iw, e0 * inv, 0.f);
    out[1] = make_float4(ref.x + o0.z * iw, ref.y + o0.w * iw, e1 * inv, 0.f);
    out[2] = make_float4(ref.x + o1.x * iw, ref.y + o1.y * iw, e2 * inv, 0.f);
    out[3] = make_float4(ref.x + o1.z * iw, ref.y + o1.w * iw, e3 * inv, 0.f);
}

// =================== bilinear gather + weighted accumulate (fp16 v) ==========
__global__ __launch_bounds__(256) void msda_sample()
{
    int warp = (blockIdx.x * blockDim.x + threadIdx.x) >> 5;
    int lane = threadIdx.x & 31;
    if (warp >= NQ * NUM_HEADS) return;
    int h  = warp & 7;
    int bq = warp >> 3;
    int b  = bq / LQ_;

    const float4* samp = &g_samp[(long)warp * 16];
    const __half* vb = g_v + (long)b * LEN_V_ * EMBED + h * HEAD_DIM + lane;

    const int   Wl[4]     = {128, 64, 32, 16};
    const int   starts[4] = {0, 16384, 20480, 21504};

    float acc = 0.f;
    #pragma unroll
    for (int l = 0; l < 4; l++) {
        const int W = Wl[l];
        const int H = W;
        const __half* vl = vb + (long)starts[l] * EMBED;
        #pragma unroll
        for (int p = 0; p < 4; p++) {
            float4 sp = samp[l * 4 + p];
            float px = sp.x * (float)W - 0.5f;
            float py = sp.y * (float)H - 0.5f;
            float x0f = floorf(px), y0f = floorf(py);
            float dx = px - x0f, dy = py - y0f;
            int x0 = (int)x0f, y0 = (int)y0f;
            float w00 = (1.f - dx) * (1.f - dy) * sp.z;
            float w10 = dx * (1.f - dy) * sp.z;
            float w01 = (1.f - dx) * dy * sp.z;
            float w11 = dx * dy * sp.z;
            bool xv0 = (x0 >= 0) && (x0 < W);
            bool xv1 = (x0 >= -1) && (x0 + 1 < W);
            bool yv0 = (y0 >= 0) && (y0 < H);
            bool yv1 = (y0 >= -1) && (y0 + 1 < H);
            if (xv0 && yv0) acc += w00 * __half2float(vl[((long)y0 * W + x0) * EMBED]);
            if (xv1 && yv0) acc += w10 * __half2float(vl[((long)y0 * W + x0 + 1) * EMBED]);
            if (xv0 && yv1) acc += w01 * __half2float(vl[((long)(y0 + 1) * W + x0) * EMBED]);
            if (xv1 && yv1) acc += w11 * __half2float(vl[((long)(y0 + 1) * W + x0 + 1) * EMBED]);
        }
    }
    g_mid[(long)bq * EMBED + h * HEAD_DIM + lane] = acc;
}

// =================== launch ===================
extern "C" void kernel_launch(void* const* d_in, const int* in_sizes, int n_in,
                              void* d_out, int out_size)
{
    const float* query   = (const float*)d_in[0];
    const float* refp    = (const float*)d_in[1];
    const float* value   = (const float*)d_in[2];
    const float* w_value = (const float*)d_in[3];
    const float* b_value = (const float*)d_in[4];
    const float* w_off   = (const float*)d_in[5];
    const float* b_off   = (const float*)d_in[6];
    const float* w_attn  = (const float*)d_in[7];
    const float* b_attn  = (const float*)d_in[8];
    const float* w_out   = (const float*)d_in[9];
    const float* b_out   = (const float*)d_in[10];
    float* out = (float*)d_out;

    __half* pv;
    float *pqoff, *pmid, *pqbias;
    cudaGetSymbolAddress((void**)&pv,    g_v);
    cudaGetSymbolAddress((void**)&pqoff, g_qoff);
    cudaGetSymbolAddress((void**)&pmid,  g_mid);
    cudaGetSymbolAddress((void**)&pqbias,g_qbias);

    __nv_bfloat16 *wvh, *wvl, *qh, *ql, *ouh, *oul;
    cudaGetSymbolAddress((void**)&wvh, g_wvh);  cudaGetSymbolAddress((void**)&wvl, g_wvl);
    cudaGetSymbolAddress((void**)&qh,  g_qh);   cudaGetSymbolAddress((void**)&ql,  g_ql);
    cudaGetSymbolAddress((void**)&ouh, g_ouh);  cudaGetSymbolAddress((void**)&oul, g_oul);

    static int smem_set = 0;
    if (!smem_set) {
        cudaFuncSetAttribute(bf16x3_gemm_bias,
                             cudaFuncAttributeMaxDynamicSharedMemorySize, GEMM_SMEM);
        cudaFuncSetAttribute(bf16x3_gemm_v,
                             cudaFuncAttributeMaxDynamicSharedMemorySize, V_SMEM);
        smem_set = 1;
    }

    // 1) pack all weights + combined bias (one launch)
    pack_all<<<(229376 + 255) / 256, 256>>>(w_value, w_off, w_attn, w_out, b_off, b_attn,
                                            wvh, wvl, qh, ql, ouh, oul, pqbias);

    // 2) [off|aw] = query @ [w_off|w_attn] + bias   (7200 x 384 x 256)
    {
        dim3 grid(384 / BN, (NQ + BM - 1) / BM);
        bf16x3_gemm_bias<<<grid, 256, GEMM_SMEM>>>(query, qh, ql, pqbias, pqoff, NQ, 384, EMBED);
    }
    // 3) softmax + sampling locations
    {
        int total = NQ * NUM_HEADS * 4;
        softmax_loc4<<<(total + 255) / 256, 256>>>(refp);
    }
    // 4) v = value @ w_value + b_value  (174080 x 256 x 256, fp16 out) <- profiled slot
    {
        bf16x3_gemm_v<<<MV / 128, 256, V_SMEM>>>(value, wvh, wvl, b_value, pv);
    }
    // 5) bilinear sample + weighted sum  (one warp per (b,q,h))
    {
        int warps = NQ * NUM_HEADS;
        msda_sample<<<(warps * 32 + 255) / 256, 256>>>();
    }
    // 6) out = mid @ w_out + b_out -> d_out
    {
        dim3 grid(EMBED / BN, (NQ + BM - 1) / BM);
        bf16x3_gemm_bias<<<grid, 256, GEMM_SMEM>>>(pmid, ouh, oul, b_out, out, NQ, EMBED, EMBED);
    }
}

// round 10
// speedup vs baseline: 3.6612x; 1.3851x over previous
#include <cuda_runtime.h>
#include <cuda_bf16.h>
#include <cuda_fp16.h>
#include <math.h>
#include <stdint.h>

#define NUM_HEADS  8
#define NUM_LEVELS 4
#define NUM_POINTS 4
#define HEAD_DIM   32
#define EMBED      256
#define BS_        8
#define LQ_        900
#define LEN_V_     21760
#define NQ   (BS_*LQ_)        // 7200
#define MV   (BS_*LEN_V_)     // 174080

// single extern shared declaration for the whole TU
extern __shared__ char dsmem[];

// -------- scratch (device globals; no allocations allowed) --------
__device__ __half g_v  [(size_t)MV*EMBED];          // projected value, fp16, 89 MB
__device__ float  g_qoff[(size_t)NQ*384];           // [off(256) | attn(128)] per row
__device__ float4 g_samp[(size_t)NQ*NUM_HEADS*16];  // (locx, locy, weight, _)
__device__ float  g_mid[(size_t)NQ*EMBED];
__device__ float  g_qbias[384];

// packed weights
__device__ __half        g_wvh[256*256];             // value weights, fp16 [n][k]
__device__ __nv_bfloat16 g_qh [384*256], g_ql [384*256];
__device__ __nv_bfloat16 g_ouh[256*256], g_oul[256*256];

// ======================= common helpers =======================
__device__ __forceinline__ void split2(float a, float b, uint32_t& hi, uint32_t& lo) {
    __nv_bfloat162 h = __floats2bfloat162_rn(a, b);
    float ra = a - __bfloat162float(h.x);
    float rb = b - __bfloat162float(h.y);
    __nv_bfloat162 l = __floats2bfloat162_rn(ra, rb);
    hi = *reinterpret_cast<uint32_t*>(&h);
    lo = *reinterpret_cast<uint32_t*>(&l);
}

__device__ __forceinline__ void cp16(uint32_t dst, const void* src) {
    asm volatile("cp.async.ca.shared.global [%0], [%1], 16;" :: "r"(dst), "l"(src));
}

__device__ __forceinline__ void ldsm_x4(uint32_t& r0, uint32_t& r1, uint32_t& r2,
                                        uint32_t& r3, uint32_t addr) {
    asm volatile("ldmatrix.sync.aligned.m8n8.x4.shared.b16 {%0,%1,%2,%3}, [%4];"
                 : "=r"(r0), "=r"(r1), "=r"(r2), "=r"(r3) : "r"(addr));
}

__device__ __forceinline__ void mma_bf16(float* c, const uint32_t* a, const uint32_t* b) {
    asm volatile(
        "mma.sync.aligned.m16n8k16.row.col.f32.bf16.bf16.f32 "
        "{%0,%1,%2,%3}, {%4,%5,%6,%7}, {%8,%9}, {%0,%1,%2,%3};\n"
        : "+f"(c[0]), "+f"(c[1]), "+f"(c[2]), "+f"(c[3])
        : "r"(a[0]), "r"(a[1]), "r"(a[2]), "r"(a[3]), "r"(b[0]), "r"(b[1]));
}

__device__ __forceinline__ void mma_fp16(float* c, const uint32_t* a, const uint32_t* b) {
    asm volatile(
        "mma.sync.aligned.m16n8k16.row.col.f32.f16.f16.f32 "
        "{%0,%1,%2,%3}, {%4,%5,%6,%7}, {%8,%9}, {%0,%1,%2,%3};\n"
        : "+f"(c[0]), "+f"(c[1]), "+f"(c[2]), "+f"(c[3])
        : "r"(a[0]), "r"(a[1]), "r"(a[2]), "r"(a[3]), "r"(b[0]), "r"(b[1]));
}

#define LDW 20   // 32-bit words per smem row (16 data + 4 pad), conflict-free ldmatrix

// =============== v-projection GEMM: BM=128, BN=256, plain fp16 (1 MMA term) ====
// C(174080x256 fp16) = A(fp32->fp16) * B(fp16) + bias, double-buffered.
#define V_AS 2560                 // words: A plane (128 rows x 20)
#define V_BS 5120                 // words: B plane (256 rows x 20)
#define V_STAGE (V_AS + V_BS)     // 7680 words
#define V_SMEM (2 * V_STAGE * 4)  // 61440 B

__global__ __launch_bounds__(256, 1) void fp16_gemm_v(
    const float* __restrict__ A, const __half* __restrict__ Bh,
    const float* __restrict__ bias, __half* __restrict__ C)
{
    uint32_t* smem = reinterpret_cast<uint32_t*>(dsmem);
    const uint32_t smem_u32 = (uint32_t)__cvta_generic_to_shared(smem);

    const int tid   = threadIdx.x;
    const int lane  = tid & 31;
    const int warp  = tid >> 5;
    const int warpM = warp >> 2;      // 0..1 (64 rows each)
    const int warpN = warp & 3;       // 0..3 (64 cols each)
    const int brow  = blockIdx.x * 128;
    const int g     = lane >> 2;
    const int tg    = lane & 3;

    const uint32_t a_off = (((lane & 15) * LDW) + ((lane >> 4) << 2)) * 4;
    const uint32_t b_off = ((((lane & 7) + ((lane >> 4) << 3)) * LDW) + (((lane >> 3) & 1) << 2)) * 4;

    float acc[4][8][4];
    #pragma unroll
    for (int i = 0; i < 4; i++)
        #pragma unroll
        for (int j = 0; j < 8; j++)
            #pragma unroll
            for (int r = 0; r < 4; r++) acc[i][j][r] = 0.f;

    float4 pa[4];
    auto load_A = [&](int kt) {
        #pragma unroll
        for (int i = 0; i < 4; i++) {
            int idx  = tid + i * 256;
            int arow = idx >> 3;          // 0..127
            int ac4  = idx & 7;
            pa[i] = *reinterpret_cast<const float4*>(&A[(long)(brow + arow) * 256 + kt + ac4 * 4]);
        }
    };

    auto store_A = [&](int stage) {
        uint32_t* As = smem + stage * V_STAGE;
        #pragma unroll
        for (int i = 0; i < 4; i++) {
            int idx  = tid + i * 256;
            int arow = idx >> 3;
            int ac4  = idx & 7;
            __half2 h0 = __floats2half2_rn(pa[i].x, pa[i].y);
            __half2 h1 = __floats2half2_rn(pa[i].z, pa[i].w);
            *reinterpret_cast<uint2*>(&As[arow * LDW + ac4 * 2]) =
                make_uint2(*reinterpret_cast<uint32_t*>(&h0), *reinterpret_cast<uint32_t*>(&h1));
        }
    };

    auto issue_B = [&](int stage, int kt) {
        uint32_t base = smem_u32 + (uint32_t)((stage * V_STAGE + V_AS) * 4);
        #pragma unroll
        for (int i = 0; i < 4; i++) {
            int idx = tid + i * 256;       // 0..1023
            int row = idx >> 2, c = idx & 3;
            cp16(base + (uint32_t)((row * LDW + c * 4) * 4),
                 Bh + ((long)row * 256 + kt + c * 8));
        }
        asm volatile("cp.async.commit_group;" ::: "memory");
    };

    issue_B(0, 0);
    load_A(0);
    store_A(0);
    asm volatile("cp.async.wait_group 0;" ::: "memory");
    __syncthreads();

    for (int kt = 0; kt < 256; kt += 32) {
        const int s = (kt >> 5) & 1;
        const bool has_next = (kt + 32 < 256);
        if (has_next) {
            issue_B(s ^ 1, kt + 32);
            load_A(kt + 32);
        }

        const uint32_t s_as = smem_u32 + (uint32_t)(s * V_STAGE * 4);
        const uint32_t s_bs = s_as + V_AS * 4;

        #pragma unroll
        for (int ks = 0; ks < 2; ks++) {
            const uint32_t kb = ks * 8 * 4;
            uint32_t ah[4][4], bh[8][2];
            #pragma unroll
            for (int mt = 0; mt < 4; mt++) {
                uint32_t base = s_as + a_off + (uint32_t)((warpM * 64 + mt * 16) * LDW * 4) + kb;
                ldsm_x4(ah[mt][0], ah[mt][1], ah[mt][2], ah[mt][3], base);
            }
            #pragma unroll
            for (int p = 0; p < 4; p++) {
                uint32_t base = s_bs + b_off + (uint32_t)((warpN * 64 + p * 16) * LDW * 4) + kb;
                ldsm_x4(bh[2*p][0], bh[2*p][1], bh[2*p+1][0], bh[2*p+1][1], base);
            }
            #pragma unroll
            for (int mt = 0; mt < 4; mt++)
                #pragma unroll
                for (int nt = 0; nt < 8; nt++)
                    mma_fp16(acc[mt][nt], ah[mt], bh[nt]);
        }

        if (has_next) {
            store_A(s ^ 1);
            asm volatile("cp.async.wait_group 0;" ::: "memory");
        }
        __syncthreads();
    }

    // epilogue: + bias, fp16 store (M divides exactly; no guards)
    #pragma unroll
    for (int mt = 0; mt < 4; mt++) {
        long row0 = brow + warpM * 64 + mt * 16 + g;
        #pragma unroll
        for (int nt = 0; nt < 8; nt++) {
            int col = warpN * 64 + nt * 8 + tg * 2;
            float b0 = bias[col], b1 = bias[col + 1];
            *reinterpret_cast<__half2*>(&C[row0 * 256 + col]) =
                __floats2half2_rn(acc[mt][nt][0] + b0, acc[mt][nt][1] + b1);
            *reinterpret_cast<__half2*>(&C[(row0 + 8) * 256 + col]) =
                __floats2half2_rn(acc[mt][nt][2] + b0, acc[mt][nt][3] + b1);
        }
    }
}

// ============ bf16 split-2 mma.sync GEMM (small GEMMs, BN=128) =============
#define BM 128
#define BN 128
#define BK 32
#define TILE_WORDS (BM * LDW)
#define STAGE_WORDS (4 * TILE_WORDS)
#define GEMM_SMEM (2 * STAGE_WORDS * 4)

__global__ __launch_bounds__(256) void bf16x3_gemm_bias(
    const float* __restrict__ A,
    const __nv_bfloat16* __restrict__ Bh, const __nv_bfloat16* __restrict__ Bl,
    const float* __restrict__ bias, float* __restrict__ C,
    int M, int N, int K)
{
    uint32_t* smem = reinterpret_cast<uint32_t*>(dsmem);
    const uint32_t smem_u32 = (uint32_t)__cvta_generic_to_shared(smem);

    const int tid   = threadIdx.x;
    const int lane  = tid & 31;
    const int warp  = tid >> 5;
    const int warpM = warp >> 2;
    const int warpN = warp & 3;
    const int brow  = blockIdx.y * BM;
    const int bcol  = blockIdx.x * BN;
    const int g     = lane >> 2;
    const int tg    = lane & 3;

    const uint32_t lohalf = TILE_WORDS * 4;
    const uint32_t a_off = (((lane & 15) * LDW) + ((lane >> 4) << 2)) * 4;
    const uint32_t b_off = ((((lane & 7) + ((lane >> 4) << 3)) * LDW) + (((lane >> 3) & 1) << 2)) * 4;

    float acc[4][4][4];
    #pragma unroll
    for (int i = 0; i < 4; i++)
        #pragma unroll
        for (int j = 0; j < 4; j++)
            #pragma unroll
            for (int r = 0; r < 4; r++) acc[i][j][r] = 0.f;

    float4 pa[4];
    auto load_A = [&](int kt) {
        #pragma unroll
        for (int i = 0; i < 4; i++) {
            int idx  = tid + i * 256;
            int arow = idx >> 3;
            int ac4  = idx & 7;
            int grow = brow + arow;
            pa[i] = make_float4(0.f, 0.f, 0.f, 0.f);
            if (grow < M)
                pa[i] = *reinterpret_cast<const float4*>(&A[(long)grow * K + kt + ac4 * 4]);
        }
    };

    auto store_A = [&](int stage) {
        uint32_t* As0 = smem + stage * STAGE_WORDS;
        uint32_t* As1 = As0 + TILE_WORDS;
        #pragma unroll
        for (int i = 0; i < 4; i++) {
            int idx  = tid + i * 256;
            int arow = idx >> 3;
            int ac4  = idx & 7;
            uint32_t h0, l0, h1, l1;
            split2(pa[i].x, pa[i].y, h0, l0);
            split2(pa[i].z, pa[i].w, h1, l1);
            *reinterpret_cast<uint2*>(&As0[arow * LDW + ac4 * 2]) = make_uint2(h0, h1);
            *reinterpret_cast<uint2*>(&As1[arow * LDW + ac4 * 2]) = make_uint2(l0, l1);
        }
    };

    auto issue_B = [&](int stage, int kt) {
        uint32_t base = smem_u32 + (uint32_t)((stage * STAGE_WORDS + 2 * TILE_WORDS) * 4);
        #pragma unroll
        for (int i = 0; i < 2; i++) {
            int idx = tid + i * 256;
            int row = idx >> 2, c = idx & 3;
            cp16(base + (uint32_t)((row * LDW + c * 4) * 4),
                 Bh + ((long)(bcol + row) * K + kt + c * 8));
        }
        #pragma unroll
        for (int i = 0; i < 2; i++) {
            int idx = tid + i * 256;
            int row = idx >> 2, c = idx & 3;
            cp16(base + lohalf + (uint32_t)((row * LDW + c * 4) * 4),
                 Bl + ((long)(bcol + row) * K + kt + c * 8));
        }
        asm volatile("cp.async.commit_group;" ::: "memory");
    };

    issue_B(0, 0);
    load_A(0);
    store_A(0);
    asm volatile("cp.async.wait_group 0;" ::: "memory");
    __syncthreads();

    for (int kt = 0; kt < K; kt += BK) {
        const int s = (kt >> 5) & 1;
        const bool has_next = (kt + BK < K);
        if (has_next) {
            issue_B(s ^ 1, kt + BK);
            load_A(kt + BK);
        }

        const uint32_t s_as0 = smem_u32 + (uint32_t)(s * STAGE_WORDS * 4);
        const uint32_t s_bs0 = s_as0 + 2 * lohalf;

        #pragma unroll
        for (int ks = 0; ks < 2; ks++) {
            const uint32_t kb = ks * 8 * 4;
            uint32_t ah[4][4], al[4][4], bh[4][2], bl[4][2];
            #pragma unroll
            for (int mt = 0; mt < 4; mt++) {
                uint32_t base = s_as0 + a_off + (uint32_t)((warpM * 64 + mt * 16) * LDW * 4) + kb;
                ldsm_x4(ah[mt][0], ah[mt][1], ah[mt][2], ah[mt][3], base);
                ldsm_x4(al[mt][0], al[mt][1], al[mt][2], al[mt][3], base + lohalf);
            }
            #pragma unroll
            for (int p = 0; p < 2; p++) {
                uint32_t base = s_bs0 + b_off + (uint32_t)((warpN * 32 + p * 16) * LDW * 4) + kb;
                ldsm_x4(bh[2*p][0], bh[2*p][1], bh[2*p+1][0], bh[2*p+1][1], base);
                ldsm_x4(bl[2*p][0], bl[2*p][1], bl[2*p+1][0], bl[2*p+1][1], base + lohalf);
            }
            #pragma unroll
            for (int mt = 0; mt < 4; mt++)
                #pragma unroll
                for (int nt = 0; nt < 4; nt++) {
                    mma_bf16(acc[mt][nt], ah[mt], bh[nt]);
                    mma_bf16(acc[mt][nt], ah[mt], bl[nt]);
                    mma_bf16(acc[mt][nt], al[mt], bh[nt]);
                }
        }

        if (has_next) {
            store_A(s ^ 1);
            asm volatile("cp.async.wait_group 0;" ::: "memory");
        }
        __syncthreads();
    }

    #pragma unroll
    for (int mt = 0; mt < 4; mt++) {
        int row0 = brow + warpM * 64 + mt * 16 + g;
        #pragma unroll
        for (int nt = 0; nt < 4; nt++) {
            int col = bcol + warpN * 32 + nt * 8 + tg * 2;
            float b0 = bias[col], b1 = bias[col + 1];
            if (row0 < M) {
                float2 o = make_float2(acc[mt][nt][0] + b0, acc[mt][nt][1] + b1);
                *reinterpret_cast<float2*>(&C[(long)row0 * N + col]) = o;
            }
            if (row0 + 8 < M) {
                float2 o = make_float2(acc[mt][nt][2] + b0, acc[mt][nt][3] + b1);
                *reinterpret_cast<float2*>(&C[(long)(row0 + 8) * N + col]) = o;
            }
        }
    }
}

// ====== merged weight pack ====
// value -> fp16 [n][k] single plane; q(off|attn) & out -> bf16 hi/lo planes
__global__ void pack_all(const float* __restrict__ Wv, const float* __restrict__ Wo,
                         const float* __restrict__ Wa, const float* __restrict__ Wu,
                         const float* __restrict__ bo, const float* __restrict__ ba,
                         __half* __restrict__ vh,
                         __nv_bfloat16* __restrict__ qh, __nv_bfloat16* __restrict__ ql,
                         __nv_bfloat16* __restrict__ uh, __nv_bfloat16* __restrict__ ul,
                         float* __restrict__ qbias)
{
    int idx = blockIdx.x * blockDim.x + threadIdx.x;
    if (idx < 384)
        qbias[idx] = (idx < 256) ? bo[idx] : ba[idx - 256];

    if (idx < 65536) {
        int n = idx >> 8, k = idx & 255;
        vh[idx] = __float2half(Wv[(long)k * 256 + n]);
        return;
    }
    float f; __nv_bfloat16 *hi, *lo; int local;
    if (idx < 163840) {
        local = idx - 65536;                 // [n<384][k]
        int n = local >> 8, k = local & 255;
        f = (n < 256) ? Wo[(long)k * 256 + n] : Wa[(long)k * 128 + (n - 256)];
        hi = qh; lo = ql;
    } else if (idx < 229376) {
        local = idx - 163840;
        int n = local >> 8, k = local & 255;
        f = Wu[(long)k * 256 + n]; hi = uh; lo = ul;
    } else return;
    __nv_bfloat16 h = __float2bfloat16(f);
    __nv_bfloat16 l = __float2bfloat16(f - __bfloat162float(h));
    hi[local] = h;
    lo[local] = l;
}

// =================== softmax + sampling-loc precompute (4 threads per (bq,h)) ==
__global__ void softmax_loc4(const float* __restrict__ refp)
{
    int t  = blockIdx.x * blockDim.x + threadIdx.x;
    int id = t >> 2;
    int l  = t & 3;
    if (id >= NQ * NUM_HEADS) return;
    int bq = id >> 3;
    int h  = id & 7;

    const float* qrow = &g_qoff[(long)bq * 384];
    float4 a = *reinterpret_cast<const float4*>(&qrow[256 + h * 16 + l * 4]);
    float m = fmaxf(fmaxf(a.x, a.y), fmaxf(a.z, a.w));
    m = fmaxf(m, __shfl_xor_sync(0xffffffffu, m, 1));
    m = fmaxf(m, __shfl_xor_sync(0xffffffffu, m, 2));
    float e0 = expf(a.x - m), e1 = expf(a.y - m), e2 = expf(a.z - m), e3 = expf(a.w - m);
    float s = e0 + e1 + e2 + e3;
    s += __shfl_xor_sync(0xffffffffu, s, 1);
    s += __shfl_xor_sync(0xffffffffu, s, 2);
    float inv = 1.f / s;

    const float invWH[4] = {1.f/128.f, 1.f/64.f, 1.f/32.f, 1.f/16.f};
    float iw = invWH[l];
    float2 ref = *reinterpret_cast<const float2*>(&refp[((long)bq * 4 + l) * 2]);
    float4 o0 = *reinterpret_cast<const float4*>(&qrow[h * 32 + l * 8]);
    float4 o1 = *reinterpret_cast<const float4*>(&qrow[h * 32 + l * 8 + 4]);

    float4* out = &g_samp[(long)id * 16 + l * 4];
    out[0] = make_float4(ref.x + o0.x * iw, ref.y + o0.y * iw, e0 * inv, 0.f);
    out[1] = make_float4(ref.x + o0.z * iw, ref.y + o0.w * iw, e1 * inv, 0.f);
    out[2] = make_float4(ref.x + o1.x * iw, ref.y + o1.y * iw, e2 * inv, 0.f);
    out[3] = make_float4(ref.x + o1.z * iw, ref.y + o1.w * iw, e3 * inv, 0.f);
}

// =================== bilinear gather + weighted accumulate (fp16 v) ==========
__global__ __launch_bounds__(256) void msda_sample()
{
    int warp = (blockIdx.x * blockDim.x + threadIdx.x) >> 5;
    int lane = threadIdx.x & 31;
    if (warp >= NQ * NUM_HEADS) return;
    int h  = warp & 7;
    int bq = warp >> 3;
    int b  = bq / LQ_;

    const float4* samp = &g_samp[(long)warp * 16];
    const __half* vb = g_v + (long)b * LEN_V_ * EMBED + h * HEAD_DIM + lane;

    const int   Wl[4]     = {128, 64, 32, 16};
    const int   starts[4] = {0, 16384, 20480, 21504};

    float acc = 0.f;
    #pragma unroll
    for (int l = 0; l < 4; l++) {
        const int W = Wl[l];
        const int H = W;
        const __half* vl = vb + (long)starts[l] * EMBED;
        #pragma unroll
        for (int p = 0; p < 4; p++) {
            float4 sp = samp[l * 4 + p];
            float px = sp.x * (float)W - 0.5f;
            float py = sp.y * (float)H - 0.5f;
            float x0f = floorf(px), y0f = floorf(py);
            float dx = px - x0f, dy = py - y0f;
            int x0 = (int)x0f, y0 = (int)y0f;
            float w00 = (1.f - dx) * (1.f - dy) * sp.z;
            float w10 = dx * (1.f - dy) * sp.z;
            float w01 = (1.f - dx) * dy * sp.z;
            float w11 = dx * dy * sp.z;
            bool xv0 = (x0 >= 0) && (x0 < W);
            bool xv1 = (x0 >= -1) && (x0 + 1 < W);
            bool yv0 = (y0 >= 0) && (y0 < H);
            bool yv1 = (y0 >= -1) && (y0 + 1 < H);
            if (xv0 && yv0) acc += w00 * __half2float(vl[((long)y0 * W + x0) * EMBED]);
            if (xv1 && yv0) acc += w10 * __half2float(vl[((long)y0 * W + x0 + 1) * EMBED]);
            if (xv0 && yv1) acc += w01 * __half2float(vl[((long)(y0 + 1) * W + x0) * EMBED]);
            if (xv1 && yv1) acc += w11 * __half2float(vl[((long)(y0 + 1) * W + x0 + 1) * EMBED]);
        }
    }
    g_mid[(long)bq * EMBED + h * HEAD_DIM + lane] = acc;
}

// =================== launch ===================
extern "C" void kernel_launch(void* const* d_in, const int* in_sizes, int n_in,
                              void* d_out, int out_size)
{
    const float* query   = (const float*)d_in[0];
    const float* refp    = (const float*)d_in[1];
    const float* value   = (const float*)d_in[2];
    const float* w_value = (const float*)d_in[3];
    const float* b_value = (const float*)d_in[4];
    const float* w_off   = (const float*)d_in[5];
    const float* b_off   = (const float*)d_in[6];
    const float* w_attn  = (const float*)d_in[7];
    const float* b_attn  = (const float*)d_in[8];
    const float* w_out   = (const float*)d_in[9];
    const float* b_out   = (const float*)d_in[10];
    float* out = (float*)d_out;

    __half *pv, *wvh;
    float *pqoff, *pmid, *pqbias;
    cudaGetSymbolAddress((void**)&pv,    g_v);
    cudaGetSymbolAddress((void**)&pqoff, g_qoff);
    cudaGetSymbolAddress((void**)&pmid,  g_mid);
    cudaGetSymbolAddress((void**)&pqbias,g_qbias);
    cudaGetSymbolAddress((void**)&wvh,   g_wvh);

    __nv_bfloat16 *qh, *ql, *ouh, *oul;
    cudaGetSymbolAddress((void**)&qh,  g_qh);   cudaGetSymbolAddress((void**)&ql,  g_ql);
    cudaGetSymbolAddress((void**)&ouh, g_ouh);  cudaGetSymbolAddress((void**)&oul, g_oul);

    static int smem_set = 0;
    if (!smem_set) {
        cudaFuncSetAttribute(bf16x3_gemm_bias,
                             cudaFuncAttributeMaxDynamicSharedMemorySize, GEMM_SMEM);
        cudaFuncSetAttribute(fp16_gemm_v,
                             cudaFuncAttributeMaxDynamicSharedMemorySize, V_SMEM);
        smem_set = 1;
    }

    // 1) pack all weights + combined bias (one launch)
    pack_all<<<(229376 + 255) / 256, 256>>>(w_value, w_off, w_attn, w_out, b_off, b_attn,
                                            wvh, qh, ql, ouh, oul, pqbias);

    // 2) [off|aw] = query @ [w_off|w_attn] + bias   (7200 x 384 x 256)
    {
        dim3 grid(384 / BN, (NQ + BM - 1) / BM);
        bf16x3_gemm_bias<<<grid, 256, GEMM_SMEM>>>(query, qh, ql, pqbias, pqoff, NQ, 384, EMBED);
    }
    // 3) softmax + sampling locations
    {
        int total = NQ * NUM_HEADS * 4;
        softmax_loc4<<<(total + 255) / 256, 256>>>(refp);
    }
    // 4) v = value @ w_value + b_value  (174080 x 256 x 256, plain fp16) <- profiled slot
    {
        fp16_gemm_v<<<MV / 128, 256, V_SMEM>>>(value, wvh, b_value, pv);
    }
    // 5) bilinear sample + weighted sum  (one warp per (b,q,h))
    {
        int warps = NQ * NUM_HEADS;
        msda_sample<<<(warps * 32 + 255) / 256, 256>>>();
    }
    // 6) out = mid @ w_out + b_out -> d_out
    {
        dim3 grid(EMBED / BN, (NQ + BM - 1) / BM);
        bf16x3_gemm_bias<<<grid, 256, GEMM_SMEM>>>(pmid, ouh, oul, b_out, out, NQ, EMBED, EMBED);
    }
}

// round 11
// speedup vs baseline: 3.8157x; 1.0422x over previous
#include <cuda_runtime.h>
#include <cuda_bf16.h>
#include <cuda_fp16.h>
#include <math.h>
#include <stdint.h>

#define NUM_HEADS  8
#define NUM_LEVELS 4
#define NUM_POINTS 4
#define HEAD_DIM   32
#define EMBED      256
#define BS_        8
#define LQ_        900
#define LEN_V_     21760
#define NQ   (BS_*LQ_)        // 7200
#define MV   (BS_*LEN_V_)     // 174080

// single extern shared declaration for the whole TU
extern __shared__ char dsmem[];

// -------- scratch (device globals; no allocations allowed) --------
__device__ __half g_v  [(size_t)MV*EMBED];          // projected value, fp16, 89 MB
__device__ float  g_qoff[(size_t)NQ*384];           // [off(256) | attn(128)] per row
__device__ float  g_mid[(size_t)NQ*EMBED];
__device__ float  g_qbias[384];

// packed weights
__device__ __half        g_wvh[256*256];             // value weights, fp16 [n][k]
__device__ __nv_bfloat16 g_qh [384*256], g_ql [384*256];
__device__ __nv_bfloat16 g_ouh[256*256], g_oul[256*256];

// ======================= common helpers =======================
__device__ __forceinline__ void split2(float a, float b, uint32_t& hi, uint32_t& lo) {
    __nv_bfloat162 h = __floats2bfloat162_rn(a, b);
    float ra = a - __bfloat162float(h.x);
    float rb = b - __bfloat162float(h.y);
    __nv_bfloat162 l = __floats2bfloat162_rn(ra, rb);
    hi = *reinterpret_cast<uint32_t*>(&h);
    lo = *reinterpret_cast<uint32_t*>(&l);
}

__device__ __forceinline__ void cp16(uint32_t dst, const void* src) {
    asm volatile("cp.async.ca.shared.global [%0], [%1], 16;" :: "r"(dst), "l"(src));
}

__device__ __forceinline__ void ldsm_x4(uint32_t& r0, uint32_t& r1, uint32_t& r2,
                                        uint32_t& r3, uint32_t addr) {
    asm volatile("ldmatrix.sync.aligned.m8n8.x4.shared.b16 {%0,%1,%2,%3}, [%4];"
                 : "=r"(r0), "=r"(r1), "=r"(r2), "=r"(r3) : "r"(addr));
}

__device__ __forceinline__ void mma_bf16(float* c, const uint32_t* a, const uint32_t* b) {
    asm volatile(
        "mma.sync.aligned.m16n8k16.row.col.f32.bf16.bf16.f32 "
        "{%0,%1,%2,%3}, {%4,%5,%6,%7}, {%8,%9}, {%0,%1,%2,%3};\n"
        : "+f"(c[0]), "+f"(c[1]), "+f"(c[2]), "+f"(c[3])
        : "r"(a[0]), "r"(a[1]), "r"(a[2]), "r"(a[3]), "r"(b[0]), "r"(b[1]));
}

__device__ __forceinline__ void mma_fp16(float* c, const uint32_t* a, const uint32_t* b) {
    asm volatile(
        "mma.sync.aligned.m16n8k16.row.col.f32.f16.f16.f32 "
        "{%0,%1,%2,%3}, {%4,%5,%6,%7}, {%8,%9}, {%0,%1,%2,%3};\n"
        : "+f"(c[0]), "+f"(c[1]), "+f"(c[2]), "+f"(c[3])
        : "r"(a[0]), "r"(a[1]), "r"(a[2]), "r"(a[3]), "r"(b[0]), "r"(b[1]));
}

#define LDW 20   // 32-bit words per smem row (16 data + 4 pad), conflict-free ldmatrix

// ====== v-projection GEMM: BM=128, BN=256, fp16, 512 threads (16 warps) =======
// warp tile 32x64 -> acc 64 regs/thread -> ~120 regs -> 16 warps/SM (2x hiding)
#define V_AS 2560                 // words: A plane (128 rows x 20)
#define V_BS 5120                 // words: B plane (256 rows x 20)
#define V_STAGE (V_AS + V_BS)     // 7680 words
#define V_SMEM (2 * V_STAGE * 4)  // 61440 B

__global__ __launch_bounds__(512, 1) void fp16_gemm_v(
    const float* __restrict__ A, const __half* __restrict__ Bh,
    const float* __restrict__ bias, __half* __restrict__ C)
{
    uint32_t* smem = reinterpret_cast<uint32_t*>(dsmem);
    const uint32_t smem_u32 = (uint32_t)__cvta_generic_to_shared(smem);

    const int tid   = threadIdx.x;
    const int lane  = tid & 31;
    const int warp  = tid >> 5;       // 0..15
    const int warpM = warp >> 2;      // 0..3 (32 rows each)
    const int warpN = warp & 3;       // 0..3 (64 cols each)
    const int brow  = blockIdx.x * 128;
    const int g     = lane >> 2;
    const int tg    = lane & 3;

    const uint32_t a_off = (((lane & 15) * LDW) + ((lane >> 4) << 2)) * 4;
    const uint32_t b_off = ((((lane & 7) + ((lane >> 4) << 3)) * LDW) + (((lane >> 3) & 1) << 2)) * 4;

    float acc[2][8][4];
    #pragma unroll
    for (int i = 0; i < 2; i++)
        #pragma unroll
        for (int j = 0; j < 8; j++)
            #pragma unroll
            for (int r = 0; r < 4; r++) acc[i][j][r] = 0.f;

    float4 pa[2];
    auto load_A = [&](int kt) {
        #pragma unroll
        for (int i = 0; i < 2; i++) {
            int idx  = tid + i * 512;     // 0..1023
            int arow = idx >> 3;          // 0..127
            int ac4  = idx & 7;
            pa[i] = *reinterpret_cast<const float4*>(&A[(long)(brow + arow) * 256 + kt + ac4 * 4]);
        }
    };

    auto store_A = [&](int stage) {
        uint32_t* As = smem + stage * V_STAGE;
        #pragma unroll
        for (int i = 0; i < 2; i++) {
            int idx  = tid + i * 512;
            int arow = idx >> 3;
            int ac4  = idx & 7;
            __half2 h0 = __floats2half2_rn(pa[i].x, pa[i].y);
            __half2 h1 = __floats2half2_rn(pa[i].z, pa[i].w);
            *reinterpret_cast<uint2*>(&As[arow * LDW + ac4 * 2]) =
                make_uint2(*reinterpret_cast<uint32_t*>(&h0), *reinterpret_cast<uint32_t*>(&h1));
        }
    };

    auto issue_B = [&](int stage, int kt) {
        uint32_t base = smem_u32 + (uint32_t)((stage * V_STAGE + V_AS) * 4);
        #pragma unroll
        for (int i = 0; i < 2; i++) {
            int idx = tid + i * 512;       // 0..1023
            int row = idx >> 2, c = idx & 3;
            cp16(base + (uint32_t)((row * LDW + c * 4) * 4),
                 Bh + ((long)row * 256 + kt + c * 8));
        }
        asm volatile("cp.async.commit_group;" ::: "memory");
    };

    issue_B(0, 0);
    load_A(0);
    store_A(0);
    asm volatile("cp.async.wait_group 0;" ::: "memory");
    __syncthreads();

    for (int kt = 0; kt < 256; kt += 32) {
        const int s = (kt >> 5) & 1;
        const bool has_next = (kt + 32 < 256);
        if (has_next) {
            issue_B(s ^ 1, kt + 32);
            load_A(kt + 32);
        }

        const uint32_t s_as = smem_u32 + (uint32_t)(s * V_STAGE * 4);
        const uint32_t s_bs = s_as + V_AS * 4;

        #pragma unroll
        for (int ks = 0; ks < 2; ks++) {
            const uint32_t kb = ks * 8 * 4;
            uint32_t ah[2][4], bh[8][2];
            #pragma unroll
            for (int mt = 0; mt < 2; mt++) {
                uint32_t base = s_as + a_off + (uint32_t)((warpM * 32 + mt * 16) * LDW * 4) + kb;
                ldsm_x4(ah[mt][0], ah[mt][1], ah[mt][2], ah[mt][3], base);
            }
            #pragma unroll
            for (int p = 0; p < 4; p++) {
                uint32_t base = s_bs + b_off + (uint32_t)((warpN * 64 + p * 16) * LDW * 4) + kb;
                ldsm_x4(bh[2*p][0], bh[2*p][1], bh[2*p+1][0], bh[2*p+1][1], base);
            }
            #pragma unroll
            for (int mt = 0; mt < 2; mt++)
                #pragma unroll
                for (int nt = 0; nt < 8; nt++)
                    mma_fp16(acc[mt][nt], ah[mt], bh[nt]);
        }

        if (has_next) {
            store_A(s ^ 1);
            asm volatile("cp.async.wait_group 0;" ::: "memory");
        }
        __syncthreads();
    }

    // epilogue: + bias, fp16 store (dims divide exactly; no guards)
    #pragma unroll
    for (int mt = 0; mt < 2; mt++) {
        long row0 = brow + warpM * 32 + mt * 16 + g;
        #pragma unroll
        for (int nt = 0; nt < 8; nt++) {
            int col = warpN * 64 + nt * 8 + tg * 2;
            float b0 = bias[col], b1 = bias[col + 1];
            *reinterpret_cast<__half2*>(&C[row0 * 256 + col]) =
                __floats2half2_rn(acc[mt][nt][0] + b0, acc[mt][nt][1] + b1);
            *reinterpret_cast<__half2*>(&C[(row0 + 8) * 256 + col]) =
                __floats2half2_rn(acc[mt][nt][2] + b0, acc[mt][nt][3] + b1);
        }
    }
}

// ============ bf16 split-2 mma.sync GEMM (small GEMMs, BN=128) =============
#define BM 128
#define BN 128
#define BK 32
#define TILE_WORDS (BM * LDW)
#define STAGE_WORDS (4 * TILE_WORDS)
#define GEMM_SMEM (2 * STAGE_WORDS * 4)

__global__ __launch_bounds__(256) void bf16x3_gemm_bias(
    const float* __restrict__ A,
    const __nv_bfloat16* __restrict__ Bh, const __nv_bfloat16* __restrict__ Bl,
    const float* __restrict__ bias, float* __restrict__ C,
    int M, int N, int K)
{
    uint32_t* smem = reinterpret_cast<uint32_t*>(dsmem);
    const uint32_t smem_u32 = (uint32_t)__cvta_generic_to_shared(smem);

    const int tid   = threadIdx.x;
    const int lane  = tid & 31;
    const int warp  = tid >> 5;
    const int warpM = warp >> 2;
    const int warpN = warp & 3;
    const int brow  = blockIdx.y * BM;
    const int bcol  = blockIdx.x * BN;
    const int g     = lane >> 2;
    const int tg    = lane & 3;

    const uint32_t lohalf = TILE_WORDS * 4;
    const uint32_t a_off = (((lane & 15) * LDW) + ((lane >> 4) << 2)) * 4;
    const uint32_t b_off = ((((lane & 7) + ((lane >> 4) << 3)) * LDW) + (((lane >> 3) & 1) << 2)) * 4;

    float acc[4][4][4];
    #pragma unroll
    for (int i = 0; i < 4; i++)
        #pragma unroll
        for (int j = 0; j < 4; j++)
            #pragma unroll
            for (int r = 0; r < 4; r++) acc[i][j][r] = 0.f;

    float4 pa[4];
    auto load_A = [&](int kt) {
        #pragma unroll
        for (int i = 0; i < 4; i++) {
            int idx  = tid + i * 256;
            int arow = idx >> 3;
            int ac4  = idx & 7;
            int grow = brow + arow;
            pa[i] = make_float4(0.f, 0.f, 0.f, 0.f);
            if (grow < M)
                pa[i] = *reinterpret_cast<const float4*>(&A[(long)grow * K + kt + ac4 * 4]);
        }
    };

    auto store_A = [&](int stage) {
        uint32_t* As0 = smem + stage * STAGE_WORDS;
        uint32_t* As1 = As0 + TILE_WORDS;
        #pragma unroll
        for (int i = 0; i < 4; i++) {
            int idx  = tid + i * 256;
            int arow = idx >> 3;
            int ac4  = idx & 7;
            uint32_t h0, l0, h1, l1;
            split2(pa[i].x, pa[i].y, h0, l0);
            split2(pa[i].z, pa[i].w, h1, l1);
            *reinterpret_cast<uint2*>(&As0[arow * LDW + ac4 * 2]) = make_uint2(h0, h1);
            *reinterpret_cast<uint2*>(&As1[arow * LDW + ac4 * 2]) = make_uint2(l0, l1);
        }
    };

    auto issue_B = [&](int stage, int kt) {
        uint32_t base = smem_u32 + (uint32_t)((stage * STAGE_WORDS + 2 * TILE_WORDS) * 4);
        #pragma unroll
        for (int i = 0; i < 2; i++) {
            int idx = tid + i * 256;
            int row = idx >> 2, c = idx & 3;
            cp16(base + (uint32_t)((row * LDW + c * 4) * 4),
                 Bh + ((long)(bcol + row) * K + kt + c * 8));
        }
        #pragma unroll
        for (int i = 0; i < 2; i++) {
            int idx = tid + i * 256;
            int row = idx >> 2, c = idx & 3;
            cp16(base + lohalf + (uint32_t)((row * LDW + c * 4) * 4),
                 Bl + ((long)(bcol + row) * K + kt + c * 8));
        }
        asm volatile("cp.async.commit_group;" ::: "memory");
    };

    issue_B(0, 0);
    load_A(0);
    store_A(0);
    asm volatile("cp.async.wait_group 0;" ::: "memory");
    __syncthreads();

    for (int kt = 0; kt < K; kt += BK) {
        const int s = (kt >> 5) & 1;
        const bool has_next = (kt + BK < K);
        if (has_next) {
            issue_B(s ^ 1, kt + BK);
            load_A(kt + BK);
        }

        const uint32_t s_as0 = smem_u32 + (uint32_t)(s * STAGE_WORDS * 4);
        const uint32_t s_bs0 = s_as0 + 2 * lohalf;

        #pragma unroll
        for (int ks = 0; ks < 2; ks++) {
            const uint32_t kb = ks * 8 * 4;
            uint32_t ah[4][4], al[4][4], bh[4][2], bl[4][2];
            #pragma unroll
            for (int mt = 0; mt < 4; mt++) {
                uint32_t base = s_as0 + a_off + (uint32_t)((warpM * 64 + mt * 16) * LDW * 4) + kb;
                ldsm_x4(ah[mt][0], ah[mt][1], ah[mt][2], ah[mt][3], base);
                ldsm_x4(al[mt][0], al[mt][1], al[mt][2], al[mt][3], base + lohalf);
            }
            #pragma unroll
            for (int p = 0; p < 2; p++) {
                uint32_t base = s_bs0 + b_off + (uint32_t)((warpN * 32 + p * 16) * LDW * 4) + kb;
                ldsm_x4(bh[2*p][0], bh[2*p][1], bh[2*p+1][0], bh[2*p+1][1], base);
                ldsm_x4(bl[2*p][0], bl[2*p][1], bl[2*p+1][0], bl[2*p+1][1], base + lohalf);
            }
            #pragma unroll
            for (int mt = 0; mt < 4; mt++)
                #pragma unroll
                for (int nt = 0; nt < 4; nt++) {
                    mma_bf16(acc[mt][nt], ah[mt], bh[nt]);
                    mma_bf16(acc[mt][nt], ah[mt], bl[nt]);
                    mma_bf16(acc[mt][nt], al[mt], bh[nt]);
                }
        }

        if (has_next) {
            store_A(s ^ 1);
            asm volatile("cp.async.wait_group 0;" ::: "memory");
        }
        __syncthreads();
    }

    #pragma unroll
    for (int mt = 0; mt < 4; mt++) {
        int row0 = brow + warpM * 64 + mt * 16 + g;
        #pragma unroll
        for (int nt = 0; nt < 4; nt++) {
            int col = bcol + warpN * 32 + nt * 8 + tg * 2;
            float b0 = bias[col], b1 = bias[col + 1];
            if (row0 < M) {
                float2 o = make_float2(acc[mt][nt][0] + b0, acc[mt][nt][1] + b1);
                *reinterpret_cast<float2*>(&C[(long)row0 * N + col]) = o;
            }
            if (row0 + 8 < M) {
                float2 o = make_float2(acc[mt][nt][2] + b0, acc[mt][nt][3] + b1);
                *reinterpret_cast<float2*>(&C[(long)(row0 + 8) * N + col]) = o;
            }
        }
    }
}

// ====== merged weight pack ====
// value -> fp16 [n][k] single plane; q(off|attn) & out -> bf16 hi/lo planes
__global__ void pack_all(const float* __restrict__ Wv, const float* __restrict__ Wo,
                         const float* __restrict__ Wa, const float* __restrict__ Wu,
                         const float* __restrict__ bo, const float* __restrict__ ba,
                         __half* __restrict__ vh,
                         __nv_bfloat16* __restrict__ qh, __nv_bfloat16* __restrict__ ql,
                         __nv_bfloat16* __restrict__ uh, __nv_bfloat16* __restrict__ ul,
                         float* __restrict__ qbias)
{
    int idx = blockIdx.x * blockDim.x + threadIdx.x;
    if (idx < 384)
        qbias[idx] = (idx < 256) ? bo[idx] : ba[idx - 256];

    if (idx < 65536) {
        int n = idx >> 8, k = idx & 255;
        vh[idx] = __float2half(Wv[(long)k * 256 + n]);
        return;
    }
    float f; __nv_bfloat16 *hi, *lo; int local;
    if (idx < 163840) {
        local = idx - 65536;                 // [n<384][k]
        int n = local >> 8, k = local & 255;
        f = (n < 256) ? Wo[(long)k * 256 + n] : Wa[(long)k * 128 + (n - 256)];
        hi = qh; lo = ql;
    } else if (idx < 229376) {
        local = idx - 163840;
        int n = local >> 8, k = local & 255;
        f = Wu[(long)k * 256 + n]; hi = uh; lo = ul;
    } else return;
    __nv_bfloat16 h = __float2bfloat16(f);
    __nv_bfloat16 l = __float2bfloat16(f - __bfloat162float(h));
    hi[local] = h;
    lo[local] = l;
}

// ====== fused softmax + sampling-loc + bilinear gather (one warp per (bq,h)) ===
__global__ __launch_bounds__(256) void msda_sample(const float* __restrict__ refp)
{
    int warp = (blockIdx.x * blockDim.x + threadIdx.x) >> 5;
    int lane = threadIdx.x & 31;
    if (warp >= NQ * NUM_HEADS) return;
    int h  = warp & 7;
    int bq = warp >> 3;
    int b  = bq / LQ_;

    // ---- per-warp softmax + sampling locations (lane i = point i, dup on hi half)
    const float* qrow = &g_qoff[(long)bq * 384];
    int i = lane & 15;
    int l = i >> 2;
    float aw = qrow[256 + h * 16 + i];
    float m = aw;
    #pragma unroll
    for (int s = 1; s < 16; s <<= 1) m = fmaxf(m, __shfl_xor_sync(0xffffffffu, m, s));
    float e = expf(aw - m);
    float ssum = e;
    #pragma unroll
    for (int s = 1; s < 16; s <<= 1) ssum += __shfl_xor_sync(0xffffffffu, ssum, s);
    float w = e / ssum;

    float iw = 1.f / (float)(128 >> l);
    float rx = refp[((long)bq * 4 + l) * 2 + 0];
    float ry = refp[((long)bq * 4 + l) * 2 + 1];
    float lx = rx + qrow[h * 32 + 2 * i]     * iw;
    float ly = ry + qrow[h * 32 + 2 * i + 1] * iw;

    const __half* vb = g_v + (long)b * LEN_V_ * EMBED + h * HEAD_DIM + lane;
    const int starts[4] = {0, 16384, 20480, 21504};

    float acc = 0.f;
    #pragma unroll
    for (int pt = 0; pt < 16; pt++) {
        const int lv = pt >> 2;
        const int W  = 128 >> lv;
        const int H  = W;
        const __half* vl = vb + (long)starts[lv] * EMBED;

        float sx = __shfl_sync(0xffffffffu, lx, pt);
        float sy = __shfl_sync(0xffffffffu, ly, pt);
        float sw = __shfl_sync(0xffffffffu, w,  pt);

        float px = sx * (float)W - 0.5f;
        float py = sy * (float)H - 0.5f;
        float x0f = floorf(px), y0f = floorf(py);
        float dx = px - x0f, dy = py - y0f;
        int x0 = (int)x0f, y0 = (int)y0f;
        float w00 = (1.f - dx) * (1.f - dy) * sw;
        float w10 = dx * (1.f - dy) * sw;
        float w01 = (1.f - dx) * dy * sw;
        float w11 = dx * dy * sw;
        bool xv0 = (x0 >= 0) && (x0 < W);
        bool xv1 = (x0 >= -1) && (x0 + 1 < W);
        bool yv0 = (y0 >= 0) && (y0 < H);
        bool yv1 = (y0 >= -1) && (y0 + 1 < H);
        if (xv0 && yv0) acc += w00 * __half2float(vl[((long)y0 * W + x0) * EMBED]);
        if (xv1 && yv0) acc += w10 * __half2float(vl[((long)y0 * W + x0 + 1) * EMBED]);
        if (xv0 && yv1) acc += w01 * __half2float(vl[((long)(y0 + 1) * W + x0) * EMBED]);
        if (xv1 && yv1) acc += w11 * __half2float(vl[((long)(y0 + 1) * W + x0 + 1) * EMBED]);
    }
    g_mid[(long)bq * EMBED + h * HEAD_DIM + lane] = acc;
}

// =================== launch ===================
extern "C" void kernel_launch(void* const* d_in, const int* in_sizes, int n_in,
                              void* d_out, int out_size)
{
    const float* query   = (const float*)d_in[0];
    const float* refp    = (const float*)d_in[1];
    const float* value   = (const float*)d_in[2];
    const float* w_value = (const float*)d_in[3];
    const float* b_value = (const float*)d_in[4];
    const float* w_off   = (const float*)d_in[5];
    const float* b_off   = (const float*)d_in[6];
    const float* w_attn  = (const float*)d_in[7];
    const float* b_attn  = (const float*)d_in[8];
    const float* w_out   = (const float*)d_in[9];
    const float* b_out   = (const float*)d_in[10];
    float* out = (float*)d_out;

    __half *pv, *wvh;
    float *pqoff, *pmid, *pqbias;
    cudaGetSymbolAddress((void**)&pv,    g_v);
    cudaGetSymbolAddress((void**)&pqoff, g_qoff);
    cudaGetSymbolAddress((void**)&pmid,  g_mid);
    cudaGetSymbolAddress((void**)&pqbias,g_qbias);
    cudaGetSymbolAddress((void**)&wvh,   g_wvh);

    __nv_bfloat16 *qh, *ql, *ouh, *oul;
    cudaGetSymbolAddress((void**)&qh,  g_qh);   cudaGetSymbolAddress((void**)&ql,  g_ql);
    cudaGetSymbolAddress((void**)&ouh, g_ouh);  cudaGetSymbolAddress((void**)&oul, g_oul);

    static int smem_set = 0;
    if (!smem_set) {
        cudaFuncSetAttribute(bf16x3_gemm_bias,
                             cudaFuncAttributeMaxDynamicSharedMemorySize, GEMM_SMEM);
        cudaFuncSetAttribute(fp16_gemm_v,
                             cudaFuncAttributeMaxDynamicSharedMemorySize, V_SMEM);
        smem_set = 1;
    }

    // 1) pack all weights + combined bias (one launch)
    pack_all<<<(229376 + 255) / 256, 256>>>(w_value, w_off, w_attn, w_out, b_off, b_attn,
                                            wvh, qh, ql, ouh, oul, pqbias);

    // 2) [off|aw] = query @ [w_off|w_attn] + bias   (7200 x 384 x 256)
    {
        dim3 grid(384 / BN, (NQ + BM - 1) / BM);
        bf16x3_gemm_bias<<<grid, 256, GEMM_SMEM>>>(query, qh, ql, pqbias, pqoff, NQ, 384, EMBED);
    }
    // 3) v = value @ w_value + b_value  (174080 x 256 x 256, fp16, 512 threads)
    {
        fp16_gemm_v<<<MV / 128, 512, V_SMEM>>>(value, wvh, b_value, pv);
    }
    // 4) fused softmax + bilinear sample (one warp per (b,q,h))  <- profiled slot
    {
        int warps = NQ * NUM_HEADS;
        msda_sample<<<(warps * 32 + 255) / 256, 256>>>(refp);
    }
    // 5) out = mid @ w_out + b_out -> d_out
    {
        dim3 grid(EMBED / BN, (NQ + BM - 1) / BM);
        bf16x3_gemm_bias<<<grid, 256, GEMM_SMEM>>>(pmid, ouh, oul, b_out, out, NQ, EMBED, EMBED);
    }
}

// round 12
// speedup vs baseline: 4.3850x; 1.1492x over previous
#include <cuda_runtime.h>
#include <cuda_bf16.h>
#include <cuda_fp16.h>
#include <math.h>
#include <stdint.h>

#define NUM_HEADS  8
#define NUM_LEVELS 4
#define NUM_POINTS 4
#define HEAD_DIM   32
#define EMBED      256
#define BS_        8
#define LQ_        900
#define LEN_V_     21760
#define NQ   (BS_*LQ_)        // 7200
#define MV   (BS_*LEN_V_)     // 174080

// single extern shared declaration for the whole TU
extern __shared__ char dsmem[];

// -------- scratch (device globals; no allocations allowed) --------
__device__ __half g_v  [(size_t)MV*EMBED];          // projected value, fp16, 89 MB
__device__ float  g_qoff[(size_t)NQ*384];           // [off(256) | attn(128)] per row
__device__ float  g_mid[(size_t)NQ*EMBED];
__device__ float  g_qbias[384];

// packed weights
__device__ __half        g_wvh[256*256];             // value weights, fp16 [n][k]
__device__ __nv_bfloat16 g_qh [384*256], g_ql [384*256];
__device__ __nv_bfloat16 g_ouh[256*256], g_oul[256*256];

// ======================= common helpers =======================
__device__ __forceinline__ void split2(float a, float b, uint32_t& hi, uint32_t& lo) {
    __nv_bfloat162 h = __floats2bfloat162_rn(a, b);
    float ra = a - __bfloat162float(h.x);
    float rb = b - __bfloat162float(h.y);
    __nv_bfloat162 l = __floats2bfloat162_rn(ra, rb);
    hi = *reinterpret_cast<uint32_t*>(&h);
    lo = *reinterpret_cast<uint32_t*>(&l);
}

__device__ __forceinline__ void cp16(uint32_t dst, const void* src) {
    asm volatile("cp.async.ca.shared.global [%0], [%1], 16;" :: "r"(dst), "l"(src));
}

__device__ __forceinline__ void ldsm_x4(uint32_t& r0, uint32_t& r1, uint32_t& r2,
                                        uint32_t& r3, uint32_t addr) {
    asm volatile("ldmatrix.sync.aligned.m8n8.x4.shared.b16 {%0,%1,%2,%3}, [%4];"
                 : "=r"(r0), "=r"(r1), "=r"(r2), "=r"(r3) : "r"(addr));
}

__device__ __forceinline__ void mma_bf16(float* c, const uint32_t* a, const uint32_t* b) {
    asm volatile(
        "mma.sync.aligned.m16n8k16.row.col.f32.bf16.bf16.f32 "
        "{%0,%1,%2,%3}, {%4,%5,%6,%7}, {%8,%9}, {%0,%1,%2,%3};\n"
        : "+f"(c[0]), "+f"(c[1]), "+f"(c[2]), "+f"(c[3])
        : "r"(a[0]), "r"(a[1]), "r"(a[2]), "r"(a[3]), "r"(b[0]), "r"(b[1]));
}

__device__ __forceinline__ void mma_fp16(float* c, const uint32_t* a, const uint32_t* b) {
    asm volatile(
        "mma.sync.aligned.m16n8k16.row.col.f32.f16.f16.f32 "
        "{%0,%1,%2,%3}, {%4,%5,%6,%7}, {%8,%9}, {%0,%1,%2,%3};\n"
        : "+f"(c[0]), "+f"(c[1]), "+f"(c[2]), "+f"(c[3])
        : "r"(a[0]), "r"(a[1]), "r"(a[2]), "r"(a[3]), "r"(b[0]), "r"(b[1]));
}

#define LDW 20   // 32-bit words per smem row (16 data + 4 pad), conflict-free ldmatrix

// ====== v-projection GEMM: BM=128, BN=256, fp16, 512 threads (16 warps) =======
#define V_AS 2560                 // words: A plane (128 rows x 20)
#define V_BS 5120                 // words: B plane (256 rows x 20)
#define V_STAGE (V_AS + V_BS)     // 7680 words
#define V_SMEM (2 * V_STAGE * 4)  // 61440 B

__global__ __launch_bounds__(512, 1) void fp16_gemm_v(
    const float* __restrict__ A, const __half* __restrict__ Bh,
    const float* __restrict__ bias, __half* __restrict__ C)
{
    uint32_t* smem = reinterpret_cast<uint32_t*>(dsmem);
    const uint32_t smem_u32 = (uint32_t)__cvta_generic_to_shared(smem);

    const int tid   = threadIdx.x;
    const int lane  = tid & 31;
    const int warp  = tid >> 5;       // 0..15
    const int warpM = warp >> 2;      // 0..3 (32 rows each)
    const int warpN = warp & 3;       // 0..3 (64 cols each)
    const int brow  = blockIdx.x * 128;
    const int g     = lane >> 2;
    const int tg    = lane & 3;

    const uint32_t a_off = (((lane & 15) * LDW) + ((lane >> 4) << 2)) * 4;
    const uint32_t b_off = ((((lane & 7) + ((lane >> 4) << 3)) * LDW) + (((lane >> 3) & 1) << 2)) * 4;

    float acc[2][8][4];
    #pragma unroll
    for (int i = 0; i < 2; i++)
        #pragma unroll
        for (int j = 0; j < 8; j++)
            #pragma unroll
            for (int r = 0; r < 4; r++) acc[i][j][r] = 0.f;

    float4 pa[2];
    auto load_A = [&](int kt) {
        #pragma unroll
        for (int i = 0; i < 2; i++) {
            int idx  = tid + i * 512;     // 0..1023
            int arow = idx >> 3;          // 0..127
            int ac4  = idx & 7;
            pa[i] = *reinterpret_cast<const float4*>(&A[(long)(brow + arow) * 256 + kt + ac4 * 4]);
        }
    };

    auto store_A = [&](int stage) {
        uint32_t* As = smem + stage * V_STAGE;
        #pragma unroll
        for (int i = 0; i < 2; i++) {
            int idx  = tid + i * 512;
            int arow = idx >> 3;
            int ac4  = idx & 7;
            __half2 h0 = __floats2half2_rn(pa[i].x, pa[i].y);
            __half2 h1 = __floats2half2_rn(pa[i].z, pa[i].w);
            *reinterpret_cast<uint2*>(&As[arow * LDW + ac4 * 2]) =
                make_uint2(*reinterpret_cast<uint32_t*>(&h0), *reinterpret_cast<uint32_t*>(&h1));
        }
    };

    auto issue_B = [&](int stage, int kt) {
        uint32_t base = smem_u32 + (uint32_t)((stage * V_STAGE + V_AS) * 4);
        #pragma unroll
        for (int i = 0; i < 2; i++) {
            int idx = tid + i * 512;       // 0..1023
            int row = idx >> 2, c = idx & 3;
            cp16(base + (uint32_t)((row * LDW + c * 4) * 4),
                 Bh + ((long)row * 256 + kt + c * 8));
        }
        asm volatile("cp.async.commit_group;" ::: "memory");
    };

    issue_B(0, 0);
    load_A(0);
    store_A(0);
    asm volatile("cp.async.wait_group 0;" ::: "memory");
    __syncthreads();

    for (int kt = 0; kt < 256; kt += 32) {
        const int s = (kt >> 5) & 1;
        const bool has_next = (kt + 32 < 256);
        if (has_next) {
            issue_B(s ^ 1, kt + 32);
            load_A(kt + 32);
        }

        const uint32_t s_as = smem_u32 + (uint32_t)(s * V_STAGE * 4);
        const uint32_t s_bs = s_as + V_AS * 4;

        #pragma unroll
        for (int ks = 0; ks < 2; ks++) {
            const uint32_t kb = ks * 8 * 4;
            uint32_t ah[2][4], bh[8][2];
            #pragma unroll
            for (int mt = 0; mt < 2; mt++) {
                uint32_t base = s_as + a_off + (uint32_t)((warpM * 32 + mt * 16) * LDW * 4) + kb;
                ldsm_x4(ah[mt][0], ah[mt][1], ah[mt][2], ah[mt][3], base);
            }
            #pragma unroll
            for (int p = 0; p < 4; p++) {
                uint32_t base = s_bs + b_off + (uint32_t)((warpN * 64 + p * 16) * LDW * 4) + kb;
                ldsm_x4(bh[2*p][0], bh[2*p][1], bh[2*p+1][0], bh[2*p+1][1], base);
            }
            #pragma unroll
            for (int mt = 0; mt < 2; mt++)
                #pragma unroll
                for (int nt = 0; nt < 8; nt++)
                    mma_fp16(acc[mt][nt], ah[mt], bh[nt]);
        }

        if (has_next) {
            store_A(s ^ 1);
            asm volatile("cp.async.wait_group 0;" ::: "memory");
        }
        __syncthreads();
    }

    // epilogue: + bias, fp16 store
    #pragma unroll
    for (int mt = 0; mt < 2; mt++) {
        long row0 = brow + warpM * 32 + mt * 16 + g;
        #pragma unroll
        for (int nt = 0; nt < 8; nt++) {
            int col = warpN * 64 + nt * 8 + tg * 2;
            float b0 = bias[col], b1 = bias[col + 1];
            *reinterpret_cast<__half2*>(&C[row0 * 256 + col]) =
                __floats2half2_rn(acc[mt][nt][0] + b0, acc[mt][nt][1] + b1);
            *reinterpret_cast<__half2*>(&C[(row0 + 8) * 256 + col]) =
                __floats2half2_rn(acc[mt][nt][2] + b0, acc[mt][nt][3] + b1);
        }
    }
}

// ============ bf16 split-2 mma.sync GEMM (small GEMMs, BN=128) =============
#define BM 128
#define BN 128
#define BK 32
#define TILE_WORDS (BM * LDW)
#define STAGE_WORDS (4 * TILE_WORDS)
#define GEMM_SMEM (2 * STAGE_WORDS * 4)

__global__ __launch_bounds__(256) void bf16x3_gemm_bias(
    const float* __restrict__ A,
    const __nv_bfloat16* __restrict__ Bh, const __nv_bfloat16* __restrict__ Bl,
    const float* __restrict__ bias, float* __restrict__ C,
    int M, int N, int K)
{
    uint32_t* smem = reinterpret_cast<uint32_t*>(dsmem);
    const uint32_t smem_u32 = (uint32_t)__cvta_generic_to_shared(smem);

    const int tid   = threadIdx.x;
    const int lane  = tid & 31;
    const int warp  = tid >> 5;
    const int warpM = warp >> 2;
    const int warpN = warp & 3;
    const int brow  = blockIdx.y * BM;
    const int bcol  = blockIdx.x * BN;
    const int g     = lane >> 2;
    const int tg    = lane & 3;

    const uint32_t lohalf = TILE_WORDS * 4;
    const uint32_t a_off = (((lane & 15) * LDW) + ((lane >> 4) << 2)) * 4;
    const uint32_t b_off = ((((lane & 7) + ((lane >> 4) << 3)) * LDW) + (((lane >> 3) & 1) << 2)) * 4;

    float acc[4][4][4];
    #pragma unroll
    for (int i = 0; i < 4; i++)
        #pragma unroll
        for (int j = 0; j < 4; j++)
            #pragma unroll
            for (int r = 0; r < 4; r++) acc[i][j][r] = 0.f;

    float4 pa[4];
    auto load_A = [&](int kt) {
        #pragma unroll
        for (int i = 0; i < 4; i++) {
            int idx  = tid + i * 256;
            int arow = idx >> 3;
            int ac4  = idx & 7;
            int grow = brow + arow;
            pa[i] = make_float4(0.f, 0.f, 0.f, 0.f);
            if (grow < M)
                pa[i] = *reinterpret_cast<const float4*>(&A[(long)grow * K + kt + ac4 * 4]);
        }
    };

    auto store_A = [&](int stage) {
        uint32_t* As0 = smem + stage * STAGE_WORDS;
        uint32_t* As1 = As0 + TILE_WORDS;
        #pragma unroll
        for (int i = 0; i < 4; i++) {
            int idx  = tid + i * 256;
            int arow = idx >> 3;
            int ac4  = idx & 7;
            uint32_t h0, l0, h1, l1;
            split2(pa[i].x, pa[i].y, h0, l0);
            split2(pa[i].z, pa[i].w, h1, l1);
            *reinterpret_cast<uint2*>(&As0[arow * LDW + ac4 * 2]) = make_uint2(h0, h1);
            *reinterpret_cast<uint2*>(&As1[arow * LDW + ac4 * 2]) = make_uint2(l0, l1);
        }
    };

    auto issue_B = [&](int stage, int kt) {
        uint32_t base = smem_u32 + (uint32_t)((stage * STAGE_WORDS + 2 * TILE_WORDS) * 4);
        #pragma unroll
        for (int i = 0; i < 2; i++) {
            int idx = tid + i * 256;
            int row = idx >> 2, c = idx & 3;
            cp16(base + (uint32_t)((row * LDW + c * 4) * 4),
                 Bh + ((long)(bcol + row) * K + kt + c * 8));
        }
        #pragma unroll
        for (int i = 0; i < 2; i++) {
            int idx = tid + i * 256;
            int row = idx >> 2, c = idx & 3;
            cp16(base + lohalf + (uint32_t)((row * LDW + c * 4) * 4),
                 Bl + ((long)(bcol + row) * K + kt + c * 8));
        }
        asm volatile("cp.async.commit_group;" ::: "memory");
    };

    issue_B(0, 0);
    load_A(0);
    store_A(0);
    asm volatile("cp.async.wait_group 0;" ::: "memory");
    __syncthreads();

    for (int kt = 0; kt < K; kt += BK) {
        const int s = (kt >> 5) & 1;
        const bool has_next = (kt + BK < K);
        if (has_next) {
            issue_B(s ^ 1, kt + BK);
            load_A(kt + BK);
        }

        const uint32_t s_as0 = smem_u32 + (uint32_t)(s * STAGE_WORDS * 4);
        const uint32_t s_bs0 = s_as0 + 2 * lohalf;

        #pragma unroll
        for (int ks = 0; ks < 2; ks++) {
            const uint32_t kb = ks * 8 * 4;
            uint32_t ah[4][4], al[4][4], bh[4][2], bl[4][2];
            #pragma unroll
            for (int mt = 0; mt < 4; mt++) {
                uint32_t base = s_as0 + a_off + (uint32_t)((warpM * 64 + mt * 16) * LDW * 4) + kb;
                ldsm_x4(ah[mt][0], ah[mt][1], ah[mt][2], ah[mt][3], base);
                ldsm_x4(al[mt][0], al[mt][1], al[mt][2], al[mt][3], base + lohalf);
            }
            #pragma unroll
            for (int p = 0; p < 2; p++) {
                uint32_t base = s_bs0 + b_off + (uint32_t)((warpN * 32 + p * 16) * LDW * 4) + kb;
                ldsm_x4(bh[2*p][0], bh[2*p][1], bh[2*p+1][0], bh[2*p+1][1], base);
                ldsm_x4(bl[2*p][0], bl[2*p][1], bl[2*p+1][0], bl[2*p+1][1], base + lohalf);
            }
            #pragma unroll
            for (int mt = 0; mt < 4; mt++)
                #pragma unroll
                for (int nt = 0; nt < 4; nt++) {
                    mma_bf16(acc[mt][nt], ah[mt], bh[nt]);
                    mma_bf16(acc[mt][nt], ah[mt], bl[nt]);
                    mma_bf16(acc[mt][nt], al[mt], bh[nt]);
                }
        }

        if (has_next) {
            store_A(s ^ 1);
            asm volatile("cp.async.wait_group 0;" ::: "memory");
        }
        __syncthreads();
    }

    #pragma unroll
    for (int mt = 0; mt < 4; mt++) {
        int row0 = brow + warpM * 64 + mt * 16 + g;
        #pragma unroll
        for (int nt = 0; nt < 4; nt++) {
            int col = bcol + warpN * 32 + nt * 8 + tg * 2;
            float b0 = bias[col], b1 = bias[col + 1];
            if (row0 < M) {
                float2 o = make_float2(acc[mt][nt][0] + b0, acc[mt][nt][1] + b1);
                *reinterpret_cast<float2*>(&C[(long)row0 * N + col]) = o;
            }
            if (row0 + 8 < M) {
                float2 o = make_float2(acc[mt][nt][2] + b0, acc[mt][nt][3] + b1);
                *reinterpret_cast<float2*>(&C[(long)(row0 + 8) * N + col]) = o;
            }
        }
    }
}

// ====== merged weight pack ====
__global__ void pack_all(const float* __restrict__ Wv, const float* __restrict__ Wo,
                         const float* __restrict__ Wa, const float* __restrict__ Wu,
                         const float* __restrict__ bo, const float* __restrict__ ba,
                         __half* __restrict__ vh,
                         __nv_bfloat16* __restrict__ qh, __nv_bfloat16* __restrict__ ql,
                         __nv_bfloat16* __restrict__ uh, __nv_bfloat16* __restrict__ ul,
                         float* __restrict__ qbias)
{
    int idx = blockIdx.x * blockDim.x + threadIdx.x;
    if (idx < 384)
        qbias[idx] = (idx < 256) ? bo[idx] : ba[idx - 256];

    if (idx < 65536) {
        int n = idx >> 8, k = idx & 255;
        vh[idx] = __float2half(Wv[(long)k * 256 + n]);
        return;
    }
    float f; __nv_bfloat16 *hi, *lo; int local;
    if (idx < 163840) {
        local = idx - 65536;                 // [n<384][k]
        int n = local >> 8, k = local & 255;
        f = (n < 256) ? Wo[(long)k * 256 + n] : Wa[(long)k * 128 + (n - 256)];
        hi = qh; lo = ql;
    } else if (idx < 229376) {
        local = idx - 163840;
        int n = local >> 8, k = local & 255;
        f = Wu[(long)k * 256 + n]; hi = uh; lo = ul;
    } else return;
    __nv_bfloat16 h = __float2bfloat16(f);
    __nv_bfloat16 l = __float2bfloat16(f - __bfloat162float(h));
    hi[local] = h;
    lo[local] = l;
}

// ====== fused softmax + bilinear gather: one warp per (bq,h), 2 points/iter ====
// lane = (half_id, d2): half_id = lane>>4 selects even/odd points,
// d2 = lane&15 selects half2 dim pair. 8 iterations cover 16 points.
__global__ __launch_bounds__(256) void msda_sample(const float* __restrict__ refp)
{
    int warp = (blockIdx.x * blockDim.x + threadIdx.x) >> 5;
    int lane = threadIdx.x & 31;
    if (warp >= NQ * NUM_HEADS) return;
    int h  = warp & 7;
    int bq = warp >> 3;
    int b  = bq / LQ_;

    // ---- softmax + locations: lane i (and i+16) holds point i's values
    const float* qrow = &g_qoff[(long)bq * 384];
    int i = lane & 15;
    int l = i >> 2;
    float aw = qrow[256 + h * 16 + i];
    float m = aw;
    #pragma unroll
    for (int s = 1; s < 16; s <<= 1) m = fmaxf(m, __shfl_xor_sync(0xffffffffu, m, s));
    float e = expf(aw - m);
    float ssum = e;
    #pragma unroll
    for (int s = 1; s < 16; s <<= 1) ssum += __shfl_xor_sync(0xffffffffu, ssum, s);
    float w = e / ssum;

    float iw = 1.f / (float)(128 >> l);
    float rx = refp[(bq * 4 + l) * 2 + 0];
    float ry = refp[(bq * 4 + l) * 2 + 1];
    float lx = rx + qrow[h * 32 + 2 * i]     * iw;
    float ly = ry + qrow[h * 32 + 2 * i + 1] * iw;

    // ---- gather: half2 granularity, 32-bit addressing
    const int half_id = lane >> 4;      // 0: points 0,2,..  1: points 1,3,..
    const int d2      = lane & 15;      // dim pair
    // base half2 pointer for this (b, h, d2): row stride = 128 half2
    const __half2* vb2 = reinterpret_cast<const __half2*>(g_v)
                       + (int)(b * (LEN_V_ * 128)) + h * 16 + d2;
    const int starts[4] = {0, 16384, 20480, 21504};

    float ax = 0.f, ay = 0.f;
    #pragma unroll
    for (int it = 0; it < 8; it++) {
        const int pt = it * 2 + half_id;
        const int lv = pt >> 2;
        const int W  = 128 >> lv;
        const int H  = W;
        const __half2* vl = vb2 + starts[lv] * 128;

        float sx = __shfl_sync(0xffffffffu, lx, pt);
        float sy = __shfl_sync(0xffffffffu, ly, pt);
        float sw = __shfl_sync(0xffffffffu, w,  pt);

        float px = sx * (float)W - 0.5f;
        float py = sy * (float)H - 0.5f;
        float x0f = floorf(px), y0f = floorf(py);
        float dx = px - x0f, dy = py - y0f;
        int x0 = (int)x0f, y0 = (int)y0f;
        float w00 = (1.f - dx) * (1.f - dy) * sw;
        float w10 = dx * (1.f - dy) * sw;
        float w01 = (1.f - dx) * dy * sw;
        float w11 = dx * dy * sw;
        bool xv0 = (x0 >= 0) && (x0 < W);
        bool xv1 = (x0 >= -1) && (x0 + 1 < W);
        bool yv0 = (y0 >= 0) && (y0 < H);
        bool yv1 = (y0 >= -1) && (y0 + 1 < H);
        int base = (y0 * W + x0) * 128;
        if (xv0 && yv0) { float2 v = __half22float2(vl[base]);            ax += w00 * v.x; ay += w00 * v.y; }
        if (xv1 && yv0) { float2 v = __half22float2(vl[base + 128]);      ax += w10 * v.x; ay += w10 * v.y; }
        if (xv0 && yv1) { float2 v = __half22float2(vl[base + W * 128]);  ax += w01 * v.x; ay += w01 * v.y; }
        if (xv1 && yv1) { float2 v = __half22float2(vl[base + W * 128 + 128]); ax += w11 * v.x; ay += w11 * v.y; }
    }
    // merge even/odd point partial sums across the two half-warps
    ax += __shfl_xor_sync(0xffffffffu, ax, 16);
    ay += __shfl_xor_sync(0xffffffffu, ay, 16);

    if (half_id == 0)
        *reinterpret_cast<float2*>(&g_mid[(long)bq * 256 + h * 32 + 2 * d2]) =
            make_float2(ax, ay);
}

// =================== launch ===================
extern "C" void kernel_launch(void* const* d_in, const int* in_sizes, int n_in,
                              void* d_out, int out_size)
{
    const float* query   = (const float*)d_in[0];
    const float* refp    = (const float*)d_in[1];
    const float* value   = (const float*)d_in[2];
    const float* w_value = (const float*)d_in[3];
    const float* b_value = (const float*)d_in[4];
    const float* w_off   = (const float*)d_in[5];
    const float* b_off   = (const float*)d_in[6];
    const float* w_attn  = (const float*)d_in[7];
    const float* b_attn  = (const float*)d_in[8];
    const float* w_out   = (const float*)d_in[9];
    const float* b_out   = (const float*)d_in[10];
    float* out = (float*)d_out;

    __half *pv, *wvh;
    float *pqoff, *pmid, *pqbias;
    cudaGetSymbolAddress((void**)&pv,    g_v);
    cudaGetSymbolAddress((void**)&pqoff, g_qoff);
    cudaGetSymbolAddress((void**)&pmid,  g_mid);
    cudaGetSymbolAddress((void**)&pqbias,g_qbias);
    cudaGetSymbolAddress((void**)&wvh,   g_wvh);

    __nv_bfloat16 *qh, *ql, *ouh, *oul;
    cudaGetSymbolAddress((void**)&qh,  g_qh);   cudaGetSymbolAddress((void**)&ql,  g_ql);
    cudaGetSymbolAddress((void**)&ouh, g_ouh);  cudaGetSymbolAddress((void**)&oul, g_oul);

    static int smem_set = 0;
    if (!smem_set) {
        cudaFuncSetAttribute(bf16x3_gemm_bias,
                             cudaFuncAttributeMaxDynamicSharedMemorySize, GEMM_SMEM);
        cudaFuncSetAttribute(fp16_gemm_v,
                             cudaFuncAttributeMaxDynamicSharedMemorySize, V_SMEM);
        smem_set = 1;
    }

    // 1) pack all weights + combined bias (one launch)
    pack_all<<<(229376 + 255) / 256, 256>>>(w_value, w_off, w_attn, w_out, b_off, b_attn,
                                            wvh, qh, ql, ouh, oul, pqbias);

    // 2) [off|aw] = query @ [w_off|w_attn] + bias   (7200 x 384 x 256)
    {
        dim3 grid(384 / BN, (NQ + BM - 1) / BM);
        bf16x3_gemm_bias<<<grid, 256, GEMM_SMEM>>>(query, qh, ql, pqbias, pqoff, NQ, 384, EMBED);
    }
    // 3) v = value @ w_value + b_value  (174080 x 256 x 256, fp16, 512 threads)
    {
        fp16_gemm_v<<<MV / 128, 512, V_SMEM>>>(value, wvh, b_value, pv);
    }
    // 4) fused softmax + bilinear sample (one warp per (b,q,h))  <- profiled slot
    {
        int warps = NQ * NUM_HEADS;
        msda_sample<<<(warps * 32 + 255) / 256, 256>>>(refp);
    }
    // 5) out = mid @ w_out + b_out -> d_out
    {
        dim3 grid(EMBED / BN, (NQ + BM - 1) / BM);
        bf16x3_gemm_bias<<<grid, 256, GEMM_SMEM>>>(pmid, ouh, oul, b_out, out, NQ, EMBED, EMBED);
    }
}

// round 13
// speedup vs baseline: 4.6699x; 1.0650x over previous
#include <cuda_runtime.h>
#include <cuda_bf16.h>
#include <cuda_fp16.h>
#include <math.h>
#include <stdint.h>

#define NUM_HEADS  8
#define NUM_LEVELS 4
#define NUM_POINTS 4
#define HEAD_DIM   32
#define EMBED      256
#define BS_        8
#define LQ_        900
#define LEN_V_     21760
#define NQ   (BS_*LQ_)        // 7200
#define MV   (BS_*LEN_V_)     // 174080

// single extern shared declaration for the whole TU
extern __shared__ char dsmem[];

// -------- scratch (device globals; no allocations allowed) --------
__device__ __half g_v  [(size_t)MV*EMBED];          // projected value, fp16, 89 MB
__device__ float  g_qoff[(size_t)NQ*384];           // [off(256) | attn(128)] per row
__device__ __half g_mid16[(size_t)(NQ+128)*EMBED];  // sampled output, fp16 (padded rows)
__device__ float  g_qbias[384];

// packed weights
__device__ __half        g_wvh [256*256];            // value weights, fp16 [n][k]
__device__ __half        g_ou16[256*256];            // out weights,   fp16 [n][k]
__device__ __nv_bfloat16 g_qh  [384*256], g_ql[384*256];

// ======================= common helpers =======================
__device__ __forceinline__ void split2(float a, float b, uint32_t& hi, uint32_t& lo) {
    __nv_bfloat162 h = __floats2bfloat162_rn(a, b);
    float ra = a - __bfloat162float(h.x);
    float rb = b - __bfloat162float(h.y);
    __nv_bfloat162 l = __floats2bfloat162_rn(ra, rb);
    hi = *reinterpret_cast<uint32_t*>(&h);
    lo = *reinterpret_cast<uint32_t*>(&l);
}

__device__ __forceinline__ void cp16(uint32_t dst, const void* src) {
    asm volatile("cp.async.ca.shared.global [%0], [%1], 16;" :: "r"(dst), "l"(src));
}

__device__ __forceinline__ void ldsm_x4(uint32_t& r0, uint32_t& r1, uint32_t& r2,
                                        uint32_t& r3, uint32_t addr) {
    asm volatile("ldmatrix.sync.aligned.m8n8.x4.shared.b16 {%0,%1,%2,%3}, [%4];"
                 : "=r"(r0), "=r"(r1), "=r"(r2), "=r"(r3) : "r"(addr));
}

__device__ __forceinline__ void mma_bf16(float* c, const uint32_t* a, const uint32_t* b) {
    asm volatile(
        "mma.sync.aligned.m16n8k16.row.col.f32.bf16.bf16.f32 "
        "{%0,%1,%2,%3}, {%4,%5,%6,%7}, {%8,%9}, {%0,%1,%2,%3};\n"
        : "+f"(c[0]), "+f"(c[1]), "+f"(c[2]), "+f"(c[3])
        : "r"(a[0]), "r"(a[1]), "r"(a[2]), "r"(a[3]), "r"(b[0]), "r"(b[1]));
}

__device__ __forceinline__ void mma_fp16(float* c, const uint32_t* a, const uint32_t* b) {
    asm volatile(
        "mma.sync.aligned.m16n8k16.row.col.f32.f16.f16.f32 "
        "{%0,%1,%2,%3}, {%4,%5,%6,%7}, {%8,%9}, {%0,%1,%2,%3};\n"
        : "+f"(c[0]), "+f"(c[1]), "+f"(c[2]), "+f"(c[3])
        : "r"(a[0]), "r"(a[1]), "r"(a[2]), "r"(a[3]), "r"(b[0]), "r"(b[1]));
}

#define LDW 20   // 32-bit words per smem row (16 data + 4 pad), conflict-free ldmatrix

// ====== v-projection GEMM: BM=128, BN=256, fp16, 512 threads (16 warps) =======
#define V_AS 2560                 // words: A plane (128 rows x 20)
#define V_BS 5120                 // words: B plane (256 rows x 20)
#define V_STAGE (V_AS + V_BS)     // 7680 words
#define V_SMEM (2 * V_STAGE * 4)  // 61440 B

__global__ __launch_bounds__(512, 1) void fp16_gemm_v(
    const float* __restrict__ A, const __half* __restrict__ Bh,
    const float* __restrict__ bias, __half* __restrict__ C)
{
    uint32_t* smem = reinterpret_cast<uint32_t*>(dsmem);
    const uint32_t smem_u32 = (uint32_t)__cvta_generic_to_shared(smem);

    const int tid   = threadIdx.x;
    const int lane  = tid & 31;
    const int warp  = tid >> 5;       // 0..15
    const int warpM = warp >> 2;      // 0..3 (32 rows each)
    const int warpN = warp & 3;       // 0..3 (64 cols each)
    const int brow  = blockIdx.x * 128;
    const int g     = lane >> 2;
    const int tg    = lane & 3;

    const uint32_t a_off = (((lane & 15) * LDW) + ((lane >> 4) << 2)) * 4;
    const uint32_t b_off = ((((lane & 7) + ((lane >> 4) << 3)) * LDW) + (((lane >> 3) & 1) << 2)) * 4;

    float acc[2][8][4];
    #pragma unroll
    for (int i = 0; i < 2; i++)
        #pragma unroll
        for (int j = 0; j < 8; j++)
            #pragma unroll
            for (int r = 0; r < 4; r++) acc[i][j][r] = 0.f;

    float4 pa[2];
    auto load_A = [&](int kt) {
        #pragma unroll
        for (int i = 0; i < 2; i++) {
            int idx  = tid + i * 512;     // 0..1023
            int arow = idx >> 3;          // 0..127
            int ac4  = idx & 7;
            pa[i] = *reinterpret_cast<const float4*>(&A[(long)(brow + arow) * 256 + kt + ac4 * 4]);
        }
    };

    auto store_A = [&](int stage) {
        uint32_t* As = smem + stage * V_STAGE;
        #pragma unroll
        for (int i = 0; i < 2; i++) {
            int idx  = tid + i * 512;
            int arow = idx >> 3;
            int ac4  = idx & 7;
            __half2 h0 = __floats2half2_rn(pa[i].x, pa[i].y);
            __half2 h1 = __floats2half2_rn(pa[i].z, pa[i].w);
            *reinterpret_cast<uint2*>(&As[arow * LDW + ac4 * 2]) =
                make_uint2(*reinterpret_cast<uint32_t*>(&h0), *reinterpret_cast<uint32_t*>(&h1));
        }
    };

    auto issue_B = [&](int stage, int kt) {
        uint32_t base = smem_u32 + (uint32_t)((stage * V_STAGE + V_AS) * 4);
        #pragma unroll
        for (int i = 0; i < 2; i++) {
            int idx = tid + i * 512;       // 0..1023
            int row = idx >> 2, c = idx & 3;
            cp16(base + (uint32_t)((row * LDW + c * 4) * 4),
                 Bh + ((long)row * 256 + kt + c * 8));
        }
        asm volatile("cp.async.commit_group;" ::: "memory");
    };

    issue_B(0, 0);
    load_A(0);
    store_A(0);
    asm volatile("cp.async.wait_group 0;" ::: "memory");
    __syncthreads();

    for (int kt = 0; kt < 256; kt += 32) {
        const int s = (kt >> 5) & 1;
        const bool has_next = (kt + 32 < 256);
        if (has_next) {
            issue_B(s ^ 1, kt + 32);
            load_A(kt + 32);
        }

        const uint32_t s_as = smem_u32 + (uint32_t)(s * V_STAGE * 4);
        const uint32_t s_bs = s_as + V_AS * 4;

        #pragma unroll
        for (int ks = 0; ks < 2; ks++) {
            const uint32_t kb = ks * 8 * 4;
            uint32_t ah[2][4], bh[8][2];
            #pragma unroll
            for (int mt = 0; mt < 2; mt++) {
                uint32_t base = s_as + a_off + (uint32_t)((warpM * 32 + mt * 16) * LDW * 4) + kb;
                ldsm_x4(ah[mt][0], ah[mt][1], ah[mt][2], ah[mt][3], base);
            }
            #pragma unroll
            for (int p = 0; p < 4; p++) {
                uint32_t base = s_bs + b_off + (uint32_t)((warpN * 64 + p * 16) * LDW * 4) + kb;
                ldsm_x4(bh[2*p][0], bh[2*p][1], bh[2*p+1][0], bh[2*p+1][1], base);
            }
            #pragma unroll
            for (int mt = 0; mt < 2; mt++)
                #pragma unroll
                for (int nt = 0; nt < 8; nt++)
                    mma_fp16(acc[mt][nt], ah[mt], bh[nt]);
        }

        if (has_next) {
            store_A(s ^ 1);
            asm volatile("cp.async.wait_group 0;" ::: "memory");
        }
        __syncthreads();
    }

    // epilogue: + bias, fp16 store
    #pragma unroll
    for (int mt = 0; mt < 2; mt++) {
        long row0 = brow + warpM * 32 + mt * 16 + g;
        #pragma unroll
        for (int nt = 0; nt < 8; nt++) {
            int col = warpN * 64 + nt * 8 + tg * 2;
            float b0 = bias[col], b1 = bias[col + 1];
            *reinterpret_cast<__half2*>(&C[row0 * 256 + col]) =
                __floats2half2_rn(acc[mt][nt][0] + b0, acc[mt][nt][1] + b1);
            *reinterpret_cast<__half2*>(&C[(row0 + 8) * 256 + col]) =
                __floats2half2_rn(acc[mt][nt][2] + b0, acc[mt][nt][3] + b1);
        }
    }
}

// ============ bf16 split-2 mma.sync GEMM (q-GEMM, BN=128) =============
#define BM 128
#define BN 128
#define BK 32
#define TILE_WORDS (BM * LDW)
#define STAGE_WORDS (4 * TILE_WORDS)
#define GEMM_SMEM (2 * STAGE_WORDS * 4)

__global__ __launch_bounds__(256) void bf16x3_gemm_bias(
    const float* __restrict__ A,
    const __nv_bfloat16* __restrict__ Bh, const __nv_bfloat16* __restrict__ Bl,
    const float* __restrict__ bias, float* __restrict__ C,
    int M, int N, int K)
{
    uint32_t* smem = reinterpret_cast<uint32_t*>(dsmem);
    const uint32_t smem_u32 = (uint32_t)__cvta_generic_to_shared(smem);

    const int tid   = threadIdx.x;
    const int lane  = tid & 31;
    const int warp  = tid >> 5;
    const int warpM = warp >> 2;
    const int warpN = warp & 3;
    const int brow  = blockIdx.y * BM;
    const int bcol  = blockIdx.x * BN;
    const int g     = lane >> 2;
    const int tg    = lane & 3;

    const uint32_t lohalf = TILE_WORDS * 4;
    const uint32_t a_off = (((lane & 15) * LDW) + ((lane >> 4) << 2)) * 4;
    const uint32_t b_off = ((((lane & 7) + ((lane >> 4) << 3)) * LDW) + (((lane >> 3) & 1) << 2)) * 4;

    float acc[4][4][4];
    #pragma unroll
    for (int i = 0; i < 4; i++)
        #pragma unroll
        for (int j = 0; j < 4; j++)
            #pragma unroll
            for (int r = 0; r < 4; r++) acc[i][j][r] = 0.f;

    float4 pa[4];
    auto load_A = [&](int kt) {
        #pragma unroll
        for (int i = 0; i < 4; i++) {
            int idx  = tid + i * 256;
            int arow = idx >> 3;
            int ac4  = idx & 7;
            int grow = brow + arow;
            pa[i] = make_float4(0.f, 0.f, 0.f, 0.f);
            if (grow < M)
                pa[i] = *reinterpret_cast<const float4*>(&A[(long)grow * K + kt + ac4 * 4]);
        }
    };

    auto store_A = [&](int stage) {
        uint32_t* As0 = smem + stage * STAGE_WORDS;
        uint32_t* As1 = As0 + TILE_WORDS;
        #pragma unroll
        for (int i = 0; i < 4; i++) {
            int idx  = tid + i * 256;
            int arow = idx >> 3;
            int ac4  = idx & 7;
            uint32_t h0, l0, h1, l1;
            split2(pa[i].x, pa[i].y, h0, l0);
            split2(pa[i].z, pa[i].w, h1, l1);
            *reinterpret_cast<uint2*>(&As0[arow * LDW + ac4 * 2]) = make_uint2(h0, h1);
            *reinterpret_cast<uint2*>(&As1[arow * LDW + ac4 * 2]) = make_uint2(l0, l1);
        }
    };

    auto issue_B = [&](int stage, int kt) {
        uint32_t base = smem_u32 + (uint32_t)((stage * STAGE_WORDS + 2 * TILE_WORDS) * 4);
        #pragma unroll
        for (int i = 0; i < 2; i++) {
            int idx = tid + i * 256;
            int row = idx >> 2, c = idx & 3;
            cp16(base + (uint32_t)((row * LDW + c * 4) * 4),
                 Bh + ((long)(bcol + row) * K + kt + c * 8));
        }
        #pragma unroll
        for (int i = 0; i < 2; i++) {
            int idx = tid + i * 256;
            int row = idx >> 2, c = idx & 3;
            cp16(base + lohalf + (uint32_t)((row * LDW + c * 4) * 4),
                 Bl + ((long)(bcol + row) * K + kt + c * 8));
        }
        asm volatile("cp.async.commit_group;" ::: "memory");
    };

    issue_B(0, 0);
    load_A(0);
    store_A(0);
    asm volatile("cp.async.wait_group 0;" ::: "memory");
    __syncthreads();

    for (int kt = 0; kt < K; kt += BK) {
        const int s = (kt >> 5) & 1;
        const bool has_next = (kt + BK < K);
        if (has_next) {
            issue_B(s ^ 1, kt + BK);
            load_A(kt + BK);
        }

        const uint32_t s_as0 = smem_u32 + (uint32_t)(s * STAGE_WORDS * 4);
        const uint32_t s_bs0 = s_as0 + 2 * lohalf;

        #pragma unroll
        for (int ks = 0; ks < 2; ks++) {
            const uint32_t kb = ks * 8 * 4;
            uint32_t ah[4][4], al[4][4], bh[4][2], bl[4][2];
            #pragma unroll
            for (int mt = 0; mt < 4; mt++) {
                uint32_t base = s_as0 + a_off + (uint32_t)((warpM * 64 + mt * 16) * LDW * 4) + kb;
                ldsm_x4(ah[mt][0], ah[mt][1], ah[mt][2], ah[mt][3], base);
                ldsm_x4(al[mt][0], al[mt][1], al[mt][2], al[mt][3], base + lohalf);
            }
            #pragma unroll
            for (int p = 0; p < 2; p++) {
                uint32_t base = s_bs0 + b_off + (uint32_t)((warpN * 32 + p * 16) * LDW * 4) + kb;
                ldsm_x4(bh[2*p][0], bh[2*p][1], bh[2*p+1][0], bh[2*p+1][1], base);
                ldsm_x4(bl[2*p][0], bl[2*p][1], bl[2*p+1][0], bl[2*p+1][1], base + lohalf);
            }
            #pragma unroll
            for (int mt = 0; mt < 4; mt++)
                #pragma unroll
                for (int nt = 0; nt < 4; nt++) {
                    mma_bf16(acc[mt][nt], ah[mt], bh[nt]);
                    mma_bf16(acc[mt][nt], ah[mt], bl[nt]);
                    mma_bf16(acc[mt][nt], al[mt], bh[nt]);
                }
        }

        if (has_next) {
            store_A(s ^ 1);
            asm volatile("cp.async.wait_group 0;" ::: "memory");
        }
        __syncthreads();
    }

    #pragma unroll
    for (int mt = 0; mt < 4; mt++) {
        int row0 = brow + warpM * 64 + mt * 16 + g;
        #pragma unroll
        for (int nt = 0; nt < 4; nt++) {
            int col = bcol + warpN * 32 + nt * 8 + tg * 2;
            float b0 = bias[col], b1 = bias[col + 1];
            if (row0 < M) {
                float2 o = make_float2(acc[mt][nt][0] + b0, acc[mt][nt][1] + b1);
                *reinterpret_cast<float2*>(&C[(long)row0 * N + col]) = o;
            }
            if (row0 + 8 < M) {
                float2 o = make_float2(acc[mt][nt][2] + b0, acc[mt][nt][3] + b1);
                *reinterpret_cast<float2*>(&C[(long)(row0 + 8) * N + col]) = o;
            }
        }
    }
}

// ========= fp16 GEMM for out-projection: A fp16 global, B fp16 packed =========
// BM=128, BN=128, 256 threads, warp tile 64x32, both tiles via cp.async.
#define F_TW 2560                 // words per tile (128 rows x 20)
#define F_STAGE (2 * F_TW)        // A + B
#define F_SMEM (2 * F_STAGE * 4)  // 40960 B

__global__ __launch_bounds__(256) void fp16_gemm_out(
    const __half* __restrict__ A, const __half* __restrict__ B,
    const float* __restrict__ bias, float* __restrict__ C,
    int M, int N, int K)
{
    uint32_t* smem = reinterpret_cast<uint32_t*>(dsmem);
    const uint32_t smem_u32 = (uint32_t)__cvta_generic_to_shared(smem);

    const int tid   = threadIdx.x;
    const int lane  = tid & 31;
    const int warp  = tid >> 5;
    const int warpM = warp >> 2;
    const int warpN = warp & 3;
    const int brow  = blockIdx.y * 128;
    const int bcol  = blockIdx.x * 128;
    const int g     = lane >> 2;
    const int tg    = lane & 3;

    const uint32_t a_off = (((lane & 15) * LDW) + ((lane >> 4) << 2)) * 4;
    const uint32_t b_off = ((((lane & 7) + ((lane >> 4) << 3)) * LDW) + (((lane >> 3) & 1) << 2)) * 4;

    float acc[4][4][4];
    #pragma unroll
    for (int i = 0; i < 4; i++)
        #pragma unroll
        for (int j = 0; j < 4; j++)
            #pragma unroll
            for (int r = 0; r < 4; r++) acc[i][j][r] = 0.f;

    auto issue_tiles = [&](int stage, int kt) {
        uint32_t baseA = smem_u32 + (uint32_t)(stage * F_STAGE * 4);
        uint32_t baseB = baseA + F_TW * 4;
        #pragma unroll
        for (int i = 0; i < 2; i++) {
            int idx = tid + i * 256;
            int row = idx >> 2, c = idx & 3;
            cp16(baseA + (uint32_t)((row * LDW + c * 4) * 4),
                 A + ((long)(brow + row) * K + kt + c * 8));   // A padded beyond M
        }
        #pragma unroll
        for (int i = 0; i < 2; i++) {
            int idx = tid + i * 256;
            int row = idx >> 2, c = idx & 3;
            cp16(baseB + (uint32_t)((row * LDW + c * 4) * 4),
                 B + ((long)(bcol + row) * K + kt + c * 8));
        }
        asm volatile("cp.async.commit_group;" ::: "memory");
    };

    issue_tiles(0, 0);
    asm volatile("cp.async.wait_group 0;" ::: "memory");
    __syncthreads();

    for (int kt = 0; kt < K; kt += 32) {
        const int s = (kt >> 5) & 1;
        const bool has_next = (kt + 32 < K);
        if (has_next) issue_tiles(s ^ 1, kt + 32);

        const uint32_t s_as = smem_u32 + (uint32_t)(s * F_STAGE * 4);
        const uint32_t s_bs = s_as + F_TW * 4;

        #pragma unroll
        for (int ks = 0; ks < 2; ks++) {
            const uint32_t kb = ks * 8 * 4;
            uint32_t ah[4][4], bh[4][2];
            #pragma unroll
            for (int mt = 0; mt < 4; mt++) {
                uint32_t base = s_as + a_off + (uint32_t)((warpM * 64 + mt * 16) * LDW * 4) + kb;
                ldsm_x4(ah[mt][0], ah[mt][1], ah[mt][2], ah[mt][3], base);
            }
            #pragma unroll
            for (int p = 0; p < 2; p++) {
                uint32_t base = s_bs + b_off + (uint32_t)((warpN * 32 + p * 16) * LDW * 4) + kb;
                ldsm_x4(bh[2*p][0], bh[2*p][1], bh[2*p+1][0], bh[2*p+1][1], base);
            }
            #pragma unroll
            for (int mt = 0; mt < 4; mt++)
                #pragma unroll
                for (int nt = 0; nt < 4; nt++)
                    mma_fp16(acc[mt][nt], ah[mt], bh[nt]);
        }

        if (has_next)
            asm volatile("cp.async.wait_group 0;" ::: "memory");
        __syncthreads();
    }

    #pragma unroll
    for (int mt = 0; mt < 4; mt++) {
        int row0 = brow + warpM * 64 + mt * 16 + g;
        #pragma unroll
        for (int nt = 0; nt < 4; nt++) {
            int col = bcol + warpN * 32 + nt * 8 + tg * 2;
            float b0 = bias[col], b1 = bias[col + 1];
            if (row0 < M) {
                float2 o = make_float2(acc[mt][nt][0] + b0, acc[mt][nt][1] + b1);
                *reinterpret_cast<float2*>(&C[(long)row0 * N + col]) = o;
            }
            if (row0 + 8 < M) {
                float2 o = make_float2(acc[mt][nt][2] + b0, acc[mt][nt][3] + b1);
                *reinterpret_cast<float2*>(&C[(long)(row0 + 8) * N + col]) = o;
            }
        }
    }
}

// ====== merged weight pack ====
// value -> fp16 [n][k]; q(off|attn) -> bf16 hi/lo; out -> fp16 [n][k]
__global__ void pack_all(const float* __restrict__ Wv, const float* __restrict__ Wo,
                         const float* __restrict__ Wa, const float* __restrict__ Wu,
                         const float* __restrict__ bo, const float* __restrict__ ba,
                         __half* __restrict__ vh,
                         __nv_bfloat16* __restrict__ qh, __nv_bfloat16* __restrict__ ql,
                         __half* __restrict__ u16,
                         float* __restrict__ qbias)
{
    int idx = blockIdx.x * blockDim.x + threadIdx.x;
    if (idx < 384)
        qbias[idx] = (idx < 256) ? bo[idx] : ba[idx - 256];

    if (idx < 65536) {
        int n = idx >> 8, k = idx & 255;
        vh[idx] = __float2half(Wv[(long)k * 256 + n]);
        return;
    }
    if (idx < 163840) {
        int local = idx - 65536;             // [n<384][k]
        int n = local >> 8, k = local & 255;
        float f = (n < 256) ? Wo[(long)k * 256 + n] : Wa[(long)k * 128 + (n - 256)];
        __nv_bfloat16 h = __float2bfloat16(f);
        __nv_bfloat16 l = __float2bfloat16(f - __bfloat162float(h));
        qh[local] = h;
        ql[local] = l;
        return;
    }
    if (idx < 229376) {
        int local = idx - 163840;
        int n = local >> 8, k = local & 255;
        u16[local] = __float2half(Wu[(long)k * 256 + n]);
    }
}

// ====== fused softmax + bilinear gather: one warp per (bq,h) ==================
// Phase 1 (lanes 0-15): softmax + per-point corner addresses/weights -> smem.
// Phase 2 (all lanes): 8 iters x 2 points, pure LDS + LDG + FFMA inner loop.
__global__ __launch_bounds__(256) void msda_sample(const float* __restrict__ refp)
{
    float* sm = reinterpret_cast<float*>(dsmem) + (threadIdx.x >> 5) * 128;  // 16 pts x 8
    int warp = (blockIdx.x * blockDim.x + threadIdx.x) >> 5;
    int lane = threadIdx.x & 31;
    if (warp >= NQ * NUM_HEADS) return;
    int h  = warp & 7;
    int bq = warp >> 3;
    int b  = bq / LQ_;

    // ---- softmax (lane i and i+16 hold point i)
    const float* qrow = &g_qoff[(long)bq * 384];
    int i = lane & 15;
    int l = i >> 2;
    float aw = qrow[256 + h * 16 + i];
    float m = aw;
    #pragma unroll
    for (int s = 1; s < 16; s <<= 1) m = fmaxf(m, __shfl_xor_sync(0xffffffffu, m, s));
    float e = expf(aw - m);
    float ssum = e;
    #pragma unroll
    for (int s = 1; s < 16; s <<= 1) ssum += __shfl_xor_sync(0xffffffffu, ssum, s);
    float w = e / ssum;

    const int starts[4] = {0, 16384, 20480, 21504};

    // ---- precompute corner addresses (clamped) + weights (validity-folded)
    if (lane < 16) {
        int W = 128 >> l;
        float iw = 1.f / (float)W;
        float rx = refp[(bq * 4 + l) * 2 + 0];
        float ry = refp[(bq * 4 + l) * 2 + 1];
        float lx = rx + qrow[h * 32 + 2 * i]     * iw;
        float ly = ry + qrow[h * 32 + 2 * i + 1] * iw;

        float px = lx * (float)W - 0.5f;
        float py = ly * (float)W - 0.5f;
        float x0f = floorf(px), y0f = floorf(py);
        float dx = px - x0f, dy = py - y0f;
        int x0 = (int)x0f, y0 = (int)y0f;
        bool xv0 = (x0 >= 0) && (x0 < W);
        bool xv1 = (x0 >= -1) && (x0 + 1 < W);
        bool yv0 = (y0 >= 0) && (y0 < W);
        bool yv1 = (y0 >= -1) && (y0 + 1 < W);
        int cx0 = min(max(x0, 0), W - 1);
        int cx1 = min(max(x0 + 1, 0), W - 1);
        int cy0 = min(max(y0, 0), W - 1);
        int cy1 = min(max(y0 + 1, 0), W - 1);
        int base = starts[l] * 128;
        int W128 = W * 128;
        int* smi = reinterpret_cast<int*>(sm + i * 8);
        smi[0] = base + cy0 * W128 + cx0 * 128;
        smi[1] = base + cy0 * W128 + cx1 * 128;
        smi[2] = base + cy1 * W128 + cx0 * 128;
        smi[3] = base + cy1 * W128 + cx1 * 128;
        sm[i * 8 + 4] = (xv0 && yv0) ? (1.f - dx) * (1.f - dy) * w : 0.f;
        sm[i * 8 + 5] = (xv1 && yv0) ? dx * (1.f - dy) * w : 0.f;
        sm[i * 8 + 6] = (xv0 && yv1) ? (1.f - dx) * dy * w : 0.f;
        sm[i * 8 + 7] = (xv1 && yv1) ? dx * dy * w : 0.f;
    }
    __syncwarp();

    // ---- gather: half2 granularity, precomputed addresses
    const int half_id = lane >> 4;
    const int d2      = lane & 15;
    const __half2* vb2 = reinterpret_cast<const __half2*>(g_v)
                       + (int)(b * (LEN_V_ * 128)) + h * 16 + d2;

    float ax = 0.f, ay = 0.f;
    #pragma unroll
    for (int it = 0; it < 8; it++) {
        const int pt = it * 2 + half_id;
        int4   ad = *reinterpret_cast<const int4*>(sm + pt * 8);
        float4 ww = *reinterpret_cast<const float4*>(sm + pt * 8 + 4);
        float2 v;
        v = __half22float2(vb2[ad.x]); ax += ww.x * v.x; ay += ww.x * v.y;
        v = __half22float2(vb2[ad.y]); ax += ww.y * v.x; ay += ww.y * v.y;
        v = __half22float2(vb2[ad.z]); ax += ww.z * v.x; ay += ww.z * v.y;
        v = __half22float2(vb2[ad.w]); ax += ww.w * v.x; ay += ww.w * v.y;
    }
    ax += __shfl_xor_sync(0xffffffffu, ax, 16);
    ay += __shfl_xor_sync(0xffffffffu, ay, 16);

    if (half_id == 0)
        *reinterpret_cast<__half2*>(&g_mid16[(long)bq * 256 + h * 32 + 2 * d2]) =
            __floats2half2_rn(ax, ay);
}

// =================== launch ===================
extern "C" void kernel_launch(void* const* d_in, const int* in_sizes, int n_in,
                              void* d_out, int out_size)
{
    const float* query   = (const float*)d_in[0];
    const float* refp    = (const float*)d_in[1];
    const float* value   = (const float*)d_in[2];
    const float* w_value = (const float*)d_in[3];
    const float* b_value = (const float*)d_in[4];
    const float* w_off   = (const float*)d_in[5];
    const float* b_off   = (const float*)d_in[6];
    const float* w_attn  = (const float*)d_in[7];
    const float* b_attn  = (const float*)d_in[8];
    const float* w_out   = (const float*)d_in[9];
    const float* b_out   = (const float*)d_in[10];
    float* out = (float*)d_out;

    __half *pv, *wvh, *pmid16, *wu16;
    float *pqoff, *pqbias;
    cudaGetSymbolAddress((void**)&pv,     g_v);
    cudaGetSymbolAddress((void**)&pqoff,  g_qoff);
    cudaGetSymbolAddress((void**)&pmid16, g_mid16);
    cudaGetSymbolAddress((void**)&pqbias, g_qbias);
    cudaGetSymbolAddress((void**)&wvh,    g_wvh);
    cudaGetSymbolAddress((void**)&wu16,   g_ou16);

    __nv_bfloat16 *qh, *ql;
    cudaGetSymbolAddress((void**)&qh, g_qh);
    cudaGetSymbolAddress((void**)&ql, g_ql);

    static int smem_set = 0;
    if (!smem_set) {
        cudaFuncSetAttribute(bf16x3_gemm_bias,
                             cudaFuncAttributeMaxDynamicSharedMemorySize, GEMM_SMEM);
        cudaFuncSetAttribute(fp16_gemm_v,
                             cudaFuncAttributeMaxDynamicSharedMemorySize, V_SMEM);
        smem_set = 1;
    }

    // 1) pack all weights + combined bias (one launch)
    pack_all<<<(229376 + 255) / 256, 256>>>(w_value, w_off, w_attn, w_out, b_off, b_attn,
                                            wvh, qh, ql, wu16, pqbias);

    // 2) [off|aw] = query @ [w_off|w_attn] + bias   (7200 x 384 x 256)
    {
        dim3 grid(384 / BN, (NQ + BM - 1) / BM);
        bf16x3_gemm_bias<<<grid, 256, GEMM_SMEM>>>(query, qh, ql, pqbias, pqoff, NQ, 384, EMBED);
    }
    // 3) v = value @ w_value + b_value  (174080 x 256 x 256, fp16, 512 threads)
    {
        fp16_gemm_v<<<MV / 128, 512, V_SMEM>>>(value, wvh, b_value, pv);
    }
    // 4) fused softmax + bilinear sample (one warp per (b,q,h))  <- profiled slot
    {
        int warps = NQ * NUM_HEADS;
        msda_sample<<<(warps * 32 + 255) / 256, 256, 4096>>>(refp);
    }
    // 5) out = mid16 @ w_out + b_out -> d_out   (fp16 GEMM)
    {
        dim3 grid(EMBED / 128, (NQ + 127) / 128);
        fp16_gemm_out<<<grid, 256, F_SMEM>>>(pmid16, wu16, b_out, out, NQ, EMBED, EMBED);
    }
}

// round 15
// speedup vs baseline: 4.8929x; 1.0477x over previous
#include <cuda_runtime.h>
#include <cuda_bf16.h>
#include <cuda_fp16.h>
#include <math.h>
#include <stdint.h>

#define NUM_HEADS  8
#define NUM_LEVELS 4
#define NUM_POINTS 4
#define HEAD_DIM   32
#define EMBED      256
#define BS_        8
#define LQ_        900
#define LEN_V_     21760
#define NQ   (BS_*LQ_)        // 7200
#define MV   (BS_*LEN_V_)     // 174080

// single extern shared declaration for the whole TU
extern __shared__ char dsmem[];

// -------- scratch (device globals; no allocations allowed) --------
__device__ __half g_v  [(size_t)MV*EMBED];          // projected value, fp16, 89 MB
__device__ float  g_qoff[(size_t)NQ*384];           // [off(256) | attn(128)] per row
__device__ __half g_mid16[(size_t)(NQ+128)*EMBED];  // sampled output, fp16 (padded rows)
__device__ float  g_qbias[384];

// packed weights
__device__ __half        g_wvh [256*256];            // value weights, fp16 [n][k]
__device__ __half        g_ou16[256*256];            // out weights,   fp16 [n][k]
__device__ __nv_bfloat16 g_qh  [384*256], g_ql[384*256];

// ======================= common helpers =======================
__device__ __forceinline__ void split2(float a, float b, uint32_t& hi, uint32_t& lo) {
    __nv_bfloat162 h = __floats2bfloat162_rn(a, b);
    float ra = a - __bfloat162float(h.x);
    float rb = b - __bfloat162float(h.y);
    __nv_bfloat162 l = __floats2bfloat162_rn(ra, rb);
    hi = *reinterpret_cast<uint32_t*>(&h);
    lo = *reinterpret_cast<uint32_t*>(&l);
}

__device__ __forceinline__ void cp16(uint32_t dst, const void* src) {
    asm volatile("cp.async.ca.shared.global [%0], [%1], 16;" :: "r"(dst), "l"(src));
}

__device__ __forceinline__ void ldsm_x4(uint32_t& r0, uint32_t& r1, uint32_t& r2,
                                        uint32_t& r3, uint32_t addr) {
    asm volatile("ldmatrix.sync.aligned.m8n8.x4.shared.b16 {%0,%1,%2,%3}, [%4];"
                 : "=r"(r0), "=r"(r1), "=r"(r2), "=r"(r3) : "r"(addr));
}

__device__ __forceinline__ void mma_bf16(float* c, const uint32_t* a, const uint32_t* b) {
    asm volatile(
        "mma.sync.aligned.m16n8k16.row.col.f32.bf16.bf16.f32 "
        "{%0,%1,%2,%3}, {%4,%5,%6,%7}, {%8,%9}, {%0,%1,%2,%3};\n"
        : "+f"(c[0]), "+f"(c[1]), "+f"(c[2]), "+f"(c[3])
        : "r"(a[0]), "r"(a[1]), "r"(a[2]), "r"(a[3]), "r"(b[0]), "r"(b[1]));
}

__device__ __forceinline__ void mma_fp16(float* c, const uint32_t* a, const uint32_t* b) {
    asm volatile(
        "mma.sync.aligned.m16n8k16.row.col.f32.f16.f16.f32 "
        "{%0,%1,%2,%3}, {%4,%5,%6,%7}, {%8,%9}, {%0,%1,%2,%3};\n"
        : "+f"(c[0]), "+f"(c[1]), "+f"(c[2]), "+f"(c[3])
        : "r"(a[0]), "r"(a[1]), "r"(a[2]), "r"(a[3]), "r"(b[0]), "r"(b[1]));
}

#define LDW 20   // 32-bit words per smem row (16 data + 4 pad), conflict-free ldmatrix

// ====== v-projection GEMM: BM=128, BN=256, fp16, 512 threads ==================
// 4-slot B ring issued TWO tiles ahead (wait_group 1 per tile -> one B fetch
// always in flight behind the MMA block); A double-buffered via LDG+cvt+STS.
#define V_AS 2560                      // words: A stage (128 rows x 20)
#define V_BBLK 5120                    // words: one B k-block (256 rows x 20)
#define V_BBASE (2 * V_AS)             // B ring starts after 2 A stages
#define V_SMEM ((2 * V_AS + 4 * V_BBLK) * 4)   // 102400 B

__global__ __launch_bounds__(512, 1) void fp16_gemm_v(
    const float* __restrict__ A, const __half* __restrict__ Bh,
    const float* __restrict__ bias, __half* __restrict__ C)
{
    uint32_t* smem = reinterpret_cast<uint32_t*>(dsmem);
    const uint32_t smem_u32 = (uint32_t)__cvta_generic_to_shared(smem);

    const int tid   = threadIdx.x;
    const int lane  = tid & 31;
    const int warp  = tid >> 5;       // 0..15
    const int warpM = warp >> 2;      // 0..3 (32 rows each)
    const int warpN = warp & 3;       // 0..3 (64 cols each)
    const int brow  = blockIdx.x * 128;
    const int g     = lane >> 2;
    const int tg    = lane & 3;

    const uint32_t a_off = (((lane & 15) * LDW) + ((lane >> 4) << 2)) * 4;
    const uint32_t b_off = ((((lane & 7) + ((lane >> 4) << 3)) * LDW) + (((lane >> 3) & 1) << 2)) * 4;

    float acc[2][8][4];
    #pragma unroll
    for (int i = 0; i < 2; i++)
        #pragma unroll
        for (int j = 0; j < 8; j++)
            #pragma unroll
            for (int r = 0; r < 4; r++) acc[i][j][r] = 0.f;

    float4 pa[2];
    auto load_A = [&](int kt) {
        #pragma unroll
        for (int i = 0; i < 2; i++) {
            int idx  = tid + i * 512;     // 0..1023
            int arow = idx >> 3;          // 0..127
            int ac4  = idx & 7;
            pa[i] = *reinterpret_cast<const float4*>(&A[(long)(brow + arow) * 256 + kt + ac4 * 4]);
        }
    };

    auto store_A = [&](int stage) {
        uint32_t* As = smem + stage * V_AS;
        #pragma unroll
        for (int i = 0; i < 2; i++) {
            int idx  = tid + i * 512;
            int arow = idx >> 3;
            int ac4  = idx & 7;
            __half2 h0 = __floats2half2_rn(pa[i].x, pa[i].y);
            __half2 h1 = __floats2half2_rn(pa[i].z, pa[i].w);
            *reinterpret_cast<uint2*>(&As[arow * LDW + ac4 * 2]) =
                make_uint2(*reinterpret_cast<uint32_t*>(&h0), *reinterpret_cast<uint32_t*>(&h1));
        }
    };

    // issue B k-block t into ring slot (t&3) as its own cp.async group
    auto issue_B = [&](int t) {
        uint32_t base = smem_u32 + (uint32_t)((V_BBASE + (t & 3) * V_BBLK) * 4);
        int kt = t * 32;
        #pragma unroll
        for (int i = 0; i < 2; i++) {
            int idx = tid + i * 512;       // 0..1023
            int row = idx >> 2, c = idx & 3;
            cp16(base + (uint32_t)((row * LDW + c * 4) * 4),
                 Bh + ((long)row * 256 + kt + c * 8));
        }
        asm volatile("cp.async.commit_group;" ::: "memory");
    };

    // ---- prologue: B(0), B(1) in flight; stage A(0); require B(0) complete
    issue_B(0);
    issue_B(1);
    load_A(0);
    store_A(0);
    asm volatile("cp.async.wait_group 1;" ::: "memory");
    __syncthreads();

    #pragma unroll
    for (int t = 0; t < 8; t++) {
        if (t + 2 < 8) issue_B(t + 2);
        if (t + 1 < 8) load_A((t + 1) * 32);

        const uint32_t s_as = smem_u32 + (uint32_t)(((t & 1) * V_AS) * 4);
        const uint32_t s_bs = smem_u32 + (uint32_t)((V_BBASE + (t & 3) * V_BBLK) * 4);

        #pragma unroll
        for (int ks = 0; ks < 2; ks++) {
            const uint32_t kb = ks * 8 * 4;
            uint32_t ah[2][4], bh[8][2];
            #pragma unroll
            for (int mt = 0; mt < 2; mt++) {
                uint32_t base = s_as + a_off + (uint32_t)((warpM * 32 + mt * 16) * LDW * 4) + kb;
                ldsm_x4(ah[mt][0], ah[mt][1], ah[mt][2], ah[mt][3], base);
            }
            #pragma unroll
            for (int p = 0; p < 4; p++) {
                uint32_t base = s_bs + b_off + (uint32_t)((warpN * 64 + p * 16) * LDW * 4) + kb;
                ldsm_x4(bh[2*p][0], bh[2*p][1], bh[2*p+1][0], bh[2*p+1][1], base);
            }
            #pragma unroll
            for (int mt = 0; mt < 2; mt++)
                #pragma unroll
                for (int nt = 0; nt < 8; nt++)
                    mma_fp16(acc[mt][nt], ah[mt], bh[nt]);
        }

        if (t + 1 < 8) {
            store_A((t + 1) & 1);
            // need B(t+1) complete; B(t+2) (if issued) may stay in flight
            if (t + 2 < 8) asm volatile("cp.async.wait_group 1;" ::: "memory");
            else           asm volatile("cp.async.wait_group 0;" ::: "memory");
            __syncthreads();
        }
    }

    // epilogue: + bias, fp16 store
    #pragma unroll
    for (int mt = 0; mt < 2; mt++) {
        long row0 = brow + warpM * 32 + mt * 16 + g;
        #pragma unroll
        for (int nt = 0; nt < 8; nt++) {
            int col = warpN * 64 + nt * 8 + tg * 2;
            float b0 = bias[col], b1 = bias[col + 1];
            *reinterpret_cast<__half2*>(&C[row0 * 256 + col]) =
                __floats2half2_rn(acc[mt][nt][0] + b0, acc[mt][nt][1] + b1);
            *reinterpret_cast<__half2*>(&C[(row0 + 8) * 256 + col]) =
                __floats2half2_rn(acc[mt][nt][2] + b0, acc[mt][nt][3] + b1);
        }
    }
}

// ============ bf16 split-2 mma.sync GEMM (q-GEMM, BN=128) =============
#define BM 128
#define BN 128
#define BK 32
#define TILE_WORDS (BM * LDW)
#define STAGE_WORDS (4 * TILE_WORDS)
#define GEMM_SMEM (2 * STAGE_WORDS * 4)

__global__ __launch_bounds__(256) void bf16x3_gemm_bias(
    const float* __restrict__ A,
    const __nv_bfloat16* __restrict__ Bh, const __nv_bfloat16* __restrict__ Bl,
    const float* __restrict__ bias, float* __restrict__ C,
    int M, int N, int K)
{
    uint32_t* smem = reinterpret_cast<uint32_t*>(dsmem);
    const uint32_t smem_u32 = (uint32_t)__cvta_generic_to_shared(smem);

    const int tid   = threadIdx.x;
    const int lane  = tid & 31;
    const int warp  = tid >> 5;
    const int warpM = warp >> 2;
    const int warpN = warp & 3;
    const int brow  = blockIdx.y * BM;
    const int bcol  = blockIdx.x * BN;
    const int g     = lane >> 2;
    const int tg    = lane & 3;

    const uint32_t lohalf = TILE_WORDS * 4;
    const uint32_t a_off = (((lane & 15) * LDW) + ((lane >> 4) << 2)) * 4;
    const uint32_t b_off = ((((lane & 7) + ((lane >> 4) << 3)) * LDW) + (((lane >> 3) & 1) << 2)) * 4;

    float acc[4][4][4];
    #pragma unroll
    for (int i = 0; i < 4; i++)
        #pragma unroll
        for (int j = 0; j < 4; j++)
            #pragma unroll
            for (int r = 0; r < 4; r++) acc[i][j][r] = 0.f;

    float4 pa[4];
    auto load_A = [&](int kt) {
        #pragma unroll
        for (int i = 0; i < 4; i++) {
            int idx  = tid + i * 256;
            int arow = idx >> 3;
            int ac4  = idx & 7;
            int grow = brow + arow;
            pa[i] = make_float4(0.f, 0.f, 0.f, 0.f);
            if (grow < M)
                pa[i] = *reinterpret_cast<const float4*>(&A[(long)grow * K + kt + ac4 * 4]);
        }
    };

    auto store_A = [&](int stage) {
        uint32_t* As0 = smem + stage * STAGE_WORDS;
        uint32_t* As1 = As0 + TILE_WORDS;
        #pragma unroll
        for (int i = 0; i < 4; i++) {
            int idx  = tid + i * 256;
            int arow = idx >> 3;
            int ac4  = idx & 7;
            uint32_t h0, l0, h1, l1;
            split2(pa[i].x, pa[i].y, h0, l0);
            split2(pa[i].z, pa[i].w, h1, l1);
            *reinterpret_cast<uint2*>(&As0[arow * LDW + ac4 * 2]) = make_uint2(h0, h1);
            *reinterpret_cast<uint2*>(&As1[arow * LDW + ac4 * 2]) = make_uint2(l0, l1);
        }
    };

    auto issue_B = [&](int stage, int kt) {
        uint32_t base = smem_u32 + (uint32_t)((stage * STAGE_WORDS + 2 * TILE_WORDS) * 4);
        #pragma unroll
        for (int i = 0; i < 2; i++) {
            int idx = tid + i * 256;
            int row = idx >> 2, c = idx & 3;
            cp16(base + (uint32_t)((row * LDW + c * 4) * 4),
                 Bh + ((long)(bcol + row) * K + kt + c * 8));
        }
        #pragma unroll
        for (int i = 0; i < 2; i++) {
            int idx = tid + i * 256;
            int row = idx >> 2, c = idx & 3;
            cp16(base + lohalf + (uint32_t)((row * LDW + c * 4) * 4),
                 Bl + ((long)(bcol + row) * K + kt + c * 8));
        }
        asm volatile("cp.async.commit_group;" ::: "memory");
    };

    issue_B(0, 0);
    load_A(0);
    store_A(0);
    asm volatile("cp.async.wait_group 0;" ::: "memory");
    __syncthreads();

    for (int kt = 0; kt < K; kt += BK) {
        const int s = (kt >> 5) & 1;
        const bool has_next = (kt + BK < K);
        if (has_next) {
            issue_B(s ^ 1, kt + BK);
            load_A(kt + BK);
        }

        const uint32_t s_as0 = smem_u32 + (uint32_t)(s * STAGE_WORDS * 4);
        const uint32_t s_bs0 = s_as0 + 2 * lohalf;

        #pragma unroll
        for (int ks = 0; ks < 2; ks++) {
            const uint32_t kb = ks * 8 * 4;
            uint32_t ah[4][4], al[4][4], bh[4][2], bl[4][2];
            #pragma unroll
            for (int mt = 0; mt < 4; mt++) {
                uint32_t base = s_as0 + a_off + (uint32_t)((warpM * 64 + mt * 16) * LDW * 4) + kb;
                ldsm_x4(ah[mt][0], ah[mt][1], ah[mt][2], ah[mt][3], base);
                ldsm_x4(al[mt][0], al[mt][1], al[mt][2], al[mt][3], base + lohalf);
            }
            #pragma unroll
            for (int p = 0; p < 2; p++) {
                uint32_t base = s_bs0 + b_off + (uint32_t)((warpN * 32 + p * 16) * LDW * 4) + kb;
                ldsm_x4(bh[2*p][0], bh[2*p][1], bh[2*p+1][0], bh[2*p+1][1], base);
                ldsm_x4(bl[2*p][0], bl[2*p][1], bl[2*p+1][0], bl[2*p+1][1], base + lohalf);
            }
            #pragma unroll
            for (int mt = 0; mt < 4; mt++)
                #pragma unroll
                for (int nt = 0; nt < 4; nt++) {
                    mma_bf16(acc[mt][nt], ah[mt], bh[nt]);
                    mma_bf16(acc[mt][nt], ah[mt], bl[nt]);
                    mma_bf16(acc[mt][nt], al[mt], bh[nt]);
                }
        }

        if (has_next) {
            store_A(s ^ 1);
            asm volatile("cp.async.wait_group 0;" ::: "memory");
        }
        __syncthreads();
    }

    #pragma unroll
    for (int mt = 0; mt < 4; mt++) {
        int row0 = brow + warpM * 64 + mt * 16 + g;
        #pragma unroll
        for (int nt = 0; nt < 4; nt++) {
            int col = bcol + warpN * 32 + nt * 8 + tg * 2;
            float b0 = bias[col], b1 = bias[col + 1];
            if (row0 < M) {
                float2 o = make_float2(acc[mt][nt][0] + b0, acc[mt][nt][1] + b1);
                *reinterpret_cast<float2*>(&C[(long)row0 * N + col]) = o;
            }
            if (row0 + 8 < M) {
                float2 o = make_float2(acc[mt][nt][2] + b0, acc[mt][nt][3] + b1);
                *reinterpret_cast<float2*>(&C[(long)(row0 + 8) * N + col]) = o;
            }
        }
    }
}

// ========= fp16 GEMM for out-projection: A fp16 global, B fp16 packed =========
#define F_TW 2560
#define F_STAGE (2 * F_TW)
#define F_SMEM (2 * F_STAGE * 4)

__global__ __launch_bounds__(256) void fp16_gemm_out(
    const __half* __restrict__ A, const __half* __restrict__ B,
    const float* __restrict__ bias, float* __restrict__ C,
    int M, int N, int K)
{
    uint32_t* smem = reinterpret_cast<uint32_t*>(dsmem);
    const uint32_t smem_u32 = (uint32_t)__cvta_generic_to_shared(smem);

    const int tid   = threadIdx.x;
    const int lane  = tid & 31;
    const int warp  = tid >> 5;
    const int warpM = warp >> 2;
    const int warpN = warp & 3;
    const int brow  = blockIdx.y * 128;
    const int bcol  = blockIdx.x * 128;
    const int g     = lane >> 2;
    const int tg    = lane & 3;

    const uint32_t a_off = (((lane & 15) * LDW) + ((lane >> 4) << 2)) * 4;
    const uint32_t b_off = ((((lane & 7) + ((lane >> 4) << 3)) * LDW) + (((lane >> 3) & 1) << 2)) * 4;

    float acc[4][4][4];
    #pragma unroll
    for (int i = 0; i < 4; i++)
        #pragma unroll
        for (int j = 0; j < 4; j++)
            #pragma unroll
            for (int r = 0; r < 4; r++) acc[i][j][r] = 0.f;

    auto issue_tiles = [&](int stage, int kt) {
        uint32_t baseA = smem_u32 + (uint32_t)(stage * F_STAGE * 4);
        uint32_t baseB = baseA + F_TW * 4;
        #pragma unroll
        for (int i = 0; i < 2; i++) {
            int idx = tid + i * 256;
            int row = idx >> 2, c = idx & 3;
            cp16(baseA + (uint32_t)((row * LDW + c * 4) * 4),
                 A + ((long)(brow + row) * K + kt + c * 8));
        }
        #pragma unroll
        for (int i = 0; i < 2; i++) {
            int idx = tid + i * 256;
            int row = idx >> 2, c = idx & 3;
            cp16(baseB + (uint32_t)((row * LDW + c * 4) * 4),
                 B + ((long)(bcol + row) * K + kt + c * 8));
        }
        asm volatile("cp.async.commit_group;" ::: "memory");
    };

    issue_tiles(0, 0);
    asm volatile("cp.async.wait_group 0;" ::: "memory");
    __syncthreads();

    for (int kt = 0; kt < K; kt += 32) {
        const int s = (kt >> 5) & 1;
        const bool has_next = (kt + 32 < K);
        if (has_next) issue_tiles(s ^ 1, kt + 32);

        const uint32_t s_as = smem_u32 + (uint32_t)(s * F_STAGE * 4);
        const uint32_t s_bs = s_as + F_TW * 4;

        #pragma unroll
        for (int ks = 0; ks < 2; ks++) {
            const uint32_t kb = ks * 8 * 4;
            uint32_t ah[4][4], bh[4][2];
            #pragma unroll
            for (int mt = 0; mt < 4; mt++) {
                uint32_t base = s_as + a_off + (uint32_t)((warpM * 64 + mt * 16) * LDW * 4) + kb;
                ldsm_x4(ah[mt][0], ah[mt][1], ah[mt][2], ah[mt][3], base);
            }
            #pragma unroll
            for (int p = 0; p < 2; p++) {
                uint32_t base = s_bs + b_off + (uint32_t)((warpN * 32 + p * 16) * LDW * 4) + kb;
                ldsm_x4(bh[2*p][0], bh[2*p][1], bh[2*p+1][0], bh[2*p+1][1], base);
            }
            #pragma unroll
            for (int mt = 0; mt < 4; mt++)
                #pragma unroll
                for (int nt = 0; nt < 4; nt++)
                    mma_fp16(acc[mt][nt], ah[mt], bh[nt]);
        }

        if (has_next)
            asm volatile("cp.async.wait_group 0;" ::: "memory");
        __syncthreads();
    }

    #pragma unroll
    for (int mt = 0; mt < 4; mt++) {
        int row0 = brow + warpM * 64 + mt * 16 + g;
        #pragma unroll
        for (int nt = 0; nt < 4; nt++) {
            int col = bcol + warpN * 32 + nt * 8 + tg * 2;
            float b0 = bias[col], b1 = bias[col + 1];
            if (row0 < M) {
                float2 o = make_float2(acc[mt][nt][0] + b0, acc[mt][nt][1] + b1);
                *reinterpret_cast<float2*>(&C[(long)row0 * N + col]) = o;
            }
            if (row0 + 8 < M) {
                float2 o = make_float2(acc[mt][nt][2] + b0, acc[mt][nt][3] + b1);
                *reinterpret_cast<float2*>(&C[(long)(row0 + 8) * N + col]) = o;
            }
        }
    }
}

// ====== merged weight pack ====
__global__ void pack_all(const float* __restrict__ Wv, const float* __restrict__ Wo,
                         const float* __restrict__ Wa, const float* __restrict__ Wu,
                         const float* __restrict__ bo, const float* __restrict__ ba,
                         __half* __restrict__ vh,
                         __nv_bfloat16* __restrict__ qh, __nv_bfloat16* __restrict__ ql,
                         __half* __restrict__ u16,
                         float* __restrict__ qbias)
{
    int idx = blockIdx.x * blockDim.x + threadIdx.x;
    if (idx < 384)
        qbias[idx] = (idx < 256) ? bo[idx] : ba[idx - 256];

    if (idx < 65536) {
        int n = idx >> 8, k = idx & 255;
        vh[idx] = __float2half(Wv[(long)k * 256 + n]);
        return;
    }
    if (idx < 163840) {
        int local = idx - 65536;             // [n<384][k]
        int n = local >> 8, k = local & 255;
        float f = (n < 256) ? Wo[(long)k * 256 + n] : Wa[(long)k * 128 + (n - 256)];
        __nv_bfloat16 h = __float2bfloat16(f);
        __nv_bfloat16 l = __float2bfloat16(f - __bfloat162float(h));
        qh[local] = h;
        ql[local] = l;
        return;
    }
    if (idx < 229376) {
        int local = idx - 163840;
        int n = local >> 8, k = local & 255;
        u16[local] = __float2half(Wu[(long)k * 256 + n]);
    }
}

// ====== fused softmax + bilinear gather: one warp per (bq,h) ==================
__global__ __launch_bounds__(256) void msda_sample(const float* __restrict__ refp)
{
    float* sm = reinterpret_cast<float*>(dsmem) + (threadIdx.x >> 5) * 128;  // 16 pts x 8
    int warp = (blockIdx.x * blockDim.x + threadIdx.x) >> 5;
    int lane = threadIdx.x & 31;
    if (warp >= NQ * NUM_HEADS) return;
    int h  = warp & 7;
    int bq = warp >> 3;
    int b  = bq / LQ_;

    // ---- softmax (lane i and i+16 hold point i)
    const float* qrow = &g_qoff[(long)bq * 384];
    int i = lane & 15;
    int l = i >> 2;
    float aw = qrow[256 + h * 16 + i];
    float m = aw;
    #pragma unroll
    for (int s = 1; s < 16; s <<= 1) m = fmaxf(m, __shfl_xor_sync(0xffffffffu, m, s));
    float e = expf(aw - m);
    float ssum = e;
    #pragma unroll
    for (int s = 1; s < 16; s <<= 1) ssum += __shfl_xor_sync(0xffffffffu, ssum, s);
    float w = e / ssum;

    const int starts[4] = {0, 16384, 20480, 21504};

    // ---- precompute corner addresses (clamped) + weights (validity-folded)
    if (lane < 16) {
        int W = 128 >> l;
        float iw = 1.f / (float)W;
        float rx = refp[(bq * 4 + l) * 2 + 0];
        float ry = refp[(bq * 4 + l) * 2 + 1];
        float lx = rx + qrow[h * 32 + 2 * i]     * iw;
        float ly = ry + qrow[h * 32 + 2 * i + 1] * iw;

        float px = lx * (float)W - 0.5f;
        float py = ly * (float)W - 0.5f;
        float x0f = floorf(px), y0f = floorf(py);
        float dx = px - x0f, dy = py - y0f;
        int x0 = (int)x0f, y0 = (int)y0f;
        bool xv0 = (x0 >= 0) && (x0 < W);
        bool xv1 = (x0 >= -1) && (x0 + 1 < W);
        bool yv0 = (y0 >= 0) && (y0 < W);
        bool yv1 = (y0 >= -1) && (y0 + 1 < W);
        int cx0 = min(max(x0, 0), W - 1);
        int cx1 = min(max(x0 + 1, 0), W - 1);
        int cy0 = min(max(y0, 0), W - 1);
        int cy1 = min(max(y0 + 1, 0), W - 1);
        int base = starts[l] * 128;
        int W128 = W * 128;
        int* smi = reinterpret_cast<int*>(sm + i * 8);
        smi[0] = base + cy0 * W128 + cx0 * 128;
        smi[1] = base + cy0 * W128 + cx1 * 128;
        smi[2] = base + cy1 * W128 + cx0 * 128;
        smi[3] = base + cy1 * W128 + cx1 * 128;
        sm[i * 8 + 4] = (xv0 && yv0) ? (1.f - dx) * (1.f - dy) * w : 0.f;
        sm[i * 8 + 5] = (xv1 && yv0) ? dx * (1.f - dy) * w : 0.f;
        sm[i * 8 + 6] = (xv0 && yv1) ? (1.f - dx) * dy * w : 0.f;
        sm[i * 8 + 7] = (xv1 && yv1) ? dx * dy * w : 0.f;
    }
    __syncwarp();

    // ---- gather: half2 granularity, precomputed addresses
    const int half_id = lane >> 4;
    const int d2      = lane & 15;
    const __half2* vb2 = reinterpret_cast<const __half2*>(g_v)
                       + (int)(b * (LEN_V_ * 128)) + h * 16 + d2;

    float ax = 0.f, ay = 0.f;
    #pragma unroll
    for (int it = 0; it < 8; it++) {
        const int pt = it * 2 + half_id;
        int4   ad = *reinterpret_cast<const int4*>(sm + pt * 8);
        float4 ww = *reinterpret_cast<const float4*>(sm + pt * 8 + 4);
        float2 v;
        v = __half22float2(vb2[ad.x]); ax += ww.x * v.x; ay += ww.x * v.y;
        v = __half22float2(vb2[ad.y]); ax += ww.y * v.x; ay += ww.y * v.y;
        v = __half22float2(vb2[ad.z]); ax += ww.z * v.x; ay += ww.z * v.y;
        v = __half22float2(vb2[ad.w]); ax += ww.w * v.x; ay += ww.w * v.y;
    }
    ax += __shfl_xor_sync(0xffffffffu, ax, 16);
    ay += __shfl_xor_sync(0xffffffffu, ay, 16);

    if (half_id == 0)
        *reinterpret_cast<__half2*>(&g_mid16[(long)bq * 256 + h * 32 + 2 * d2]) =
            __floats2half2_rn(ax, ay);
}

// =================== launch ===================
extern "C" void kernel_launch(void* const* d_in, const int* in_sizes, int n_in,
                              void* d_out, int out_size)
{
    const float* query   = (const float*)d_in[0];
    const float* refp    = (const float*)d_in[1];
    const float* value   = (const float*)d_in[2];
    const float* w_value = (const float*)d_in[3];
    const float* b_value = (const float*)d_in[4];
    const float* w_off   = (const float*)d_in[5];
    const float* b_off   = (const float*)d_in[6];
    const float* w_attn  = (const float*)d_in[7];
    const float* b_attn  = (const float*)d_in[8];
    const float* w_out   = (const float*)d_in[9];
    const float* b_out   = (const float*)d_in[10];
    float* out = (float*)d_out;

    __half *pv, *wvh, *pmid16, *wu16;
    float *pqoff, *pqbias;
    cudaGetSymbolAddress((void**)&pv,     g_v);
    cudaGetSymbolAddress((void**)&pqoff,  g_qoff);
    cudaGetSymbolAddress((void**)&pmid16, g_mid16);
    cudaGetSymbolAddress((void**)&pqbias, g_qbias);
    cudaGetSymbolAddress((void**)&wvh,    g_wvh);
    cudaGetSymbolAddress((void**)&wu16,   g_ou16);

    __nv_bfloat16 *qh, *ql;
    cudaGetSymbolAddress((void**)&qh, g_qh);
    cudaGetSymbolAddress((void**)&ql, g_ql);

    static int smem_set = 0;
    if (!smem_set) {
        cudaFuncSetAttribute(bf16x3_gemm_bias,
                             cudaFuncAttributeMaxDynamicSharedMemorySize, GEMM_SMEM);
        cudaFuncSetAttribute(fp16_gemm_v,
                             cudaFuncAttributeMaxDynamicSharedMemorySize, V_SMEM);
        smem_set = 1;
    }

    // 1) pack all weights + combined bias (one launch)
    pack_all<<<(229376 + 255) / 256, 256>>>(w_value, w_off, w_attn, w_out, b_off, b_attn,
                                            wvh, qh, ql, wu16, pqbias);

    // 2) [off|aw] = query @ [w_off|w_attn] + bias   (7200 x 384 x 256)
    {
        dim3 grid(384 / BN, (NQ + BM - 1) / BM);
        bf16x3_gemm_bias<<<grid, 256, GEMM_SMEM>>>(query, qh, ql, pqbias, pqoff, NQ, 384, EMBED);
    }
    // 3) v = value @ w_value + b_value  (174080 x 256 x 256, fp16, ring-4 B)
    {
        fp16_gemm_v<<<MV / 128, 512, V_SMEM>>>(value, wvh, b_value, pv);
    }
    // 4) fused softmax + bilinear sample (one warp per (b,q,h))
    {
        int warps = NQ * NUM_HEADS;
        msda_sample<<<(warps * 32 + 255) / 256, 256, 4096>>>(refp);
    }
    // 5) out = mid16 @ w_out + b_out -> d_out   (fp16 GEMM)
    {
        dim3 grid(EMBED / 128, (NQ + 127) / 128);
        fp16_gemm_out<<<grid, 256, F_SMEM>>>(pmid16, wu16, b_out, out, NQ, EMBED, EMBED);
    }
}

// round 16
// speedup vs baseline: 5.0140x; 1.0247x over previous
#include <cuda_runtime.h>
#include <cuda_bf16.h>
#include <cuda_fp16.h>
#include <math.h>
#include <stdint.h>

#define NUM_HEADS  8
#define NUM_LEVELS 4
#define NUM_POINTS 4
#define HEAD_DIM   32
#define EMBED      256
#define BS_        8
#define LQ_        900
#define LEN_V_     21760
#define NQ   (BS_*LQ_)        // 7200
#define MV   (BS_*LEN_V_)     // 174080

// single extern shared declaration for the whole TU
extern __shared__ char dsmem[];

// -------- scratch (device globals; no allocations allowed) --------
__device__ __half g_v  [(size_t)MV*EMBED];          // projected value, fp16, 89 MB
__device__ float  g_qoff[(size_t)NQ*384];           // [off(256) | attn(128)] per row
__device__ __half g_mid16[(size_t)(NQ+128)*EMBED];  // sampled output, fp16 (padded rows)
__device__ float  g_qbias[384];

// packed weights
__device__ __half        g_wvh [256*256];            // value weights, fp16 [n][k]
__device__ __half        g_ou16[256*256];            // out weights,   fp16 [n][k]
__device__ __nv_bfloat16 g_qh  [384*256], g_ql[384*256];

// ======================= common helpers =======================
__device__ __forceinline__ void split2(float a, float b, uint32_t& hi, uint32_t& lo) {
    __nv_bfloat162 h = __floats2bfloat162_rn(a, b);
    float ra = a - __bfloat162float(h.x);
    float rb = b - __bfloat162float(h.y);
    __nv_bfloat162 l = __floats2bfloat162_rn(ra, rb);
    hi = *reinterpret_cast<uint32_t*>(&h);
    lo = *reinterpret_cast<uint32_t*>(&l);
}

__device__ __forceinline__ void cp16(uint32_t dst, const void* src) {
    asm volatile("cp.async.ca.shared.global [%0], [%1], 16;" :: "r"(dst), "l"(src));
}

__device__ __forceinline__ void ldsm_x4(uint32_t& r0, uint32_t& r1, uint32_t& r2,
                                        uint32_t& r3, uint32_t addr) {
    asm volatile("ldmatrix.sync.aligned.m8n8.x4.shared.b16 {%0,%1,%2,%3}, [%4];"
                 : "=r"(r0), "=r"(r1), "=r"(r2), "=r"(r3) : "r"(addr));
}

__device__ __forceinline__ void mma_bf16(float* c, const uint32_t* a, const uint32_t* b) {
    asm volatile(
        "mma.sync.aligned.m16n8k16.row.col.f32.bf16.bf16.f32 "
        "{%0,%1,%2,%3}, {%4,%5,%6,%7}, {%8,%9}, {%0,%1,%2,%3};\n"
        : "+f"(c[0]), "+f"(c[1]), "+f"(c[2]), "+f"(c[3])
        : "r"(a[0]), "r"(a[1]), "r"(a[2]), "r"(a[3]), "r"(b[0]), "r"(b[1]));
}

__device__ __forceinline__ void mma_fp16(float* c, const uint32_t* a, const uint32_t* b) {
    asm volatile(
        "mma.sync.aligned.m16n8k16.row.col.f32.f16.f16.f32 "
        "{%0,%1,%2,%3}, {%4,%5,%6,%7}, {%8,%9}, {%0,%1,%2,%3};\n"
        : "+f"(c[0]), "+f"(c[1]), "+f"(c[2]), "+f"(c[3])
        : "r"(a[0]), "r"(a[1]), "r"(a[2]), "r"(a[3]), "r"(b[0]), "r"(b[1]));
}

#define LDW 20   // 32-bit words per smem row (16 data + 4 pad), conflict-free ldmatrix

// ====== v-projection GEMM: BM=128, BN=256, fp16, 512 threads ==================
// 4-slot B ring issued THREE tiles ahead (wait_group 2 steady-state);
// A double-buffered via LDG+cvt+STS.
#define V_AS 2560                      // words: A stage (128 rows x 20)
#define V_BBLK 5120                    // words: one B k-block (256 rows x 20)
#define V_BBASE (2 * V_AS)             // B ring starts after 2 A stages
#define V_SMEM ((2 * V_AS + 4 * V_BBLK) * 4)   // 102400 B

__global__ __launch_bounds__(512, 1) void fp16_gemm_v(
    const float* __restrict__ A, const __half* __restrict__ Bh,
    const float* __restrict__ bias, __half* __restrict__ C)
{
    uint32_t* smem = reinterpret_cast<uint32_t*>(dsmem);
    const uint32_t smem_u32 = (uint32_t)__cvta_generic_to_shared(smem);

    const int tid   = threadIdx.x;
    const int lane  = tid & 31;
    const int warp  = tid >> 5;       // 0..15
    const int warpM = warp >> 2;      // 0..3 (32 rows each)
    const int warpN = warp & 3;       // 0..3 (64 cols each)
    const int brow  = blockIdx.x * 128;
    const int g     = lane >> 2;
    const int tg    = lane & 3;

    const uint32_t a_off = (((lane & 15) * LDW) + ((lane >> 4) << 2)) * 4;
    const uint32_t b_off = ((((lane & 7) + ((lane >> 4) << 3)) * LDW) + (((lane >> 3) & 1) << 2)) * 4;

    float acc[2][8][4];
    #pragma unroll
    for (int i = 0; i < 2; i++)
        #pragma unroll
        for (int j = 0; j < 8; j++)
            #pragma unroll
            for (int r = 0; r < 4; r++) acc[i][j][r] = 0.f;

    float4 pa[2];
    auto load_A = [&](int kt) {
        #pragma unroll
        for (int i = 0; i < 2; i++) {
            int idx  = tid + i * 512;     // 0..1023
            int arow = idx >> 3;          // 0..127
            int ac4  = idx & 7;
            pa[i] = *reinterpret_cast<const float4*>(&A[(long)(brow + arow) * 256 + kt + ac4 * 4]);
        }
    };

    auto store_A = [&](int stage) {
        uint32_t* As = smem + stage * V_AS;
        #pragma unroll
        for (int i = 0; i < 2; i++) {
            int idx  = tid + i * 512;
            int arow = idx >> 3;
            int ac4  = idx & 7;
            __half2 h0 = __floats2half2_rn(pa[i].x, pa[i].y);
            __half2 h1 = __floats2half2_rn(pa[i].z, pa[i].w);
            *reinterpret_cast<uint2*>(&As[arow * LDW + ac4 * 2]) =
                make_uint2(*reinterpret_cast<uint32_t*>(&h0), *reinterpret_cast<uint32_t*>(&h1));
        }
    };

    // issue B k-block t into ring slot (t&3) as its own cp.async group
    auto issue_B = [&](int t) {
        uint32_t base = smem_u32 + (uint32_t)((V_BBASE + (t & 3) * V_BBLK) * 4);
        int kt = t * 32;
        #pragma unroll
        for (int i = 0; i < 2; i++) {
            int idx = tid + i * 512;       // 0..1023
            int row = idx >> 2, c = idx & 3;
            cp16(base + (uint32_t)((row * LDW + c * 4) * 4),
                 Bh + ((long)row * 256 + kt + c * 8));
        }
        asm volatile("cp.async.commit_group;" ::: "memory");
    };

    // ---- prologue: B(0..2) in flight; stage A(0); require B(0) complete
    issue_B(0);
    issue_B(1);
    issue_B(2);
    load_A(0);
    store_A(0);
    asm volatile("cp.async.wait_group 2;" ::: "memory");
    __syncthreads();

    #pragma unroll
    for (int t = 0; t < 8; t++) {
        if (t + 3 < 8) issue_B(t + 3);
        if (t + 1 < 8) load_A((t + 1) * 32);

        const uint32_t s_as = smem_u32 + (uint32_t)(((t & 1) * V_AS) * 4);
        const uint32_t s_bs = smem_u32 + (uint32_t)((V_BBASE + (t & 3) * V_BBLK) * 4);

        #pragma unroll
        for (int ks = 0; ks < 2; ks++) {
            const uint32_t kb = ks * 8 * 4;
            uint32_t ah[2][4], bh[8][2];
            #pragma unroll
            for (int mt = 0; mt < 2; mt++) {
                uint32_t base = s_as + a_off + (uint32_t)((warpM * 32 + mt * 16) * LDW * 4) + kb;
                ldsm_x4(ah[mt][0], ah[mt][1], ah[mt][2], ah[mt][3], base);
            }
            #pragma unroll
            for (int p = 0; p < 4; p++) {
                uint32_t base = s_bs + b_off + (uint32_t)((warpN * 64 + p * 16) * LDW * 4) + kb;
                ldsm_x4(bh[2*p][0], bh[2*p][1], bh[2*p+1][0], bh[2*p+1][1], base);
            }
            #pragma unroll
            for (int mt = 0; mt < 2; mt++)
                #pragma unroll
                for (int nt = 0; nt < 8; nt++)
                    mma_fp16(acc[mt][nt], ah[mt], bh[nt]);
        }

        if (t + 1 < 8) {
            store_A((t + 1) & 1);
            // need B(t+1) complete; later groups may stay in flight
            if      (t + 3 < 8) asm volatile("cp.async.wait_group 2;" ::: "memory");
            else if (t + 2 < 8) asm volatile("cp.async.wait_group 1;" ::: "memory");
            else                asm volatile("cp.async.wait_group 0;" ::: "memory");
            __syncthreads();
        }
    }

    // epilogue: + bias, fp16 store
    #pragma unroll
    for (int mt = 0; mt < 2; mt++) {
        long row0 = brow + warpM * 32 + mt * 16 + g;
        #pragma unroll
        for (int nt = 0; nt < 8; nt++) {
            int col = warpN * 64 + nt * 8 + tg * 2;
            float b0 = bias[col], b1 = bias[col + 1];
            *reinterpret_cast<__half2*>(&C[row0 * 256 + col]) =
                __floats2half2_rn(acc[mt][nt][0] + b0, acc[mt][nt][1] + b1);
            *reinterpret_cast<__half2*>(&C[(row0 + 8) * 256 + col]) =
                __floats2half2_rn(acc[mt][nt][2] + b0, acc[mt][nt][3] + b1);
        }
    }
}

// ============ bf16 split-2 mma.sync GEMM (q-GEMM, BN=128) =============
#define BM 128
#define BN 128
#define BK 32
#define TILE_WORDS (BM * LDW)
#define STAGE_WORDS (4 * TILE_WORDS)
#define GEMM_SMEM (2 * STAGE_WORDS * 4)

__global__ __launch_bounds__(256) void bf16x3_gemm_bias(
    const float* __restrict__ A,
    const __nv_bfloat16* __restrict__ Bh, const __nv_bfloat16* __restrict__ Bl,
    const float* __restrict__ bias, float* __restrict__ C,
    int M, int N, int K)
{
    uint32_t* smem = reinterpret_cast<uint32_t*>(dsmem);
    const uint32_t smem_u32 = (uint32_t)__cvta_generic_to_shared(smem);

    const int tid   = threadIdx.x;
    const int lane  = tid & 31;
    const int warp  = tid >> 5;
    const int warpM = warp >> 2;
    const int warpN = warp & 3;
    const int brow  = blockIdx.y * BM;
    const int bcol  = blockIdx.x * BN;
    const int g     = lane >> 2;
    const int tg    = lane & 3;

    const uint32_t lohalf = TILE_WORDS * 4;
    const uint32_t a_off = (((lane & 15) * LDW) + ((lane >> 4) << 2)) * 4;
    const uint32_t b_off = ((((lane & 7) + ((lane >> 4) << 3)) * LDW) + (((lane >> 3) & 1) << 2)) * 4;

    float acc[4][4][4];
    #pragma unroll
    for (int i = 0; i < 4; i++)
        #pragma unroll
        for (int j = 0; j < 4; j++)
            #pragma unroll
            for (int r = 0; r < 4; r++) acc[i][j][r] = 0.f;

    float4 pa[4];
    auto load_A = [&](int kt) {
        #pragma unroll
        for (int i = 0; i < 4; i++) {
            int idx  = tid + i * 256;
            int arow = idx >> 3;
            int ac4  = idx & 7;
            int grow = brow + arow;
            pa[i] = make_float4(0.f, 0.f, 0.f, 0.f);
            if (grow < M)
                pa[i] = *reinterpret_cast<const float4*>(&A[(long)grow * K + kt + ac4 * 4]);
        }
    };

    auto store_A = [&](int stage) {
        uint32_t* As0 = smem + stage * STAGE_WORDS;
        uint32_t* As1 = As0 + TILE_WORDS;
        #pragma unroll
        for (int i = 0; i < 4; i++) {
            int idx  = tid + i * 256;
            int arow = idx >> 3;
            int ac4  = idx & 7;
            uint32_t h0, l0, h1, l1;
            split2(pa[i].x, pa[i].y, h0, l0);
            split2(pa[i].z, pa[i].w, h1, l1);
            *reinterpret_cast<uint2*>(&As0[arow * LDW + ac4 * 2]) = make_uint2(h0, h1);
            *reinterpret_cast<uint2*>(&As1[arow * LDW + ac4 * 2]) = make_uint2(l0, l1);
        }
    };

    auto issue_B = [&](int stage, int kt) {
        uint32_t base = smem_u32 + (uint32_t)((stage * STAGE_WORDS + 2 * TILE_WORDS) * 4);
        #pragma unroll
        for (int i = 0; i < 2; i++) {
            int idx = tid + i * 256;
            int row = idx >> 2, c = idx & 3;
            cp16(base + (uint32_t)((row * LDW + c * 4) * 4),
                 Bh + ((long)(bcol + row) * K + kt + c * 8));
        }
        #pragma unroll
        for (int i = 0; i < 2; i++) {
            int idx = tid + i * 256;
            int row = idx >> 2, c = idx & 3;
            cp16(base + lohalf + (uint32_t)((row * LDW + c * 4) * 4),
                 Bl + ((long)(bcol + row) * K + kt + c * 8));
        }
        asm volatile("cp.async.commit_group;" ::: "memory");
    };

    issue_B(0, 0);
    load_A(0);
    store_A(0);
    asm volatile("cp.async.wait_group 0;" ::: "memory");
    __syncthreads();

    for (int kt = 0; kt < K; kt += BK) {
        const int s = (kt >> 5) & 1;
        const bool has_next = (kt + BK < K);
        if (has_next) {
            issue_B(s ^ 1, kt + BK);
            load_A(kt + BK);
        }

        const uint32_t s_as0 = smem_u32 + (uint32_t)(s * STAGE_WORDS * 4);
        const uint32_t s_bs0 = s_as0 + 2 * lohalf;

        #pragma unroll
        for (int ks = 0; ks < 2; ks++) {
            const uint32_t kb = ks * 8 * 4;
            uint32_t ah[4][4], al[4][4], bh[4][2], bl[4][2];
            #pragma unroll
            for (int mt = 0; mt < 4; mt++) {
                uint32_t base = s_as0 + a_off + (uint32_t)((warpM * 64 + mt * 16) * LDW * 4) + kb;
                ldsm_x4(ah[mt][0], ah[mt][1], ah[mt][2], ah[mt][3], base);
                ldsm_x4(al[mt][0], al[mt][1], al[mt][2], al[mt][3], base + lohalf);
            }
            #pragma unroll
            for (int p = 0; p < 2; p++) {
                uint32_t base = s_bs0 + b_off + (uint32_t)((warpN * 32 + p * 16) * LDW * 4) + kb;
                ldsm_x4(bh[2*p][0], bh[2*p][1], bh[2*p+1][0], bh[2*p+1][1], base);
                ldsm_x4(bl[2*p][0], bl[2*p][1], bl[2*p+1][0], bl[2*p+1][1], base + lohalf);
            }
            #pragma unroll
            for (int mt = 0; mt < 4; mt++)
                #pragma unroll
                for (int nt = 0; nt < 4; nt++) {
                    mma_bf16(acc[mt][nt], ah[mt], bh[nt]);
                    mma_bf16(acc[mt][nt], ah[mt], bl[nt]);
                    mma_bf16(acc[mt][nt], al[mt], bh[nt]);
                }
        }

        if (has_next) {
            store_A(s ^ 1);
            asm volatile("cp.async.wait_group 0;" ::: "memory");
        }
        __syncthreads();
    }

    #pragma unroll
    for (int mt = 0; mt < 4; mt++) {
        int row0 = brow + warpM * 64 + mt * 16 + g;
        #pragma unroll
        for (int nt = 0; nt < 4; nt++) {
            int col = bcol + warpN * 32 + nt * 8 + tg * 2;
            float b0 = bias[col], b1 = bias[col + 1];
            if (row0 < M) {
                float2 o = make_float2(acc[mt][nt][0] + b0, acc[mt][nt][1] + b1);
                *reinterpret_cast<float2*>(&C[(long)row0 * N + col]) = o;
            }
            if (row0 + 8 < M) {
                float2 o = make_float2(acc[mt][nt][2] + b0, acc[mt][nt][3] + b1);
                *reinterpret_cast<float2*>(&C[(long)(row0 + 8) * N + col]) = o;
            }
        }
    }
}

// ========= fp16 GEMM for out-projection: A fp16 global, B fp16 packed =========
#define F_TW 2560
#define F_STAGE (2 * F_TW)
#define F_SMEM (2 * F_STAGE * 4)

__global__ __launch_bounds__(256) void fp16_gemm_out(
    const __half* __restrict__ A, const __half* __restrict__ B,
    const float* __restrict__ bias, float* __restrict__ C,
    int M, int N, int K)
{
    uint32_t* smem = reinterpret_cast<uint32_t*>(dsmem);
    const uint32_t smem_u32 = (uint32_t)__cvta_generic_to_shared(smem);

    const int tid   = threadIdx.x;
    const int lane  = tid & 31;
    const int warp  = tid >> 5;
    const int warpM = warp >> 2;
    const int warpN = warp & 3;
    const int brow  = blockIdx.y * 128;
    const int bcol  = blockIdx.x * 128;
    const int g     = lane >> 2;
    const int tg    = lane & 3;

    const uint32_t a_off = (((lane & 15) * LDW) + ((lane >> 4) << 2)) * 4;
    const uint32_t b_off = ((((lane & 7) + ((lane >> 4) << 3)) * LDW) + (((lane >> 3) & 1) << 2)) * 4;

    float acc[4][4][4];
    #pragma unroll
    for (int i = 0; i < 4; i++)
        #pragma unroll
        for (int j = 0; j < 4; j++)
            #pragma unroll
            for (int r = 0; r < 4; r++) acc[i][j][r] = 0.f;

    auto issue_tiles = [&](int stage, int kt) {
        uint32_t baseA = smem_u32 + (uint32_t)(stage * F_STAGE * 4);
        uint32_t baseB = baseA + F_TW * 4;
        #pragma unroll
        for (int i = 0; i < 2; i++) {
            int idx = tid + i * 256;
            int row = idx >> 2, c = idx & 3;
            cp16(baseA + (uint32_t)((row * LDW + c * 4) * 4),
                 A + ((long)(brow + row) * K + kt + c * 8));
        }
        #pragma unroll
        for (int i = 0; i < 2; i++) {
            int idx = tid + i * 256;
            int row = idx >> 2, c = idx & 3;
            cp16(baseB + (uint32_t)((row * LDW + c * 4) * 4),
                 B + ((long)(bcol + row) * K + kt + c * 8));
        }
        asm volatile("cp.async.commit_group;" ::: "memory");
    };

    issue_tiles(0, 0);
    asm volatile("cp.async.wait_group 0;" ::: "memory");
    __syncthreads();

    for (int kt = 0; kt < K; kt += 32) {
        const int s = (kt >> 5) & 1;
        const bool has_next = (kt + 32 < K);
        if (has_next) issue_tiles(s ^ 1, kt + 32);

        const uint32_t s_as = smem_u32 + (uint32_t)(s * F_STAGE * 4);
        const uint32_t s_bs = s_as + F_TW * 4;

        #pragma unroll
        for (int ks = 0; ks < 2; ks++) {
            const uint32_t kb = ks * 8 * 4;
            uint32_t ah[4][4], bh[4][2];
            #pragma unroll
            for (int mt = 0; mt < 4; mt++) {
                uint32_t base = s_as + a_off + (uint32_t)((warpM * 64 + mt * 16) * LDW * 4) + kb;
                ldsm_x4(ah[mt][0], ah[mt][1], ah[mt][2], ah[mt][3], base);
            }
            #pragma unroll
            for (int p = 0; p < 2; p++) {
                uint32_t base = s_bs + b_off + (uint32_t)((warpN * 32 + p * 16) * LDW * 4) + kb;
                ldsm_x4(bh[2*p][0], bh[2*p][1], bh[2*p+1][0], bh[2*p+1][1], base);
            }
            #pragma unroll
            for (int mt = 0; mt < 4; mt++)
                #pragma unroll
                for (int nt = 0; nt < 4; nt++)
                    mma_fp16(acc[mt][nt], ah[mt], bh[nt]);
        }

        if (has_next)
            asm volatile("cp.async.wait_group 0;" ::: "memory");
        __syncthreads();
    }

    #pragma unroll
    for (int mt = 0; mt < 4; mt++) {
        int row0 = brow + warpM * 64 + mt * 16 + g;
        #pragma unroll
        for (int nt = 0; nt < 4; nt++) {
            int col = bcol + warpN * 32 + nt * 8 + tg * 2;
            float b0 = bias[col], b1 = bias[col + 1];
            if (row0 < M) {
                float2 o = make_float2(acc[mt][nt][0] + b0, acc[mt][nt][1] + b1);
                *reinterpret_cast<float2*>(&C[(long)row0 * N + col]) = o;
            }
            if (row0 + 8 < M) {
                float2 o = make_float2(acc[mt][nt][2] + b0, acc[mt][nt][3] + b1);
                *reinterpret_cast<float2*>(&C[(long)(row0 + 8) * N + col]) = o;
            }
        }
    }
}

// ====== merged weight pack ====
__global__ void pack_all(const float* __restrict__ Wv, const float* __restrict__ Wo,
                         const float* __restrict__ Wa, const float* __restrict__ Wu,
                         const float* __restrict__ bo, const float* __restrict__ ba,
                         __half* __restrict__ vh,
                         __nv_bfloat16* __restrict__ qh, __nv_bfloat16* __restrict__ ql,
                         __half* __restrict__ u16,
                         float* __restrict__ qbias)
{
    int idx = blockIdx.x * blockDim.x + threadIdx.x;
    if (idx < 384)
        qbias[idx] = (idx < 256) ? bo[idx] : ba[idx - 256];

    if (idx < 65536) {
        int n = idx >> 8, k = idx & 255;
        vh[idx] = __float2half(Wv[(long)k * 256 + n]);
        return;
    }
    if (idx < 163840) {
        int local = idx - 65536;             // [n<384][k]
        int n = local >> 8, k = local & 255;
        float f = (n < 256) ? Wo[(long)k * 256 + n] : Wa[(long)k * 128 + (n - 256)];
        __nv_bfloat16 h = __float2bfloat16(f);
        __nv_bfloat16 l = __float2bfloat16(f - __bfloat162float(h));
        qh[local] = h;
        ql[local] = l;
        return;
    }
    if (idx < 229376) {
        int local = idx - 163840;
        int n = local >> 8, k = local & 255;
        u16[local] = __float2half(Wu[(long)k * 256 + n]);
    }
}

// ====== fused softmax + bilinear gather: one warp per (bq,h) ==================
// Phase 1 (lanes 0-15): softmax + per-point corner addresses (uint2 units) +
// validity-folded weights -> smem.
// Phase 2: lane = (quarter, d4). 4 quarters process 4 points/iter, 4 iters.
// Each lane loads uint2 (4 dims, 8B) per corner -> 16 LDG/warp total.
__global__ __launch_bounds__(256) void msda_sample(const float* __restrict__ refp)
{
    float* sm = reinterpret_cast<float*>(dsmem) + (threadIdx.x >> 5) * 128;  // 16 pts x 8
    int warp = (blockIdx.x * blockDim.x + threadIdx.x) >> 5;
    int lane = threadIdx.x & 31;
    if (warp >= NQ * NUM_HEADS) return;
    int h  = warp & 7;
    int bq = warp >> 3;
    int b  = bq / LQ_;

    // ---- softmax (lane i and i+16 hold point i)
    const float* qrow = &g_qoff[(long)bq * 384];
    int i = lane & 15;
    int l = i >> 2;
    float aw = qrow[256 + h * 16 + i];
    float m = aw;
    #pragma unroll
    for (int s = 1; s < 16; s <<= 1) m = fmaxf(m, __shfl_xor_sync(0xffffffffu, m, s));
    float e = expf(aw - m);
    float ssum = e;
    #pragma unroll
    for (int s = 1; s < 16; s <<= 1) ssum += __shfl_xor_sync(0xffffffffu, ssum, s);
    float w = e / ssum;

    const int starts[4] = {0, 16384, 20480, 21504};

    // ---- precompute corner addresses (uint2 units, clamped) + folded weights
    if (lane < 16) {
        int W = 128 >> l;
        float iw = 1.f / (float)W;
        float rx = refp[(bq * 4 + l) * 2 + 0];
        float ry = refp[(bq * 4 + l) * 2 + 1];
        float lx = rx + qrow[h * 32 + 2 * i]     * iw;
        float ly = ry + qrow[h * 32 + 2 * i + 1] * iw;

        float px = lx * (float)W - 0.5f;
        float py = ly * (float)W - 0.5f;
        float x0f = floorf(px), y0f = floorf(py);
        float dx = px - x0f, dy = py - y0f;
        int x0 = (int)x0f, y0 = (int)y0f;
        bool xv0 = (x0 >= 0) && (x0 < W);
        bool xv1 = (x0 >= -1) && (x0 + 1 < W);
        bool yv0 = (y0 >= 0) && (y0 < W);
        bool yv1 = (y0 >= -1) && (y0 + 1 < W);
        int cx0 = min(max(x0, 0), W - 1);
        int cx1 = min(max(x0 + 1, 0), W - 1);
        int cy0 = min(max(y0, 0), W - 1);
        int cy1 = min(max(y0 + 1, 0), W - 1);
        int base = starts[l] * 64;          // uint2 units: row = 64 uint2
        int W64 = W * 64;
        int* smi = reinterpret_cast<int*>(sm + i * 8);
        smi[0] = base + cy0 * W64 + cx0 * 64;
        smi[1] = base + cy0 * W64 + cx1 * 64;
        smi[2] = base + cy1 * W64 + cx0 * 64;
        smi[3] = base + cy1 * W64 + cx1 * 64;
        sm[i * 8 + 4] = (xv0 && yv0) ? (1.f - dx) * (1.f - dy) * w : 0.f;
        sm[i * 8 + 5] = (xv1 && yv0) ? dx * (1.f - dy) * w : 0.f;
        sm[i * 8 + 6] = (xv0 && yv1) ? (1.f - dx) * dy * w : 0.f;
        sm[i * 8 + 7] = (xv1 && yv1) ? dx * dy * w : 0.f;
    }
    __syncwarp();

    // ---- gather: uint2 (4 dims) per lane, 4 points per iteration
    const int quarter = lane >> 3;      // 0..3: point group
    const int d4      = lane & 7;       // 4-dim group
    const uint2* vb4 = reinterpret_cast<const uint2*>(g_v)
                     + (int)(b * (LEN_V_ * 64)) + h * 8 + d4;

    float4 acc4 = make_float4(0.f, 0.f, 0.f, 0.f);
    #pragma unroll
    for (int it = 0; it < 4; it++) {
        const int pt = it * 4 + quarter;
        int4   ad = *reinterpret_cast<const int4*>(sm + pt * 8);
        float4 ww = *reinterpret_cast<const float4*>(sm + pt * 8 + 4);
        #pragma unroll
        for (int c = 0; c < 4; c++) {
            int   addr = (c == 0) ? ad.x : (c == 1) ? ad.y : (c == 2) ? ad.z : ad.w;
            float wt   = (c == 0) ? ww.x : (c == 1) ? ww.y : (c == 2) ? ww.z : ww.w;
            uint2 r = vb4[addr];
            float2 v0 = __half22float2(*reinterpret_cast<__half2*>(&r.x));
            float2 v1 = __half22float2(*reinterpret_cast<__half2*>(&r.y));
            acc4.x += wt * v0.x;
            acc4.y += wt * v0.y;
            acc4.z += wt * v1.x;
            acc4.w += wt * v1.y;
        }
    }
    // reduce across the 4 quarters (same d4)
    #pragma unroll
    for (int s = 8; s < 32; s <<= 1) {
        acc4.x += __shfl_xor_sync(0xffffffffu, acc4.x, s);
        acc4.y += __shfl_xor_sync(0xffffffffu, acc4.y, s);
        acc4.z += __shfl_xor_sync(0xffffffffu, acc4.z, s);
        acc4.w += __shfl_xor_sync(0xffffffffu, acc4.w, s);
    }

    if (quarter == 0) {
        __half2 o0 = __floats2half2_rn(acc4.x, acc4.y);
        __half2 o1 = __floats2half2_rn(acc4.z, acc4.w);
        *reinterpret_cast<uint2*>(&g_mid16[(long)bq * 256 + h * 32 + d4 * 4]) =
            make_uint2(*reinterpret_cast<uint32_t*>(&o0), *reinterpret_cast<uint32_t*>(&o1));
    }
}

// =================== launch ===================
extern "C" void kernel_launch(void* const* d_in, const int* in_sizes, int n_in,
                              void* d_out, int out_size)
{
    const float* query   = (const float*)d_in[0];
    const float* refp    = (const float*)d_in[1];
    const float* value   = (const float*)d_in[2];
    const float* w_value = (const float*)d_in[3];
    const float* b_value = (const float*)d_in[4];
    const float* w_off   = (const float*)d_in[5];
    const float* b_off   = (const float*)d_in[6];
    const float* w_attn  = (const float*)d_in[7];
    const float* b_attn  = (const float*)d_in[8];
    const float* w_out   = (const float*)d_in[9];
    const float* b_out   = (const float*)d_in[10];
    float* out = (float*)d_out;

    __half *pv, *wvh, *pmid16, *wu16;
    float *pqoff, *pqbias;
    cudaGetSymbolAddress((void**)&pv,     g_v);
    cudaGetSymbolAddress((void**)&pqoff,  g_qoff);
    cudaGetSymbolAddress((void**)&pmid16, g_mid16);
    cudaGetSymbolAddress((void**)&pqbias, g_qbias);
    cudaGetSymbolAddress((void**)&wvh,    g_wvh);
    cudaGetSymbolAddress((void**)&wu16,   g_ou16);

    __nv_bfloat16 *qh, *ql;
    cudaGetSymbolAddress((void**)&qh, g_qh);
    cudaGetSymbolAddress((void**)&ql, g_ql);

    static int smem_set = 0;
    if (!smem_set) {
        cudaFuncSetAttribute(bf16x3_gemm_bias,
                             cudaFuncAttributeMaxDynamicSharedMemorySize, GEMM_SMEM);
        cudaFuncSetAttribute(fp16_gemm_v,
                             cudaFuncAttributeMaxDynamicSharedMemorySize, V_SMEM);
        smem_set = 1;
    }

    // 1) pack all weights + combined bias (one launch)
    pack_all<<<(229376 + 255) / 256, 256>>>(w_value, w_off, w_attn, w_out, b_off, b_attn,
                                            wvh, qh, ql, wu16, pqbias);

    // 2) [off|aw] = query @ [w_off|w_attn] + bias   (7200 x 384 x 256)
    {
        dim3 grid(384 / BN, (NQ + BM - 1) / BM);
        bf16x3_gemm_bias<<<grid, 256, GEMM_SMEM>>>(query, qh, ql, pqbias, pqoff, NQ, 384, EMBED);
    }
    // 3) v = value @ w_value + b_value  (174080 x 256 x 256, fp16, ring-4 depth-3)
    {
        fp16_gemm_v<<<MV / 128, 512, V_SMEM>>>(value, wvh, b_value, pv);
    }
    // 4) fused softmax + bilinear sample (one warp per (b,q,h))
    {
        int warps = NQ * NUM_HEADS;
        msda_sample<<<(warps * 32 + 255) / 256, 256, 4096>>>(refp);
    }
    // 5) out = mid16 @ w_out + b_out -> d_out   (fp16 GEMM)
    {
        dim3 grid(EMBED / 128, (NQ + 127) / 128);
        fp16_gemm_out<<<grid, 256, F_SMEM>>>(pmid16, wu16, b_out, out, NQ, EMBED, EMBED);
    }
}

// round 17
// speedup vs baseline: 5.3525x; 1.0675x over previous
#include <cuda_runtime.h>
#include <cuda_bf16.h>
#include <cuda_fp16.h>
#include <math.h>
#include <stdint.h>

#define NUM_HEADS  8
#define NUM_LEVELS 4
#define NUM_POINTS 4
#define HEAD_DIM   32
#define EMBED      256
#define BS_        8
#define LQ_        900
#define LEN_V_     21760
#define NQ   (BS_*LQ_)        // 7200
#define MV   (BS_*LEN_V_)     // 174080

// single extern shared declaration for the whole TU
extern __shared__ char dsmem[];

// -------- scratch (device globals; no allocations allowed) --------
__device__ __half g_v  [(size_t)MV*EMBED];          // projected value, fp16, 89 MB
__device__ float  g_qoff[(size_t)NQ*384];           // [off(256) | attn(128)] per row
__device__ __half g_mid16[(size_t)(NQ+128)*EMBED];  // sampled output, fp16 (padded rows)
__device__ float  g_qbias[384];

// packed weights
__device__ __half        g_wvh [256*256];            // value weights, fp16 [n][k]
__device__ __half        g_ou16[256*256];            // out weights,   fp16 [n][k]
__device__ __nv_bfloat16 g_qh  [384*256], g_ql[384*256];

// ======================= common helpers =======================
__device__ __forceinline__ void split2(float a, float b, uint32_t& hi, uint32_t& lo) {
    __nv_bfloat162 h = __floats2bfloat162_rn(a, b);
    float ra = a - __bfloat162float(h.x);
    float rb = b - __bfloat162float(h.y);
    __nv_bfloat162 l = __floats2bfloat162_rn(ra, rb);
    hi = *reinterpret_cast<uint32_t*>(&h);
    lo = *reinterpret_cast<uint32_t*>(&l);
}

__device__ __forceinline__ void cp16(uint32_t dst, const void* src) {
    asm volatile("cp.async.ca.shared.global [%0], [%1], 16;" :: "r"(dst), "l"(src));
}

__device__ __forceinline__ void ldsm_x4(uint32_t& r0, uint32_t& r1, uint32_t& r2,
                                        uint32_t& r3, uint32_t addr) {
    asm volatile("ldmatrix.sync.aligned.m8n8.x4.shared.b16 {%0,%1,%2,%3}, [%4];"
                 : "=r"(r0), "=r"(r1), "=r"(r2), "=r"(r3) : "r"(addr));
}

__device__ __forceinline__ void mma_bf16(float* c, const uint32_t* a, const uint32_t* b) {
    asm volatile(
        "mma.sync.aligned.m16n8k16.row.col.f32.bf16.bf16.f32 "
        "{%0,%1,%2,%3}, {%4,%5,%6,%7}, {%8,%9}, {%0,%1,%2,%3};\n"
        : "+f"(c[0]), "+f"(c[1]), "+f"(c[2]), "+f"(c[3])
        : "r"(a[0]), "r"(a[1]), "r"(a[2]), "r"(a[3]), "r"(b[0]), "r"(b[1]));
}

__device__ __forceinline__ void mma_fp16(float* c, const uint32_t* a, const uint32_t* b) {
    asm volatile(
        "mma.sync.aligned.m16n8k16.row.col.f32.f16.f16.f32 "
        "{%0,%1,%2,%3}, {%4,%5,%6,%7}, {%8,%9}, {%0,%1,%2,%3};\n"
        : "+f"(c[0]), "+f"(c[1]), "+f"(c[2]), "+f"(c[3])
        : "r"(a[0]), "r"(a[1]), "r"(a[2]), "r"(a[3]), "r"(b[0]), "r"(b[1]));
}

#define LDW 20   // 32-bit words per smem row (16 data + 4 pad), conflict-free ldmatrix

// ====== v-projection GEMM: BM=128, BN=256, fp16, 512 threads ==================
// 4-slot B ring issued THREE tiles ahead (wait_group 2 steady-state);
// A double-buffered via LDG+cvt+STS.
#define V_AS 2560                      // words: A stage (128 rows x 20)
#define V_BBLK 5120                    // words: one B k-block (256 rows x 20)
#define V_BBASE (2 * V_AS)             // B ring starts after 2 A stages
#define V_SMEM ((2 * V_AS + 4 * V_BBLK) * 4)   // 102400 B

__global__ __launch_bounds__(512, 1) void fp16_gemm_v(
    const float* __restrict__ A, const __half* __restrict__ Bh,
    const float* __restrict__ bias, __half* __restrict__ C)
{
    uint32_t* smem = reinterpret_cast<uint32_t*>(dsmem);
    const uint32_t smem_u32 = (uint32_t)__cvta_generic_to_shared(smem);

    const int tid   = threadIdx.x;
    const int lane  = tid & 31;
    const int warp  = tid >> 5;       // 0..15
    const int warpM = warp >> 2;      // 0..3 (32 rows each)
    const int warpN = warp & 3;       // 0..3 (64 cols each)
    const int brow  = blockIdx.x * 128;
    const int g     = lane >> 2;
    const int tg    = lane & 3;

    const uint32_t a_off = (((lane & 15) * LDW) + ((lane >> 4) << 2)) * 4;
    const uint32_t b_off = ((((lane & 7) + ((lane >> 4) << 3)) * LDW) + (((lane >> 3) & 1) << 2)) * 4;

    float acc[2][8][4];
    #pragma unroll
    for (int i = 0; i < 2; i++)
        #pragma unroll
        for (int j = 0; j < 8; j++)
            #pragma unroll
            for (int r = 0; r < 4; r++) acc[i][j][r] = 0.f;

    float4 pa[2];
    auto load_A = [&](int kt) {
        #pragma unroll
        for (int i = 0; i < 2; i++) {
            int idx  = tid + i * 512;     // 0..1023
            int arow = idx >> 3;          // 0..127
            int ac4  = idx & 7;
            pa[i] = *reinterpret_cast<const float4*>(&A[(long)(brow + arow) * 256 + kt + ac4 * 4]);
        }
    };

    auto store_A = [&](int stage) {
        uint32_t* As = smem + stage * V_AS;
        #pragma unroll
        for (int i = 0; i < 2; i++) {
            int idx  = tid + i * 512;
            int arow = idx >> 3;
            int ac4  = idx & 7;
            __half2 h0 = __floats2half2_rn(pa[i].x, pa[i].y);
            __half2 h1 = __floats2half2_rn(pa[i].z, pa[i].w);
            *reinterpret_cast<uint2*>(&As[arow * LDW + ac4 * 2]) =
                make_uint2(*reinterpret_cast<uint32_t*>(&h0), *reinterpret_cast<uint32_t*>(&h1));
        }
    };

    // issue B k-block t into ring slot (t&3) as its own cp.async group
    auto issue_B = [&](int t) {
        uint32_t base = smem_u32 + (uint32_t)((V_BBASE + (t & 3) * V_BBLK) * 4);
        int kt = t * 32;
        #pragma unroll
        for (int i = 0; i < 2; i++) {
            int idx = tid + i * 512;       // 0..1023
            int row = idx >> 2, c = idx & 3;
            cp16(base + (uint32_t)((row * LDW + c * 4) * 4),
                 Bh + ((long)row * 256 + kt + c * 8));
        }
        asm volatile("cp.async.commit_group;" ::: "memory");
    };

    // ---- prologue: B(0..2) in flight; stage A(0); require B(0) complete
    issue_B(0);
    issue_B(1);
    issue_B(2);
    load_A(0);
    store_A(0);
    asm volatile("cp.async.wait_group 2;" ::: "memory");
    __syncthreads();

    #pragma unroll
    for (int t = 0; t < 8; t++) {
        if (t + 3 < 8) issue_B(t + 3);
        if (t + 1 < 8) load_A((t + 1) * 32);

        const uint32_t s_as = smem_u32 + (uint32_t)(((t & 1) * V_AS) * 4);
        const uint32_t s_bs = smem_u32 + (uint32_t)((V_BBASE + (t & 3) * V_BBLK) * 4);

        #pragma unroll
        for (int ks = 0; ks < 2; ks++) {
            const uint32_t kb = ks * 8 * 4;
            uint32_t ah[2][4], bh[8][2];
            #pragma unroll
            for (int mt = 0; mt < 2; mt++) {
                uint32_t base = s_as + a_off + (uint32_t)((warpM * 32 + mt * 16) * LDW * 4) + kb;
                ldsm_x4(ah[mt][0], ah[mt][1], ah[mt][2], ah[mt][3], base);
            }
            #pragma unroll
            for (int p = 0; p < 4; p++) {
                uint32_t base = s_bs + b_off + (uint32_t)((warpN * 64 + p * 16) * LDW * 4) + kb;
                ldsm_x4(bh[2*p][0], bh[2*p][1], bh[2*p+1][0], bh[2*p+1][1], base);
            }
            #pragma unroll
            for (int mt = 0; mt < 2; mt++)
                #pragma unroll
                for (int nt = 0; nt < 8; nt++)
                    mma_fp16(acc[mt][nt], ah[mt], bh[nt]);
        }

        if (t + 1 < 8) {
            store_A((t + 1) & 1);
            // need B(t+1) complete; later groups may stay in flight
            if      (t + 3 < 8) asm volatile("cp.async.wait_group 2;" ::: "memory");
            else if (t + 2 < 8) asm volatile("cp.async.wait_group 1;" ::: "memory");
            else                asm volatile("cp.async.wait_group 0;" ::: "memory");
            __syncthreads();
        }
    }

    // epilogue: + bias, fp16 store
    #pragma unroll
    for (int mt = 0; mt < 2; mt++) {
        long row0 = brow + warpM * 32 + mt * 16 + g;
        #pragma unroll
        for (int nt = 0; nt < 8; nt++) {
            int col = warpN * 64 + nt * 8 + tg * 2;
            float b0 = bias[col], b1 = bias[col + 1];
            *reinterpret_cast<__half2*>(&C[row0 * 256 + col]) =
                __floats2half2_rn(acc[mt][nt][0] + b0, acc[mt][nt][1] + b1);
            *reinterpret_cast<__half2*>(&C[(row0 + 8) * 256 + col]) =
                __floats2half2_rn(acc[mt][nt][2] + b0, acc[mt][nt][3] + b1);
        }
    }
}

// ============ bf16 split-2 mma.sync GEMM (q-GEMM, BN=128) =============
#define BM 128
#define BN 128
#define BK 32
#define TILE_WORDS (BM * LDW)
#define STAGE_WORDS (4 * TILE_WORDS)
#define GEMM_SMEM (2 * STAGE_WORDS * 4)

__global__ __launch_bounds__(256) void bf16x3_gemm_bias(
    const float* __restrict__ A,
    const __nv_bfloat16* __restrict__ Bh, const __nv_bfloat16* __restrict__ Bl,
    const float* __restrict__ bias, float* __restrict__ C,
    int M, int N, int K)
{
    uint32_t* smem = reinterpret_cast<uint32_t*>(dsmem);
    const uint32_t smem_u32 = (uint32_t)__cvta_generic_to_shared(smem);

    const int tid   = threadIdx.x;
    const int lane  = tid & 31;
    const int warp  = tid >> 5;
    const int warpM = warp >> 2;
    const int warpN = warp & 3;
    const int brow  = blockIdx.y * BM;
    const int bcol  = blockIdx.x * BN;
    const int g     = lane >> 2;
    const int tg    = lane & 3;

    const uint32_t lohalf = TILE_WORDS * 4;
    const uint32_t a_off = (((lane & 15) * LDW) + ((lane >> 4) << 2)) * 4;
    const uint32_t b_off = ((((lane & 7) + ((lane >> 4) << 3)) * LDW) + (((lane >> 3) & 1) << 2)) * 4;

    float acc[4][4][4];
    #pragma unroll
    for (int i = 0; i < 4; i++)
        #pragma unroll
        for (int j = 0; j < 4; j++)
            #pragma unroll
            for (int r = 0; r < 4; r++) acc[i][j][r] = 0.f;

    float4 pa[4];
    auto load_A = [&](int kt) {
        #pragma unroll
        for (int i = 0; i < 4; i++) {
            int idx  = tid + i * 256;
            int arow = idx >> 3;
            int ac4  = idx & 7;
            int grow = brow + arow;
            pa[i] = make_float4(0.f, 0.f, 0.f, 0.f);
            if (grow < M)
                pa[i] = *reinterpret_cast<const float4*>(&A[(long)grow * K + kt + ac4 * 4]);
        }
    };

    auto store_A = [&](int stage) {
        uint32_t* As0 = smem + stage * STAGE_WORDS;
        uint32_t* As1 = As0 + TILE_WORDS;
        #pragma unroll
        for (int i = 0; i < 4; i++) {
            int idx  = tid + i * 256;
            int arow = idx >> 3;
            int ac4  = idx & 7;
            uint32_t h0, l0, h1, l1;
            split2(pa[i].x, pa[i].y, h0, l0);
            split2(pa[i].z, pa[i].w, h1, l1);
            *reinterpret_cast<uint2*>(&As0[arow * LDW + ac4 * 2]) = make_uint2(h0, h1);
            *reinterpret_cast<uint2*>(&As1[arow * LDW + ac4 * 2]) = make_uint2(l0, l1);
        }
    };

    auto issue_B = [&](int stage, int kt) {
        uint32_t base = smem_u32 + (uint32_t)((stage * STAGE_WORDS + 2 * TILE_WORDS) * 4);
        #pragma unroll
        for (int i = 0; i < 2; i++) {
            int idx = tid + i * 256;
            int row = idx >> 2, c = idx & 3;
            cp16(base + (uint32_t)((row * LDW + c * 4) * 4),
                 Bh + ((long)(bcol + row) * K + kt + c * 8));
        }
        #pragma unroll
        for (int i = 0; i < 2; i++) {
            int idx = tid + i * 256;
            int row = idx >> 2, c = idx & 3;
            cp16(base + lohalf + (uint32_t)((row * LDW + c * 4) * 4),
                 Bl + ((long)(bcol + row) * K + kt + c * 8));
        }
        asm volatile("cp.async.commit_group;" ::: "memory");
    };

    issue_B(0, 0);
    load_A(0);
    store_A(0);
    asm volatile("cp.async.wait_group 0;" ::: "memory");
    __syncthreads();

    for (int kt = 0; kt < K; kt += BK) {
        const int s = (kt >> 5) & 1;
        const bool has_next = (kt + BK < K);
        if (has_next) {
            issue_B(s ^ 1, kt + BK);
            load_A(kt + BK);
        }

        const uint32_t s_as0 = smem_u32 + (uint32_t)(s * STAGE_WORDS * 4);
        const uint32_t s_bs0 = s_as0 + 2 * lohalf;

        #pragma unroll
        for (int ks = 0; ks < 2; ks++) {
            const uint32_t kb = ks * 8 * 4;
            uint32_t ah[4][4], al[4][4], bh[4][2], bl[4][2];
            #pragma unroll
            for (int mt = 0; mt < 4; mt++) {
                uint32_t base = s_as0 + a_off + (uint32_t)((warpM * 64 + mt * 16) * LDW * 4) + kb;
                ldsm_x4(ah[mt][0], ah[mt][1], ah[mt][2], ah[mt][3], base);
                ldsm_x4(al[mt][0], al[mt][1], al[mt][2], al[mt][3], base + lohalf);
            }
            #pragma unroll
            for (int p = 0; p < 2; p++) {
                uint32_t base = s_bs0 + b_off + (uint32_t)((warpN * 32 + p * 16) * LDW * 4) + kb;
                ldsm_x4(bh[2*p][0], bh[2*p][1], bh[2*p+1][0], bh[2*p+1][1], base);
                ldsm_x4(bl[2*p][0], bl[2*p][1], bl[2*p+1][0], bl[2*p+1][1], base + lohalf);
            }
            #pragma unroll
            for (int mt = 0; mt < 4; mt++)
                #pragma unroll
                for (int nt = 0; nt < 4; nt++) {
                    mma_bf16(acc[mt][nt], ah[mt], bh[nt]);
                    mma_bf16(acc[mt][nt], ah[mt], bl[nt]);
                    mma_bf16(acc[mt][nt], al[mt], bh[nt]);
                }
        }

        if (has_next) {
            store_A(s ^ 1);
            asm volatile("cp.async.wait_group 0;" ::: "memory");
        }
        __syncthreads();
    }

    #pragma unroll
    for (int mt = 0; mt < 4; mt++) {
        int row0 = brow + warpM * 64 + mt * 16 + g;
        #pragma unroll
        for (int nt = 0; nt < 4; nt++) {
            int col = bcol + warpN * 32 + nt * 8 + tg * 2;
            float b0 = bias[col], b1 = bias[col + 1];
            if (row0 < M) {
                float2 o = make_float2(acc[mt][nt][0] + b0, acc[mt][nt][1] + b1);
                *reinterpret_cast<float2*>(&C[(long)row0 * N + col]) = o;
            }
            if (row0 + 8 < M) {
                float2 o = make_float2(acc[mt][nt][2] + b0, acc[mt][nt][3] + b1);
                *reinterpret_cast<float2*>(&C[(long)(row0 + 8) * N + col]) = o;
            }
        }
    }
}

// ========= fp16 GEMM for out-projection: A fp16 global, B fp16 packed =========
#define F_TW 2560
#define F_STAGE (2 * F_TW)
#define F_SMEM (2 * F_STAGE * 4)

__global__ __launch_bounds__(256) void fp16_gemm_out(
    const __half* __restrict__ A, const __half* __restrict__ B,
    const float* __restrict__ bias, float* __restrict__ C,
    int M, int N, int K)
{
    uint32_t* smem = reinterpret_cast<uint32_t*>(dsmem);
    const uint32_t smem_u32 = (uint32_t)__cvta_generic_to_shared(smem);

    const int tid   = threadIdx.x;
    const int lane  = tid & 31;
    const int warp  = tid >> 5;
    const int warpM = warp >> 2;
    const int warpN = warp & 3;
    const int brow  = blockIdx.y * 128;
    const int bcol  = blockIdx.x * 128;
    const int g     = lane >> 2;
    const int tg    = lane & 3;

    const uint32_t a_off = (((lane & 15) * LDW) + ((lane >> 4) << 2)) * 4;
    const uint32_t b_off = ((((lane & 7) + ((lane >> 4) << 3)) * LDW) + (((lane >> 3) & 1) << 2)) * 4;

    float acc[4][4][4];
    #pragma unroll
    for (int i = 0; i < 4; i++)
        #pragma unroll
        for (int j = 0; j < 4; j++)
            #pragma unroll
            for (int r = 0; r < 4; r++) acc[i][j][r] = 0.f;

    auto issue_tiles = [&](int stage, int kt) {
        uint32_t baseA = smem_u32 + (uint32_t)(stage * F_STAGE * 4);
        uint32_t baseB = baseA + F_TW * 4;
        #pragma unroll
        for (int i = 0; i < 2; i++) {
            int idx = tid + i * 256;
            int row = idx >> 2, c = idx & 3;
            cp16(baseA + (uint32_t)((row * LDW + c * 4) * 4),
                 A + ((long)(brow + row) * K + kt + c * 8));
        }
        #pragma unroll
        for (int i = 0; i < 2; i++) {
            int idx = tid + i * 256;
            int row = idx >> 2, c = idx & 3;
            cp16(baseB + (uint32_t)((row * LDW + c * 4) * 4),
                 B + ((long)(bcol + row) * K + kt + c * 8));
        }
        asm volatile("cp.async.commit_group;" ::: "memory");
    };

    issue_tiles(0, 0);
    asm volatile("cp.async.wait_group 0;" ::: "memory");
    __syncthreads();

    for (int kt = 0; kt < K; kt += 32) {
        const int s = (kt >> 5) & 1;
        const bool has_next = (kt + 32 < K);
        if (has_next) issue_tiles(s ^ 1, kt + 32);

        const uint32_t s_as = smem_u32 + (uint32_t)(s * F_STAGE * 4);
        const uint32_t s_bs = s_as + F_TW * 4;

        #pragma unroll
        for (int ks = 0; ks < 2; ks++) {
            const uint32_t kb = ks * 8 * 4;
            uint32_t ah[4][4], bh[4][2];
            #pragma unroll
            for (int mt = 0; mt < 4; mt++) {
                uint32_t base = s_as + a_off + (uint32_t)((warpM * 64 + mt * 16) * LDW * 4) + kb;
                ldsm_x4(ah[mt][0], ah[mt][1], ah[mt][2], ah[mt][3], base);
            }
            #pragma unroll
            for (int p = 0; p < 2; p++) {
                uint32_t base = s_bs + b_off + (uint32_t)((warpN * 32 + p * 16) * LDW * 4) + kb;
                ldsm_x4(bh[2*p][0], bh[2*p][1], bh[2*p+1][0], bh[2*p+1][1], base);
            }
            #pragma unroll
            for (int mt = 0; mt < 4; mt++)
                #pragma unroll
                for (int nt = 0; nt < 4; nt++)
                    mma_fp16(acc[mt][nt], ah[mt], bh[nt]);
        }

        if (has_next)
            asm volatile("cp.async.wait_group 0;" ::: "memory");
        __syncthreads();
    }

    #pragma unroll
    for (int mt = 0; mt < 4; mt++) {
        int row0 = brow + warpM * 64 + mt * 16 + g;
        #pragma unroll
        for (int nt = 0; nt < 4; nt++) {
            int col = bcol + warpN * 32 + nt * 8 + tg * 2;
            float b0 = bias[col], b1 = bias[col + 1];
            if (row0 < M) {
                float2 o = make_float2(acc[mt][nt][0] + b0, acc[mt][nt][1] + b1);
                *reinterpret_cast<float2*>(&C[(long)row0 * N + col]) = o;
            }
            if (row0 + 8 < M) {
                float2 o = make_float2(acc[mt][nt][2] + b0, acc[mt][nt][3] + b1);
                *reinterpret_cast<float2*>(&C[(long)(row0 + 8) * N + col]) = o;
            }
        }
    }
}

// ====== merged weight pack ====
__global__ void pack_all(const float* __restrict__ Wv, const float* __restrict__ Wo,
                         const float* __restrict__ Wa, const float* __restrict__ Wu,
                         const float* __restrict__ bo, const float* __restrict__ ba,
                         __half* __restrict__ vh,
                         __nv_bfloat16* __restrict__ qh, __nv_bfloat16* __restrict__ ql,
                         __half* __restrict__ u16,
                         float* __restrict__ qbias)
{
    int idx = blockIdx.x * blockDim.x + threadIdx.x;
    if (idx < 384)
        qbias[idx] = (idx < 256) ? bo[idx] : ba[idx - 256];

    if (idx < 65536) {
        int n = idx >> 8, k = idx & 255;
        vh[idx] = __float2half(Wv[(long)k * 256 + n]);
        return;
    }
    if (idx < 163840) {
        int local = idx - 65536;             // [n<384][k]
        int n = local >> 8, k = local & 255;
        float f = (n < 256) ? Wo[(long)k * 256 + n] : Wa[(long)k * 128 + (n - 256)];
        __nv_bfloat16 h = __float2bfloat16(f);
        __nv_bfloat16 l = __float2bfloat16(f - __bfloat162float(h));
        qh[local] = h;
        ql[local] = l;
        return;
    }
    if (idx < 229376) {
        int local = idx - 163840;
        int n = local >> 8, k = local & 255;
        u16[local] = __float2half(Wu[(long)k * 256 + n]);
    }
}

// ====== fused softmax + bilinear gather: one warp per (bq,h) ==================
__global__ __launch_bounds__(256) void msda_sample(const float* __restrict__ refp)
{
    float* sm = reinterpret_cast<float*>(dsmem) + (threadIdx.x >> 5) * 128;  // 16 pts x 8
    int warp = (blockIdx.x * blockDim.x + threadIdx.x) >> 5;
    int lane = threadIdx.x & 31;
    if (warp >= NQ * NUM_HEADS) return;
    int h  = warp & 7;
    int bq = warp >> 3;
    int b  = bq / LQ_;

    // ---- softmax (lane i and i+16 hold point i)
    const float* qrow = &g_qoff[(long)bq * 384];
    int i = lane & 15;
    int l = i >> 2;
    float aw = qrow[256 + h * 16 + i];
    float m = aw;
    #pragma unroll
    for (int s = 1; s < 16; s <<= 1) m = fmaxf(m, __shfl_xor_sync(0xffffffffu, m, s));
    float e = expf(aw - m);
    float ssum = e;
    #pragma unroll
    for (int s = 1; s < 16; s <<= 1) ssum += __shfl_xor_sync(0xffffffffu, ssum, s);
    float w = e / ssum;

    const int starts[4] = {0, 16384, 20480, 21504};

    // ---- precompute corner addresses (uint2 units, clamped) + folded weights
    if (lane < 16) {
        int W = 128 >> l;
        float iw = 1.f / (float)W;
        float rx = refp[(bq * 4 + l) * 2 + 0];
        float ry = refp[(bq * 4 + l) * 2 + 1];
        float lx = rx + qrow[h * 32 + 2 * i]     * iw;
        float ly = ry + qrow[h * 32 + 2 * i + 1] * iw;

        float px = lx * (float)W - 0.5f;
        float py = ly * (float)W - 0.5f;
        float x0f = floorf(px), y0f = floorf(py);
        float dx = px - x0f, dy = py - y0f;
        int x0 = (int)x0f, y0 = (int)y0f;
        bool xv0 = (x0 >= 0) && (x0 < W);
        bool xv1 = (x0 >= -1) && (x0 + 1 < W);
        bool yv0 = (y0 >= 0) && (y0 < W);
        bool yv1 = (y0 >= -1) && (y0 + 1 < W);
        int cx0 = min(max(x0, 0), W - 1);
        int cx1 = min(max(x0 + 1, 0), W - 1);
        int cy0 = min(max(y0, 0), W - 1);
        int cy1 = min(max(y0 + 1, 0), W - 1);
        int base = starts[l] * 64;          // uint2 units: row = 64 uint2
        int W64 = W * 64;
        int* smi = reinterpret_cast<int*>(sm + i * 8);
        smi[0] = base + cy0 * W64 + cx0 * 64;
        smi[1] = base + cy0 * W64 + cx1 * 64;
        smi[2] = base + cy1 * W64 + cx0 * 64;
        smi[3] = base + cy1 * W64 + cx1 * 64;
        sm[i * 8 + 4] = (xv0 && yv0) ? (1.f - dx) * (1.f - dy) * w : 0.f;
        sm[i * 8 + 5] = (xv1 && yv0) ? dx * (1.f - dy) * w : 0.f;
        sm[i * 8 + 6] = (xv0 && yv1) ? (1.f - dx) * dy * w : 0.f;
        sm[i * 8 + 7] = (xv1 && yv1) ? dx * dy * w : 0.f;
    }
    __syncwarp();

    // ---- gather: uint2 (4 dims) per lane, 4 points per iteration
    const int quarter = lane >> 3;      // 0..3: point group
    const int d4      = lane & 7;       // 4-dim group
    const uint2* vb4 = reinterpret_cast<const uint2*>(g_v)
                     + (int)(b * (LEN_V_ * 64)) + h * 8 + d4;

    float4 acc4 = make_float4(0.f, 0.f, 0.f, 0.f);
    #pragma unroll
    for (int it = 0; it < 4; it++) {
        const int pt = it * 4 + quarter;
        int4   ad = *reinterpret_cast<const int4*>(sm + pt * 8);
        float4 ww = *reinterpret_cast<const float4*>(sm + pt * 8 + 4);
        #pragma unroll
        for (int c = 0; c < 4; c++) {
            int   addr = (c == 0) ? ad.x : (c == 1) ? ad.y : (c == 2) ? ad.z : ad.w;
            float wt   = (c == 0) ? ww.x : (c == 1) ? ww.y : (c == 2) ? ww.z : ww.w;
            uint2 r = vb4[addr];
            float2 v0 = __half22float2(*reinterpret_cast<__half2*>(&r.x));
            float2 v1 = __half22float2(*reinterpret_cast<__half2*>(&r.y));
            acc4.x += wt * v0.x;
            acc4.y += wt * v0.y;
            acc4.z += wt * v1.x;
            acc4.w += wt * v1.y;
        }
    }
    // reduce across the 4 quarters (same d4)
    #pragma unroll
    for (int s = 8; s < 32; s <<= 1) {
        acc4.x += __shfl_xor_sync(0xffffffffu, acc4.x, s);
        acc4.y += __shfl_xor_sync(0xffffffffu, acc4.y, s);
        acc4.z += __shfl_xor_sync(0xffffffffu, acc4.z, s);
        acc4.w += __shfl_xor_sync(0xffffffffu, acc4.w, s);
    }

    if (quarter == 0) {
        __half2 o0 = __floats2half2_rn(acc4.x, acc4.y);
        __half2 o1 = __floats2half2_rn(acc4.z, acc4.w);
        *reinterpret_cast<uint2*>(&g_mid16[(long)bq * 256 + h * 32 + d4 * 4]) =
            make_uint2(*reinterpret_cast<uint32_t*>(&o0), *reinterpret_cast<uint32_t*>(&o1));
    }
}

// =================== launch ===================
extern "C" void kernel_launch(void* const* d_in, const int* in_sizes, int n_in,
                              void* d_out, int out_size)
{
    const float* query   = (const float*)d_in[0];
    const float* refp    = (const float*)d_in[1];
    const float* value   = (const float*)d_in[2];
    const float* w_value = (const float*)d_in[3];
    const float* b_value = (const float*)d_in[4];
    const float* w_off   = (const float*)d_in[5];
    const float* b_off   = (const float*)d_in[6];
    const float* w_attn  = (const float*)d_in[7];
    const float* b_attn  = (const float*)d_in[8];
    const float* w_out   = (const float*)d_in[9];
    const float* b_out   = (const float*)d_in[10];
    float* out = (float*)d_out;

    __half *pv, *wvh, *pmid16, *wu16;
    float *pqoff, *pqbias;
    cudaGetSymbolAddress((void**)&pv,     g_v);
    cudaGetSymbolAddress((void**)&pqoff,  g_qoff);
    cudaGetSymbolAddress((void**)&pmid16, g_mid16);
    cudaGetSymbolAddress((void**)&pqbias, g_qbias);
    cudaGetSymbolAddress((void**)&wvh,    g_wvh);
    cudaGetSymbolAddress((void**)&wu16,   g_ou16);

    __nv_bfloat16 *qh, *ql;
    cudaGetSymbolAddress((void**)&qh, g_qh);
    cudaGetSymbolAddress((void**)&ql, g_ql);

    static int inited = 0;
    static cudaStream_t s1;
    static cudaEvent_t ev_fork, ev_join;
    if (!inited) {
        cudaFuncSetAttribute(bf16x3_gemm_bias,
                             cudaFuncAttributeMaxDynamicSharedMemorySize, GEMM_SMEM);
        cudaFuncSetAttribute(fp16_gemm_v,
                             cudaFuncAttributeMaxDynamicSharedMemorySize, V_SMEM);
        cudaStreamCreateWithFlags(&s1, cudaStreamNonBlocking);
        cudaEventCreateWithFlags(&ev_fork, cudaEventDisableTiming);
        cudaEventCreateWithFlags(&ev_join, cudaEventDisableTiming);
        inited = 1;
    }

    // 1) pack all weights + combined bias (one launch, main stream)
    pack_all<<<(229376 + 255) / 256, 256>>>(w_value, w_off, w_attn, w_out, b_off, b_attn,
                                            wvh, qh, ql, wu16, pqbias);

    // fork: side stream runs the (independent) q-GEMM concurrently with v-GEMM
    cudaEventRecord(ev_fork, 0);
    cudaStreamWaitEvent(s1, ev_fork, 0);

    // 2a) [off|aw] = query @ [w_off|w_attn] + bias  (side stream, 57 CTAs)
    {
        dim3 grid(384 / BN, (NQ + BM - 1) / BM);
        bf16x3_gemm_bias<<<grid, 256, GEMM_SMEM, s1>>>(query, qh, ql, pqbias, pqoff,
                                                       NQ, 384, EMBED);
    }
    // 2b) v = value @ w_value + b_value  (main stream, 1360 CTAs)
    {
        fp16_gemm_v<<<MV / 128, 512, V_SMEM>>>(value, wvh, b_value, pv);
    }

    // join: msda needs both
    cudaEventRecord(ev_join, s1);
    cudaStreamWaitEvent(0, ev_join, 0);

    // 3) fused softmax + bilinear sample (one warp per (b,q,h))
    {
        int warps = NQ * NUM_HEADS;
        msda_sample<<<(warps * 32 + 255) / 256, 256, 4096>>>(refp);
    }
    // 4) out = mid16 @ w_out + b_out -> d_out   (fp16 GEMM)
    {
        dim3 grid(EMBED / 128, (NQ + 127) / 128);
        fp16_gemm_out<<<grid, 256, F_SMEM>>>(pmid16, wu16, b_out, out, NQ, EMBED, EMBED);
    }
}